// round 1
// baseline (speedup 1.0000x reference)
#include <cuda_runtime.h>
#include <cuda_bf16.h>
#include <math.h>
#include <stdint.h>

// Problem constants (fixed shapes)
#define BATCH 2
#define SEQ   2048
#define DMODEL 1024
#define NHEAD 16
#define HDIM  64
#define MROWS (BATCH*SEQ)          // 4096

// Scratch buffers (device globals; no allocation allowed)
__device__ float g_q[BATCH*SEQ*DMODEL];
__device__ float g_k[BATCH*SEQ*DMODEL];
__device__ float g_v[BATCH*SEQ*DMODEL];
__device__ float g_o[BATCH*SEQ*DMODEL];

// ---------------------------------------------------------------------------
// Generic tiled fp32 GEMM: C[M,N] = A[M,K] @ B[K,N], all row-major.
// BM=BN=64, BK=32, 256 threads, 4x4 micro-tile per thread.
// ---------------------------------------------------------------------------
__global__ __launch_bounds__(256) void gemm64(const float* __restrict__ A,
                                              const float* __restrict__ B,
                                              float* __restrict__ C,
                                              int M, int N, int K) {
    __shared__ float As[64][33];
    __shared__ float Bs[32][65];
    int tid = threadIdx.x;
    int ty = tid >> 4, tx = tid & 15;
    int m0 = blockIdx.y * 64, n0 = blockIdx.x * 64;

    float acc[4][4];
#pragma unroll
    for (int i = 0; i < 4; i++)
#pragma unroll
        for (int j = 0; j < 4; j++) acc[i][j] = 0.f;

    for (int k0 = 0; k0 < K; k0 += 32) {
        for (int i = tid; i < 64 * 32; i += 256) {
            int r = i >> 5, c = i & 31;
            As[r][c] = A[(size_t)(m0 + r) * K + k0 + c];
        }
        for (int i = tid; i < 32 * 64; i += 256) {
            int r = i >> 6, c = i & 63;
            Bs[r][c] = B[(size_t)(k0 + r) * N + n0 + c];
        }
        __syncthreads();
#pragma unroll
        for (int kk = 0; kk < 32; kk++) {
            float a[4], b[4];
#pragma unroll
            for (int i = 0; i < 4; i++) a[i] = As[ty * 4 + i][kk];
#pragma unroll
            for (int j = 0; j < 4; j++) b[j] = Bs[kk][tx * 4 + j];
#pragma unroll
            for (int i = 0; i < 4; i++)
#pragma unroll
                for (int j = 0; j < 4; j++) acc[i][j] += a[i] * b[j];
        }
        __syncthreads();
    }
#pragma unroll
    for (int i = 0; i < 4; i++)
#pragma unroll
        for (int j = 0; j < 4; j++)
            C[(size_t)(m0 + ty * 4 + i) * N + n0 + tx * 4 + j] = acc[i][j];
}

// ---------------------------------------------------------------------------
// E8 quantization of q (in place). One thread per (b, t, h) row.
// All 240 roots have ||r||^2 == 2.0 exactly; argmin(-2 x.r + 2) with
// first-index tie-break (strict <) matches jnp.argmin semantics.
// ---------------------------------------------------------------------------
__global__ __launch_bounds__(256) void e8_quant(float* __restrict__ q,
                                                const float* __restrict__ Wt,   // [64,8]
                                                const float* __restrict__ Wf) { // [8,64]
    __shared__ float roots[240][8];
    __shared__ float sWt[64 * 8];
    __shared__ float sWf[8 * 64];
    int tid = threadIdx.x;
    for (int i = tid; i < 512; i += 256) { sWt[i] = Wt[i]; sWf[i] = Wf[i]; }
    for (int i = tid; i < 240 * 8; i += 256) {
        int r = i >> 3, d = i & 7;
        float v;
        if (r < 112) {
            int p = r >> 2, s = r & 3;
            // p-th pair (a < b) out of C(8,2) in lexicographic order
            int a = 0, b = 1, cnt = 0; bool done = false;
            for (a = 0; a < 8 && !done; a++) {
                for (b = a + 1; b < 8; b++) {
                    if (cnt == p) { done = true; break; }
                    cnt++;
                }
            }
            a--; // undo final ++ from loop exit
            float si = (s & 2) ? -1.f : 1.f;
            float sj = (s & 1) ? -1.f : 1.f;
            v = (d == a) ? si : ((d == b) ? sj : 0.f);
        } else {
            int k = r - 112;
            int mask = (k << 1) | (__popc(k) & 1);  // k-th even-parity mask, ascending
            v = ((mask >> d) & 1) ? -0.5f : 0.5f;
        }
        roots[r][d] = v;
    }
    __syncthreads();

    int idx = blockIdx.x * 256 + tid;           // over B*T*H = 65536
    int h = idx & 15;
    int row = idx >> 4;                          // b*T + t
    float* qp = q + (size_t)row * DMODEL + h * HDIM;

    float e8[8];
#pragma unroll
    for (int j = 0; j < 8; j++) e8[j] = 0.f;
    for (int d = 0; d < HDIM; d++) {
        float v = qp[d];
#pragma unroll
        for (int j = 0; j < 8; j++) e8[j] += v * sWt[d * 8 + j];
    }
    int best = 0;
    float bests = 3.4e38f;
    for (int r = 0; r < 240; r++) {
        float dot = 0.f;
#pragma unroll
        for (int j = 0; j < 8; j++) dot += e8[j] * roots[r][j];
        float score = -2.0f * dot + 2.0f;
        if (score < bests) { bests = score; best = r; }
    }
    float rt[8];
#pragma unroll
    for (int j = 0; j < 8; j++) rt[j] = roots[best][j];
    for (int d = 0; d < HDIM; d++) {
        float s = 0.f;
#pragma unroll
        for (int j = 0; j < 8; j++) s += rt[j] * sWf[j * HDIM + d];
        qp[d] = s;
    }
}

// ---------------------------------------------------------------------------
// Flash-style causal attention. One block per (q-tile of 64, head, batch).
// K/V tiles of 32. fp32 online softmax. Static smem < 48KB.
// ---------------------------------------------------------------------------
__global__ __launch_bounds__(256) void flash_attn(const float* __restrict__ Q,
                                                  const float* __restrict__ K,
                                                  const float* __restrict__ V,
                                                  float* __restrict__ O) {
    __shared__ float Qs[64][65];
    __shared__ float Ks[32][65];
    __shared__ float Vs[32][65];
    __shared__ float Ps[64][33];
    int tid = threadIdx.x;
    int ty = tid >> 4, tx = tid & 15;
    int mblk = blockIdx.x, h = blockIdx.y, b = blockIdx.z;
    size_t base = ((size_t)b * SEQ) * DMODEL + h * HDIM;
    int m0 = mblk * 64;
    const float scale = 0.125f;  // 1/sqrt(64)

    for (int i = tid; i < 64 * 64; i += 256) {
        int r = i >> 6, c = i & 63;
        Qs[r][c] = Q[base + (size_t)(m0 + r) * DMODEL + c];
    }
    float mi[4], li[4], acc[4][4];
#pragma unroll
    for (int i = 0; i < 4; i++) {
        mi[i] = -INFINITY; li[i] = 0.f;
#pragma unroll
        for (int j = 0; j < 4; j++) acc[i][j] = 0.f;
    }
    __syncthreads();

    int ktiles = 2 * mblk + 2;  // keys 0 .. m0+63 inclusive
    for (int nt = 0; nt < ktiles; nt++) {
        int n0 = nt * 32;
        for (int i = tid; i < 32 * 64; i += 256) {
            int r = i >> 6, c = i & 63;
            Ks[r][c] = K[base + (size_t)(n0 + r) * DMODEL + c];
            Vs[r][c] = V[base + (size_t)(n0 + r) * DMODEL + c];
        }
        __syncthreads();

        // S = Q K^T  (64x32), each thread: rows ty*4+i, cols tx*2+j
        float s[4][2];
#pragma unroll
        for (int i = 0; i < 4; i++) { s[i][0] = 0.f; s[i][1] = 0.f; }
#pragma unroll
        for (int d = 0; d < HDIM; d++) {
            float a[4], bb[2];
#pragma unroll
            for (int i = 0; i < 4; i++) a[i] = Qs[ty * 4 + i][d];
            bb[0] = Ks[tx * 2 + 0][d];
            bb[1] = Ks[tx * 2 + 1][d];
#pragma unroll
            for (int i = 0; i < 4; i++) {
                s[i][0] += a[i] * bb[0];
                s[i][1] += a[i] * bb[1];
            }
        }
        // scale + causal mask (mask value exactly -1e9 like reference)
#pragma unroll
        for (int i = 0; i < 4; i++) {
#pragma unroll
            for (int j = 0; j < 2; j++) {
                int qi = m0 + ty * 4 + i, kj = n0 + tx * 2 + j;
                s[i][j] = (kj > qi) ? -1e9f : s[i][j] * scale;
            }
        }
        // row max across the 16-lane row group
        float tmax[4];
#pragma unroll
        for (int i = 0; i < 4; i++) tmax[i] = fmaxf(s[i][0], s[i][1]);
#pragma unroll
        for (int off = 1; off < 16; off <<= 1)
#pragma unroll
            for (int i = 0; i < 4; i++)
                tmax[i] = fmaxf(tmax[i], __shfl_xor_sync(0xffffffffu, tmax[i], off, 16));

        float mnew[4], alpha[4], rs[4];
#pragma unroll
        for (int i = 0; i < 4; i++) {
            mnew[i] = fmaxf(mi[i], tmax[i]);
            alpha[i] = __expf(mi[i] - mnew[i]);
            float p0 = __expf(s[i][0] - mnew[i]);
            float p1 = __expf(s[i][1] - mnew[i]);
            Ps[ty * 4 + i][tx * 2 + 0] = p0;
            Ps[ty * 4 + i][tx * 2 + 1] = p1;
            rs[i] = p0 + p1;
        }
#pragma unroll
        for (int off = 1; off < 16; off <<= 1)
#pragma unroll
            for (int i = 0; i < 4; i++)
                rs[i] += __shfl_xor_sync(0xffffffffu, rs[i], off, 16);
#pragma unroll
        for (int i = 0; i < 4; i++) {
            li[i] = li[i] * alpha[i] + rs[i];
            mi[i] = mnew[i];
#pragma unroll
            for (int j = 0; j < 4; j++) acc[i][j] *= alpha[i];
        }
        __syncthreads();  // Ps visible

        // O += P @ V (64x64), each thread rows ty*4+i, cols tx*4+j
#pragma unroll
        for (int kk = 0; kk < 32; kk++) {
            float p[4], vv[4];
#pragma unroll
            for (int i = 0; i < 4; i++) p[i] = Ps[ty * 4 + i][kk];
#pragma unroll
            for (int j = 0; j < 4; j++) vv[j] = Vs[kk][tx * 4 + j];
#pragma unroll
            for (int i = 0; i < 4; i++)
#pragma unroll
                for (int j = 0; j < 4; j++) acc[i][j] += p[i] * vv[j];
        }
        __syncthreads();  // before next K/V load
    }
#pragma unroll
    for (int i = 0; i < 4; i++) {
        float inv = 1.0f / li[i];
#pragma unroll
        for (int j = 0; j < 4; j++)
            O[base + (size_t)(m0 + ty * 4 + i) * DMODEL + tx * 4 + j] = acc[i][j] * inv;
    }
}

// ---------------------------------------------------------------------------
// Launch
// ---------------------------------------------------------------------------
extern "C" void kernel_launch(void* const* d_in, const int* in_sizes, int n_in,
                              void* d_out, int out_size) {
    const float* x     = (const float*)d_in[0];
    const float* Wq    = (const float*)d_in[1];
    const float* Wk    = (const float*)d_in[2];
    const float* Wv    = (const float*)d_in[3];
    const float* Wte8  = (const float*)d_in[4];
    const float* Wfe8  = (const float*)d_in[5];
    const float* Wout  = (const float*)d_in[6];
    float* out = (float*)d_out;

    float *q, *k, *v, *o;
    cudaGetSymbolAddress((void**)&q, g_q);
    cudaGetSymbolAddress((void**)&k, g_k);
    cudaGetSymbolAddress((void**)&v, g_v);
    cudaGetSymbolAddress((void**)&o, g_o);

    dim3 ggrid(DMODEL / 64, MROWS / 64);
    gemm64<<<ggrid, 256>>>(x, Wq, q, MROWS, DMODEL, DMODEL);
    gemm64<<<ggrid, 256>>>(x, Wk, k, MROWS, DMODEL, DMODEL);
    gemm64<<<ggrid, 256>>>(x, Wv, v, MROWS, DMODEL, DMODEL);

    e8_quant<<<(BATCH * SEQ * NHEAD) / 256, 256>>>(q, Wte8, Wfe8);

    dim3 fgrid(SEQ / 64, NHEAD, BATCH);
    flash_attn<<<fgrid, 256>>>(q, k, v, o);

    gemm64<<<ggrid, 256>>>(o, Wout, out, MROWS, DMODEL, DMODEL);
}

// round 2
// speedup vs baseline: 1.0054x; 1.0054x over previous
#include <cuda_runtime.h>
#include <cuda_bf16.h>
#include <math.h>
#include <stdint.h>

// Problem constants (fixed shapes)
#define BATCH 2
#define SEQ   2048
#define DMODEL 1024
#define NHEAD 16
#define HDIM  64
#define MROWS (BATCH*SEQ)          // 4096

// Scratch buffers (device globals; no allocation allowed)
__device__ float g_q[BATCH*SEQ*DMODEL];
__device__ float g_k[BATCH*SEQ*DMODEL];
__device__ float g_v[BATCH*SEQ*DMODEL];
__device__ float g_o[BATCH*SEQ*DMODEL];

// ---------------------------------------------------------------------------
// Generic tiled fp32 GEMM: C[M,N] = A[M,K] @ B[K,N], all row-major.
// BM=BN=64, BK=32, 256 threads, 4x4 micro-tile per thread.
// ---------------------------------------------------------------------------
__global__ __launch_bounds__(256) void gemm64(const float* __restrict__ A,
                                              const float* __restrict__ B,
                                              float* __restrict__ C,
                                              int M, int N, int K) {
    __shared__ float As[64][33];
    __shared__ float Bs[32][65];
    int tid = threadIdx.x;
    int ty = tid >> 4, tx = tid & 15;
    int m0 = blockIdx.y * 64, n0 = blockIdx.x * 64;

    float acc[4][4];
#pragma unroll
    for (int i = 0; i < 4; i++)
#pragma unroll
        for (int j = 0; j < 4; j++) acc[i][j] = 0.f;

    for (int k0 = 0; k0 < K; k0 += 32) {
        for (int i = tid; i < 64 * 32; i += 256) {
            int r = i >> 5, c = i & 31;
            As[r][c] = A[(size_t)(m0 + r) * K + k0 + c];
        }
        for (int i = tid; i < 32 * 64; i += 256) {
            int r = i >> 6, c = i & 63;
            Bs[r][c] = B[(size_t)(k0 + r) * N + n0 + c];
        }
        __syncthreads();
#pragma unroll
        for (int kk = 0; kk < 32; kk++) {
            float a[4], b[4];
#pragma unroll
            for (int i = 0; i < 4; i++) a[i] = As[ty * 4 + i][kk];
#pragma unroll
            for (int j = 0; j < 4; j++) b[j] = Bs[kk][tx * 4 + j];
#pragma unroll
            for (int i = 0; i < 4; i++)
#pragma unroll
                for (int j = 0; j < 4; j++) acc[i][j] += a[i] * b[j];
        }
        __syncthreads();
    }
#pragma unroll
    for (int i = 0; i < 4; i++)
#pragma unroll
        for (int j = 0; j < 4; j++)
            C[(size_t)(m0 + ty * 4 + i) * N + n0 + tx * 4 + j] = acc[i][j];
}

// ---------------------------------------------------------------------------
// E8 quantization of q (in place). One thread per (b, t, h) row.
// All 240 roots have ||r||^2 == 2.0 exactly; argmin(-2 x.r + 2) with
// first-index tie-break (strict <) matches jnp.argmin semantics.
// ---------------------------------------------------------------------------
__global__ __launch_bounds__(256) void e8_quant(float* __restrict__ q,
                                                const float* __restrict__ Wt,   // [64,8]
                                                const float* __restrict__ Wf) { // [8,64]
    __shared__ float roots[240][8];
    __shared__ float sWt[64 * 8];
    __shared__ float sWf[8 * 64];
    int tid = threadIdx.x;
    for (int i = tid; i < 512; i += 256) { sWt[i] = Wt[i]; sWf[i] = Wf[i]; }
    for (int i = tid; i < 240 * 8; i += 256) {
        int r = i >> 3, d = i & 7;
        float v;
        if (r < 112) {
            int p = r >> 2, s = r & 3;
            // p-th pair (a < b) out of C(8,2) in lexicographic order
            int a = 0, b = 1, cnt = 0; bool done = false;
            for (a = 0; a < 8 && !done; a++) {
                for (b = a + 1; b < 8; b++) {
                    if (cnt == p) { done = true; break; }
                    cnt++;
                }
            }
            a--; // undo final ++ from loop exit
            float si = (s & 2) ? -1.f : 1.f;
            float sj = (s & 1) ? -1.f : 1.f;
            v = (d == a) ? si : ((d == b) ? sj : 0.f);
        } else {
            int k = r - 112;
            int mask = (k << 1) | (__popc(k) & 1);  // k-th even-parity mask, ascending
            v = ((mask >> d) & 1) ? -0.5f : 0.5f;
        }
        roots[r][d] = v;
    }
    __syncthreads();

    int idx = blockIdx.x * 256 + tid;           // over B*T*H = 65536
    int h = idx & 15;
    int row = idx >> 4;                          // b*T + t
    float* qp = q + (size_t)row * DMODEL + h * HDIM;

    float e8[8];
#pragma unroll
    for (int j = 0; j < 8; j++) e8[j] = 0.f;
    for (int d = 0; d < HDIM; d++) {
        float v = qp[d];
#pragma unroll
        for (int j = 0; j < 8; j++) e8[j] += v * sWt[d * 8 + j];
    }
    int best = 0;
    float bests = 3.4e38f;
    for (int r = 0; r < 240; r++) {
        float dot = 0.f;
#pragma unroll
        for (int j = 0; j < 8; j++) dot += e8[j] * roots[r][j];
        float score = -2.0f * dot + 2.0f;
        if (score < bests) { bests = score; best = r; }
    }
    float rt[8];
#pragma unroll
    for (int j = 0; j < 8; j++) rt[j] = roots[best][j];
    for (int d = 0; d < HDIM; d++) {
        float s = 0.f;
#pragma unroll
        for (int j = 0; j < 8; j++) s += rt[j] * sWf[j * HDIM + d];
        qp[d] = s;
    }
}

// ---------------------------------------------------------------------------
// Flash-style causal attention. One block per (q-tile of 64, head, batch).
// K/V tiles of 32. fp32 online softmax. Static smem < 48KB.
// ---------------------------------------------------------------------------
__global__ __launch_bounds__(256) void flash_attn(const float* __restrict__ Q,
                                                  const float* __restrict__ K,
                                                  const float* __restrict__ V,
                                                  float* __restrict__ O) {
    __shared__ float Qs[64][65];
    __shared__ float Ks[32][65];
    __shared__ float Vs[32][65];
    __shared__ float Ps[64][33];
    int tid = threadIdx.x;
    int ty = tid >> 4, tx = tid & 15;
    int mblk = blockIdx.x, h = blockIdx.y, b = blockIdx.z;
    size_t base = ((size_t)b * SEQ) * DMODEL + h * HDIM;
    int m0 = mblk * 64;
    const float scale = 0.125f;  // 1/sqrt(64)

    for (int i = tid; i < 64 * 64; i += 256) {
        int r = i >> 6, c = i & 63;
        Qs[r][c] = Q[base + (size_t)(m0 + r) * DMODEL + c];
    }
    float mi[4], li[4], acc[4][4];
#pragma unroll
    for (int i = 0; i < 4; i++) {
        mi[i] = -INFINITY; li[i] = 0.f;
#pragma unroll
        for (int j = 0; j < 4; j++) acc[i][j] = 0.f;
    }
    __syncthreads();

    int ktiles = 2 * mblk + 2;  // keys 0 .. m0+63 inclusive
    for (int nt = 0; nt < ktiles; nt++) {
        int n0 = nt * 32;
        for (int i = tid; i < 32 * 64; i += 256) {
            int r = i >> 6, c = i & 63;
            Ks[r][c] = K[base + (size_t)(n0 + r) * DMODEL + c];
            Vs[r][c] = V[base + (size_t)(n0 + r) * DMODEL + c];
        }
        __syncthreads();

        // S = Q K^T  (64x32), each thread: rows ty*4+i, cols tx*2+j
        float s[4][2];
#pragma unroll
        for (int i = 0; i < 4; i++) { s[i][0] = 0.f; s[i][1] = 0.f; }
#pragma unroll
        for (int d = 0; d < HDIM; d++) {
            float a[4], bb[2];
#pragma unroll
            for (int i = 0; i < 4; i++) a[i] = Qs[ty * 4 + i][d];
            bb[0] = Ks[tx * 2 + 0][d];
            bb[1] = Ks[tx * 2 + 1][d];
#pragma unroll
            for (int i = 0; i < 4; i++) {
                s[i][0] += a[i] * bb[0];
                s[i][1] += a[i] * bb[1];
            }
        }
        // scale + causal mask (mask value exactly -1e9 like reference)
#pragma unroll
        for (int i = 0; i < 4; i++) {
#pragma unroll
            for (int j = 0; j < 2; j++) {
                int qi = m0 + ty * 4 + i, kj = n0 + tx * 2 + j;
                s[i][j] = (kj > qi) ? -1e9f : s[i][j] * scale;
            }
        }
        // row max across the 16-lane row group
        float tmax[4];
#pragma unroll
        for (int i = 0; i < 4; i++) tmax[i] = fmaxf(s[i][0], s[i][1]);
#pragma unroll
        for (int off = 1; off < 16; off <<= 1)
#pragma unroll
            for (int i = 0; i < 4; i++)
                tmax[i] = fmaxf(tmax[i], __shfl_xor_sync(0xffffffffu, tmax[i], off, 16));

        float mnew[4], alpha[4], rs[4];
#pragma unroll
        for (int i = 0; i < 4; i++) {
            mnew[i] = fmaxf(mi[i], tmax[i]);
            alpha[i] = __expf(mi[i] - mnew[i]);
            float p0 = __expf(s[i][0] - mnew[i]);
            float p1 = __expf(s[i][1] - mnew[i]);
            Ps[ty * 4 + i][tx * 2 + 0] = p0;
            Ps[ty * 4 + i][tx * 2 + 1] = p1;
            rs[i] = p0 + p1;
        }
#pragma unroll
        for (int off = 1; off < 16; off <<= 1)
#pragma unroll
            for (int i = 0; i < 4; i++)
                rs[i] += __shfl_xor_sync(0xffffffffu, rs[i], off, 16);
#pragma unroll
        for (int i = 0; i < 4; i++) {
            li[i] = li[i] * alpha[i] + rs[i];
            mi[i] = mnew[i];
#pragma unroll
            for (int j = 0; j < 4; j++) acc[i][j] *= alpha[i];
        }
        __syncthreads();  // Ps visible

        // O += P @ V (64x64), each thread rows ty*4+i, cols tx*4+j
#pragma unroll
        for (int kk = 0; kk < 32; kk++) {
            float p[4], vv[4];
#pragma unroll
            for (int i = 0; i < 4; i++) p[i] = Ps[ty * 4 + i][kk];
#pragma unroll
            for (int j = 0; j < 4; j++) vv[j] = Vs[kk][tx * 4 + j];
#pragma unroll
            for (int i = 0; i < 4; i++)
#pragma unroll
                for (int j = 0; j < 4; j++) acc[i][j] += p[i] * vv[j];
        }
        __syncthreads();  // before next K/V load
    }
#pragma unroll
    for (int i = 0; i < 4; i++) {
        float inv = 1.0f / li[i];
#pragma unroll
        for (int j = 0; j < 4; j++)
            O[base + (size_t)(m0 + ty * 4 + i) * DMODEL + tx * 4 + j] = acc[i][j] * inv;
    }
}

// ---------------------------------------------------------------------------
// Launch
// ---------------------------------------------------------------------------
extern "C" void kernel_launch(void* const* d_in, const int* in_sizes, int n_in,
                              void* d_out, int out_size) {
    const float* x     = (const float*)d_in[0];
    const float* Wq    = (const float*)d_in[1];
    const float* Wk    = (const float*)d_in[2];
    const float* Wv    = (const float*)d_in[3];
    const float* Wte8  = (const float*)d_in[4];
    const float* Wfe8  = (const float*)d_in[5];
    const float* Wout  = (const float*)d_in[6];
    float* out = (float*)d_out;

    float *q, *k, *v, *o;
    cudaGetSymbolAddress((void**)&q, g_q);
    cudaGetSymbolAddress((void**)&k, g_k);
    cudaGetSymbolAddress((void**)&v, g_v);
    cudaGetSymbolAddress((void**)&o, g_o);

    dim3 ggrid(DMODEL / 64, MROWS / 64);
    gemm64<<<ggrid, 256>>>(x, Wq, q, MROWS, DMODEL, DMODEL);
    gemm64<<<ggrid, 256>>>(x, Wk, k, MROWS, DMODEL, DMODEL);
    gemm64<<<ggrid, 256>>>(x, Wv, v, MROWS, DMODEL, DMODEL);

    e8_quant<<<(BATCH * SEQ * NHEAD) / 256, 256>>>(q, Wte8, Wfe8);

    dim3 fgrid(SEQ / 64, NHEAD, BATCH);
    flash_attn<<<fgrid, 256>>>(q, k, v, o);

    gemm64<<<ggrid, 256>>>(o, Wout, out, MROWS, DMODEL, DMODEL);
}

// round 4
// speedup vs baseline: 1.3492x; 1.3419x over previous
#include <cuda_runtime.h>
#include <cuda_bf16.h>
#include <math.h>
#include <stdint.h>

// Problem constants (fixed shapes)
#define BATCH 2
#define SEQ   2048
#define DMODEL 1024
#define NHEAD 16
#define HDIM  64
#define MROWS (BATCH*SEQ)          // 4096

// Scratch buffers (device globals; no allocation allowed)
__device__ float g_q[BATCH*SEQ*DMODEL];
__device__ float g_k[BATCH*SEQ*DMODEL];
__device__ float g_v[BATCH*SEQ*DMODEL];
__device__ float g_o[BATCH*SEQ*DMODEL];

// ===========================================================================
// helpers
// ===========================================================================
__device__ __forceinline__ uint32_t smem_u32(const void* p) {
    uint32_t a;
    asm("{ .reg .u64 t; cvta.to.shared.u64 t, %1; cvt.u32.u64 %0, t; }"
        : "=r"(a) : "l"(p));
    return a;
}

#define CP16(dst, src) \
    asm volatile("cp.async.cg.shared.global [%0], [%1], 16;" :: "r"(dst), "l"(src) : "memory")
#define CP_COMMIT() asm volatile("cp.async.commit_group;" ::: "memory")
#define CP_WAIT(n)  asm volatile("cp.async.wait_group %0;" :: "n"(n) : "memory")

// split x into tf32 hi + tf32 lo (x ~= hi + lo, error ~2^-22 |x|)
__device__ __forceinline__ void cvt3(float x, uint32_t& hi, uint32_t& lo) {
    asm("cvt.rna.tf32.f32 %0, %1;" : "=r"(hi) : "f"(x));
    float r = x - __uint_as_float(hi);
    asm("cvt.rna.tf32.f32 %0, %1;" : "=r"(lo) : "f"(r));
}

#define MMA8(c, a, b) \
    asm volatile("mma.sync.aligned.m16n8k8.row.col.f32.tf32.tf32.f32 " \
        "{%0,%1,%2,%3}, {%4,%5,%6,%7}, {%8,%9}, {%0,%1,%2,%3};" \
        : "+f"((c)[0]), "+f"((c)[1]), "+f"((c)[2]), "+f"((c)[3]) \
        : "r"((a)[0]), "r"((a)[1]), "r"((a)[2]), "r"((a)[3]), \
          "r"((b)[0]), "r"((b)[1]))

// ===========================================================================
// mma.sync tf32 GEMM (3x split): C[4096,1024] = A[4096,1024] @ B[1024,1024]
// 128x128 tile/CTA, 8 warps (4 over M x 2 over N), K-chunks of 32,
// cp.async double-buffered. Dynamic smem = 2 * (128*36 + 32*132) * 4 = 70656B.
// ===========================================================================
#define AS_STRIDE 36
#define BS_STRIDE 132
#define AS_F (128 * AS_STRIDE)           // 4608 floats
#define BS_F (32 * BS_STRIDE)            // 4224 floats
#define STG_F (AS_F + BS_F)              // 8832 floats
#define GM_SMEM (2 * STG_F * 4)          // 70656 bytes

extern __shared__ float smf[];

__global__ __launch_bounds__(256, 1) void gemm_mma(const float* __restrict__ A,
                                                   const float* __restrict__ B,
                                                   float* __restrict__ C) {
    const int N = DMODEL, K = DMODEL;
    int tid = threadIdx.x;
    int lane = tid & 31, w = tid >> 5;
    int lq = lane & 3, lr = lane >> 2;
    int wm = (w & 3) * 32, wn = (w >> 2) * 64;
    int n0 = blockIdx.x * 128, m0 = blockIdx.y * 128;
    uint32_t sb = smem_u32(smf);

    float acc[2][8][4];
#pragma unroll
    for (int mt = 0; mt < 2; mt++)
#pragma unroll
        for (int nt = 0; nt < 8; nt++)
#pragma unroll
            for (int j = 0; j < 4; j++) acc[mt][nt][j] = 0.f;

    // per-thread load coords (A: 4 float4s, B: 4 float4s per chunk)
    int ar[4], aq[4], bk[4], bn[4];
#pragma unroll
    for (int i = 0; i < 4; i++) {
        int idx = tid + i * 256;
        ar[i] = idx >> 3; aq[i] = idx & 7;     // A: row 0..127, quad 0..7
        bk[i] = idx >> 5; bn[i] = idx & 31;    // B: k 0..31, n-quad 0..31
    }

    auto issue_chunk = [&](int c) {
        int k0 = c * 32;
        uint32_t base = sb + (uint32_t)(c & 1) * (STG_F * 4);
#pragma unroll
        for (int i = 0; i < 4; i++)
            CP16(base + (uint32_t)(ar[i] * AS_STRIDE + aq[i] * 4) * 4,
                 A + (size_t)(m0 + ar[i]) * K + k0 + aq[i] * 4);
#pragma unroll
        for (int i = 0; i < 4; i++)
            CP16(base + (uint32_t)(AS_F + bk[i] * BS_STRIDE + bn[i] * 4) * 4,
                 B + (size_t)(k0 + bk[i]) * N + n0 + bn[i] * 4);
        CP_COMMIT();
    };

    issue_chunk(0);

    for (int c = 0; c < 32; c++) {
        if (c < 31) { issue_chunk(c + 1); CP_WAIT(1); }
        else        { CP_WAIT(0); }
        __syncthreads();

        const float* As = smf + (c & 1) * STG_F;
        const float* Bs = As + AS_F;

#pragma unroll
        for (int ks = 0; ks < 4; ks++) {
            int kk = ks * 8;
            uint32_t Ah[2][4], Al[2][4];
#pragma unroll
            for (int mt = 0; mt < 2; mt++) {
                int rb = wm + mt * 16 + lr;
                float x0 = As[rb * AS_STRIDE + kk + lq];
                float x1 = As[(rb + 8) * AS_STRIDE + kk + lq];
                float x2 = As[rb * AS_STRIDE + kk + lq + 4];
                float x3 = As[(rb + 8) * AS_STRIDE + kk + lq + 4];
                cvt3(x0, Ah[mt][0], Al[mt][0]);
                cvt3(x1, Ah[mt][1], Al[mt][1]);
                cvt3(x2, Ah[mt][2], Al[mt][2]);
                cvt3(x3, Ah[mt][3], Al[mt][3]);
            }
            uint32_t Bh[8][2], Bl[8][2];
#pragma unroll
            for (int nt = 0; nt < 8; nt++) {
                int cc = wn + nt * 8 + lr;
                float y0 = Bs[(kk + lq) * BS_STRIDE + cc];
                float y1 = Bs[(kk + lq + 4) * BS_STRIDE + cc];
                cvt3(y0, Bh[nt][0], Bl[nt][0]);
                cvt3(y1, Bh[nt][1], Bl[nt][1]);
            }
#pragma unroll
            for (int mt = 0; mt < 2; mt++)
#pragma unroll
                for (int nt = 0; nt < 8; nt++) {
                    MMA8(acc[mt][nt], Ah[mt], Bh[nt]);
                    MMA8(acc[mt][nt], Al[mt], Bh[nt]);
                    MMA8(acc[mt][nt], Ah[mt], Bl[nt]);
                }
        }
        __syncthreads();
    }

    // store C fragments (float2 pairs)
#pragma unroll
    for (int mt = 0; mt < 2; mt++) {
        int row = m0 + wm + mt * 16 + lr;
#pragma unroll
        for (int nt = 0; nt < 8; nt++) {
            int col = n0 + wn + nt * 8 + lq * 2;
            *(float2*)(C + (size_t)row * N + col) =
                make_float2(acc[mt][nt][0], acc[mt][nt][1]);
            *(float2*)(C + (size_t)(row + 8) * N + col) =
                make_float2(acc[mt][nt][2], acc[mt][nt][3]);
        }
    }
}

// ---------------------------------------------------------------------------
// E8 quantization of q (in place). One thread per (b, t, h) row.
// ---------------------------------------------------------------------------
__global__ __launch_bounds__(256) void e8_quant(float* __restrict__ q,
                                                const float* __restrict__ Wt,   // [64,8]
                                                const float* __restrict__ Wf) { // [8,64]
    __shared__ float roots[240][8];
    __shared__ float sWt[64 * 8];
    __shared__ float sWf[8 * 64];
    int tid = threadIdx.x;
    for (int i = tid; i < 512; i += 256) { sWt[i] = Wt[i]; sWf[i] = Wf[i]; }
    for (int i = tid; i < 240 * 8; i += 256) {
        int r = i >> 3, d = i & 7;
        float v;
        if (r < 112) {
            int p = r >> 2, s = r & 3;
            int a = 0, b = 1, cnt = 0; bool done = false;
            for (a = 0; a < 8 && !done; a++) {
                for (b = a + 1; b < 8; b++) {
                    if (cnt == p) { done = true; break; }
                    cnt++;
                }
            }
            a--;
            float si = (s & 2) ? -1.f : 1.f;
            float sj = (s & 1) ? -1.f : 1.f;
            v = (d == a) ? si : ((d == b) ? sj : 0.f);
        } else {
            int k = r - 112;
            int mask = (k << 1) | (__popc(k) & 1);
            v = ((mask >> d) & 1) ? -0.5f : 0.5f;
        }
        roots[r][d] = v;
    }
    __syncthreads();

    int idx = blockIdx.x * 256 + tid;           // over B*T*H = 65536
    int h = idx & 15;
    int row = idx >> 4;
    float* qp = q + (size_t)row * DMODEL + h * HDIM;

    float e8[8];
#pragma unroll
    for (int j = 0; j < 8; j++) e8[j] = 0.f;
    for (int d = 0; d < HDIM; d++) {
        float v = qp[d];
#pragma unroll
        for (int j = 0; j < 8; j++) e8[j] += v * sWt[d * 8 + j];
    }
    int best = 0;
    float bests = 3.4e38f;
    for (int r = 0; r < 240; r++) {
        float dot = 0.f;
#pragma unroll
        for (int j = 0; j < 8; j++) dot += e8[j] * roots[r][j];
        float score = -2.0f * dot + 2.0f;
        if (score < bests) { bests = score; best = r; }
    }
    float rt[8];
#pragma unroll
    for (int j = 0; j < 8; j++) rt[j] = roots[best][j];
    for (int d = 0; d < HDIM; d++) {
        float s = 0.f;
#pragma unroll
        for (int j = 0; j < 8; j++) s += rt[j] * sWf[j * HDIM + d];
        qp[d] = s;
    }
}

// ---------------------------------------------------------------------------
// Flash-style causal attention (fp32), unchanged from R2 (known good).
// ---------------------------------------------------------------------------
__global__ __launch_bounds__(256) void flash_attn(const float* __restrict__ Q,
                                                  const float* __restrict__ K,
                                                  const float* __restrict__ V,
                                                  float* __restrict__ O) {
    __shared__ float Qs[64][65];
    __shared__ float Ks[32][65];
    __shared__ float Vs[32][65];
    __shared__ float Ps[64][33];
    int tid = threadIdx.x;
    int ty = tid >> 4, tx = tid & 15;
    int mblk = blockIdx.x, h = blockIdx.y, b = blockIdx.z;
    size_t base = ((size_t)b * SEQ) * DMODEL + h * HDIM;
    int m0 = mblk * 64;
    const float scale = 0.125f;

    for (int i = tid; i < 64 * 64; i += 256) {
        int r = i >> 6, c = i & 63;
        Qs[r][c] = Q[base + (size_t)(m0 + r) * DMODEL + c];
    }
    float mi[4], li[4], acc[4][4];
#pragma unroll
    for (int i = 0; i < 4; i++) {
        mi[i] = -INFINITY; li[i] = 0.f;
#pragma unroll
        for (int j = 0; j < 4; j++) acc[i][j] = 0.f;
    }
    __syncthreads();

    int ktiles = 2 * mblk + 2;
    for (int nt = 0; nt < ktiles; nt++) {
        int n0 = nt * 32;
        for (int i = tid; i < 32 * 64; i += 256) {
            int r = i >> 6, c = i & 63;
            Ks[r][c] = K[base + (size_t)(n0 + r) * DMODEL + c];
            Vs[r][c] = V[base + (size_t)(n0 + r) * DMODEL + c];
        }
        __syncthreads();

        float s[4][2];
#pragma unroll
        for (int i = 0; i < 4; i++) { s[i][0] = 0.f; s[i][1] = 0.f; }
#pragma unroll
        for (int d = 0; d < HDIM; d++) {
            float a[4], bb[2];
#pragma unroll
            for (int i = 0; i < 4; i++) a[i] = Qs[ty * 4 + i][d];
            bb[0] = Ks[tx * 2 + 0][d];
            bb[1] = Ks[tx * 2 + 1][d];
#pragma unroll
            for (int i = 0; i < 4; i++) {
                s[i][0] += a[i] * bb[0];
                s[i][1] += a[i] * bb[1];
            }
        }
#pragma unroll
        for (int i = 0; i < 4; i++) {
#pragma unroll
            for (int j = 0; j < 2; j++) {
                int qi = m0 + ty * 4 + i, kj = n0 + tx * 2 + j;
                s[i][j] = (kj > qi) ? -1e9f : s[i][j] * scale;
            }
        }
        float tmax[4];
#pragma unroll
        for (int i = 0; i < 4; i++) tmax[i] = fmaxf(s[i][0], s[i][1]);
#pragma unroll
        for (int off = 1; off < 16; off <<= 1)
#pragma unroll
            for (int i = 0; i < 4; i++)
                tmax[i] = fmaxf(tmax[i], __shfl_xor_sync(0xffffffffu, tmax[i], off, 16));

        float mnew[4], alpha[4], rs[4];
#pragma unroll
        for (int i = 0; i < 4; i++) {
            mnew[i] = fmaxf(mi[i], tmax[i]);
            alpha[i] = __expf(mi[i] - mnew[i]);
            float p0 = __expf(s[i][0] - mnew[i]);
            float p1 = __expf(s[i][1] - mnew[i]);
            Ps[ty * 4 + i][tx * 2 + 0] = p0;
            Ps[ty * 4 + i][tx * 2 + 1] = p1;
            rs[i] = p0 + p1;
        }
#pragma unroll
        for (int off = 1; off < 16; off <<= 1)
#pragma unroll
            for (int i = 0; i < 4; i++)
                rs[i] += __shfl_xor_sync(0xffffffffu, rs[i], off, 16);
#pragma unroll
        for (int i = 0; i < 4; i++) {
            li[i] = li[i] * alpha[i] + rs[i];
            mi[i] = mnew[i];
#pragma unroll
            for (int j = 0; j < 4; j++) acc[i][j] *= alpha[i];
        }
        __syncthreads();

#pragma unroll
        for (int kk = 0; kk < 32; kk++) {
            float p[4], vv[4];
#pragma unroll
            for (int i = 0; i < 4; i++) p[i] = Ps[ty * 4 + i][kk];
#pragma unroll
            for (int j = 0; j < 4; j++) vv[j] = Vs[kk][tx * 4 + j];
#pragma unroll
            for (int i = 0; i < 4; i++)
#pragma unroll
                for (int j = 0; j < 4; j++) acc[i][j] += p[i] * vv[j];
        }
        __syncthreads();
    }
#pragma unroll
    for (int i = 0; i < 4; i++) {
        float inv = 1.0f / li[i];
#pragma unroll
        for (int j = 0; j < 4; j++)
            O[base + (size_t)(m0 + ty * 4 + i) * DMODEL + tx * 4 + j] = acc[i][j] * inv;
    }
}

// ---------------------------------------------------------------------------
// Launch
// ---------------------------------------------------------------------------
extern "C" void kernel_launch(void* const* d_in, const int* in_sizes, int n_in,
                              void* d_out, int out_size) {
    const float* x     = (const float*)d_in[0];
    const float* Wq    = (const float*)d_in[1];
    const float* Wk    = (const float*)d_in[2];
    const float* Wv    = (const float*)d_in[3];
    const float* Wte8  = (const float*)d_in[4];
    const float* Wfe8  = (const float*)d_in[5];
    const float* Wout  = (const float*)d_in[6];
    float* out = (float*)d_out;

    float *q, *k, *v, *o;
    cudaGetSymbolAddress((void**)&q, g_q);
    cudaGetSymbolAddress((void**)&k, g_k);
    cudaGetSymbolAddress((void**)&v, g_v);
    cudaGetSymbolAddress((void**)&o, g_o);

    cudaFuncSetAttribute(gemm_mma, cudaFuncAttributeMaxDynamicSharedMemorySize, GM_SMEM);

    dim3 ggrid(DMODEL / 128, MROWS / 128);   // (8, 32)
    gemm_mma<<<ggrid, 256, GM_SMEM>>>(x, Wq, q);
    gemm_mma<<<ggrid, 256, GM_SMEM>>>(x, Wk, k);
    gemm_mma<<<ggrid, 256, GM_SMEM>>>(x, Wv, v);

    e8_quant<<<(BATCH * SEQ * NHEAD) / 256, 256>>>(q, Wte8, Wfe8);

    dim3 fgrid(SEQ / 64, NHEAD, BATCH);
    flash_attn<<<fgrid, 256>>>(q, k, v, o);

    gemm_mma<<<ggrid, 256, GM_SMEM>>>(o, Wout, out);
}

// round 5
// speedup vs baseline: 1.9101x; 1.4158x over previous
#include <cuda_runtime.h>
#include <cuda_bf16.h>
#include <math.h>
#include <stdint.h>

#define BATCH 2
#define SEQ   2048
#define DMODEL 1024
#define NHEAD 16
#define HDIM  64
#define MROWS (BATCH*SEQ)          // 4096
#define NBH   (BATCH*NHEAD)        // 32
#define NROOT 240

// Scratch (device globals; no allocation allowed)
__device__ float g_k[MROWS*DMODEL];
__device__ float g_v[MROWS*DMODEL];
__device__ float g_o[MROWS*DMODEL];
__device__ float g_E[NBH*NROOT*SEQ];      // 62.9 MB: R then exp(R-max) as tf32
__device__ float g_coords[MROWS*128];
__device__ int   g_idx[NBH*SEQ];
__device__ float g_Wqe8[DMODEL*128];
__device__ float g_RW[NROOT*HDIM];
__device__ float g_roots[NROOT*8];

// ===========================================================================
// helpers
// ===========================================================================
__device__ __forceinline__ uint32_t smem_u32(const void* p) {
    uint32_t a;
    asm("{ .reg .u64 t; cvta.to.shared.u64 t, %1; cvt.u32.u64 %0, t; }"
        : "=r"(a) : "l"(p));
    return a;
}
#define CP16(dst, src) \
    asm volatile("cp.async.cg.shared.global [%0], [%1], 16;" :: "r"(dst), "l"(src) : "memory")
#define CP_COMMIT() asm volatile("cp.async.commit_group;" ::: "memory")
#define CP_WAIT(n)  asm volatile("cp.async.wait_group %0;" :: "n"(n) : "memory")

__device__ __forceinline__ void cvt3(float x, uint32_t& hi, uint32_t& lo) {
    asm("cvt.rna.tf32.f32 %0, %1;" : "=r"(hi) : "f"(x));
    float r = x - __uint_as_float(hi);
    asm("cvt.rna.tf32.f32 %0, %1;" : "=r"(lo) : "f"(r));
}
__device__ __forceinline__ float rtf32(float x) {
    uint32_t t;
    asm("cvt.rna.tf32.f32 %0, %1;" : "=r"(t) : "f"(x));
    return __uint_as_float(t);
}

#define MMA8(c, a, b) \
    asm volatile("mma.sync.aligned.m16n8k8.row.col.f32.tf32.tf32.f32 " \
        "{%0,%1,%2,%3}, {%4,%5,%6,%7}, {%8,%9}, {%0,%1,%2,%3};" \
        : "+f"((c)[0]), "+f"((c)[1]), "+f"((c)[2]), "+f"((c)[3]) \
        : "r"((a)[0]), "r"((a)[1]), "r"((a)[2]), "r"((a)[3]), \
          "r"((b)[0]), "r"((b)[1]))

// ===========================================================================
// mma.sync tf32 GEMM (3x split), generalized N,K: C[M,N] = A[M,K] @ B[K,N]
// 128x128 tile/CTA, 8 warps, K-chunks of 32, cp.async double-buffered.
// ===========================================================================
#define AS_STRIDE 36
#define BS_STRIDE 132
#define AS_F (128 * AS_STRIDE)
#define BS_F (32 * BS_STRIDE)
#define STG_F (AS_F + BS_F)
#define GM_SMEM (2 * STG_F * 4)

extern __shared__ float smf[];

__global__ __launch_bounds__(256, 1) void gemm_mma(const float* __restrict__ A,
                                                   const float* __restrict__ B,
                                                   float* __restrict__ C,
                                                   int N, int K) {
    int tid = threadIdx.x;
    int lane = tid & 31, w = tid >> 5;
    int lq = lane & 3, lr = lane >> 2;
    int wm = (w & 3) * 32, wn = (w >> 2) * 64;
    int n0 = blockIdx.x * 128, m0 = blockIdx.y * 128;
    uint32_t sb = smem_u32(smf);

    float acc[2][8][4];
#pragma unroll
    for (int mt = 0; mt < 2; mt++)
#pragma unroll
        for (int nt = 0; nt < 8; nt++)
#pragma unroll
            for (int j = 0; j < 4; j++) acc[mt][nt][j] = 0.f;

    int ar[4], aq[4], bk[4], bn[4];
#pragma unroll
    for (int i = 0; i < 4; i++) {
        int idx = tid + i * 256;
        ar[i] = idx >> 3; aq[i] = idx & 7;
        bk[i] = idx >> 5; bn[i] = idx & 31;
    }

    auto issue_chunk = [&](int c) {
        int k0 = c * 32;
        uint32_t base = sb + (uint32_t)(c & 1) * (STG_F * 4);
#pragma unroll
        for (int i = 0; i < 4; i++)
            CP16(base + (uint32_t)(ar[i] * AS_STRIDE + aq[i] * 4) * 4,
                 A + (size_t)(m0 + ar[i]) * K + k0 + aq[i] * 4);
#pragma unroll
        for (int i = 0; i < 4; i++)
            CP16(base + (uint32_t)(AS_F + bk[i] * BS_STRIDE + bn[i] * 4) * 4,
                 B + (size_t)(k0 + bk[i]) * N + n0 + bn[i] * 4);
        CP_COMMIT();
    };

    issue_chunk(0);
    int nchunk = K >> 5;

    for (int c = 0; c < nchunk; c++) {
        if (c < nchunk - 1) { issue_chunk(c + 1); CP_WAIT(1); }
        else                { CP_WAIT(0); }
        __syncthreads();

        const float* As = smf + (c & 1) * STG_F;
        const float* Bs = As + AS_F;

#pragma unroll
        for (int ks = 0; ks < 4; ks++) {
            int kk = ks * 8;
            uint32_t Ah[2][4], Al[2][4];
#pragma unroll
            for (int mt = 0; mt < 2; mt++) {
                int rb = wm + mt * 16 + lr;
                cvt3(As[rb * AS_STRIDE + kk + lq],           Ah[mt][0], Al[mt][0]);
                cvt3(As[(rb + 8) * AS_STRIDE + kk + lq],     Ah[mt][1], Al[mt][1]);
                cvt3(As[rb * AS_STRIDE + kk + lq + 4],       Ah[mt][2], Al[mt][2]);
                cvt3(As[(rb + 8) * AS_STRIDE + kk + lq + 4], Ah[mt][3], Al[mt][3]);
            }
            uint32_t Bh[8][2], Bl[8][2];
#pragma unroll
            for (int nt = 0; nt < 8; nt++) {
                int cc = wn + nt * 8 + lr;
                cvt3(Bs[(kk + lq) * BS_STRIDE + cc],     Bh[nt][0], Bl[nt][0]);
                cvt3(Bs[(kk + lq + 4) * BS_STRIDE + cc], Bh[nt][1], Bl[nt][1]);
            }
#pragma unroll
            for (int mt = 0; mt < 2; mt++)
#pragma unroll
                for (int nt = 0; nt < 8; nt++) {
                    MMA8(acc[mt][nt], Ah[mt], Bh[nt]);
                    MMA8(acc[mt][nt], Al[mt], Bh[nt]);
                    MMA8(acc[mt][nt], Ah[mt], Bl[nt]);
                }
        }
        __syncthreads();
    }

#pragma unroll
    for (int mt = 0; mt < 2; mt++) {
        int row = m0 + wm + mt * 16 + lr;
#pragma unroll
        for (int nt = 0; nt < 8; nt++) {
            int col = n0 + wn + nt * 8 + lq * 2;
            *(float2*)(C + (size_t)row * N + col) =
                make_float2(acc[mt][nt][0], acc[mt][nt][1]);
            *(float2*)(C + (size_t)(row + 8) * N + col) =
                make_float2(acc[mt][nt][2], acc[mt][nt][3]);
        }
    }
}

// ===========================================================================
// Wqe8[in][h*8+j] = sum_e Wq[in][h*64+e] * Wt[e][j]   (folded Q->E8 projection)
// ===========================================================================
__global__ __launch_bounds__(256) void build_wqe8(const float* __restrict__ Wq,
                                                  const float* __restrict__ Wt) {
    int i = blockIdx.x * 256 + threadIdx.x;      // < 1024*128
    int in = i >> 7, c = i & 127, h = c >> 3, j = c & 7;
    float s = 0.f;
#pragma unroll
    for (int e = 0; e < 64; e++) s += Wq[(size_t)in * DMODEL + h * 64 + e] * Wt[e * 8 + j];
    g_Wqe8[i] = s;
}

// ===========================================================================
// roots (exact reference enumeration) and RW = 0.125 * roots @ Wf
// ===========================================================================
__global__ __launch_bounds__(256) void build_tables(const float* __restrict__ Wf) {
    __shared__ float roots[NROOT * 8];
    int tid = threadIdx.x;
    for (int i = tid; i < NROOT * 8; i += 256) {
        int r = i >> 3, d = i & 7;
        float v;
        if (r < 112) {
            int p = r >> 2, s = r & 3;
            int a = 0, b = 1, cnt = 0; bool done = false;
            for (a = 0; a < 8 && !done; a++) {
                for (b = a + 1; b < 8; b++) {
                    if (cnt == p) { done = true; break; }
                    cnt++;
                }
            }
            a--;
            float si = (s & 2) ? -1.f : 1.f;
            float sj = (s & 1) ? -1.f : 1.f;
            v = (d == a) ? si : ((d == b) ? sj : 0.f);
        } else {
            int k = r - 112;
            int mask = (k << 1) | (__popc(k) & 1);
            v = ((mask >> d) & 1) ? -0.5f : 0.5f;
        }
        roots[i] = v;
        g_roots[i] = v;
    }
    __syncthreads();
    for (int i = tid; i < NROOT * HDIM; i += 256) {
        int r = i >> 6, d = i & 63;
        float s = 0.f;
#pragma unroll
        for (int j = 0; j < 8; j++) s += roots[r * 8 + j] * Wf[j * HDIM + d];
        g_RW[i] = 0.125f * s;
    }
}

// ===========================================================================
// argmin over 240 roots; coords = g_coords[(b*T+t)*128 + h*8]
// ===========================================================================
__global__ __launch_bounds__(256) void e8_argmin() {
    __shared__ float roots[NROOT * 8];
    int tid = threadIdx.x;
    for (int i = tid; i < NROOT * 8; i += 256) roots[i] = g_roots[i];
    __syncthreads();
    int id = blockIdx.x * 256 + tid;             // (b, h, t)
    int t = id & (SEQ - 1), h = (id >> 11) & 15, b = id >> 15;
    const float* cp = g_coords + ((size_t)(b * SEQ + t)) * 128 + h * 8;
    float x[8];
#pragma unroll
    for (int j = 0; j < 8; j++) x[j] = cp[j];
    int best = 0; float bs = 3.4e38f;
    for (int r = 0; r < NROOT; r++) {
        float dot = 0.f;
#pragma unroll
        for (int j = 0; j < 8; j++) dot += x[j] * roots[r * 8 + j];
        float sc = -2.f * dot + 2.f;
        if (sc < bs) { bs = sc; best = r; }
    }
    g_idx[id] = best;
}

// ===========================================================================
// R[bh][m][t] = sum_d RW[m][d] * K[b][t][h*64+d]   (240 x 2048 per bh)
// ===========================================================================
__global__ __launch_bounds__(256) void rgemm() {
    __shared__ float As[64][65], Bs[64][65];
    int tid = threadIdx.x, ty = tid >> 4, tx = tid & 15;
    int t0 = blockIdx.x * 64, m0 = blockIdx.y * 64, bh = blockIdx.z;
    int b = bh >> 4, h = bh & 15;
    for (int i = tid; i < 4096; i += 256) {
        int r = i >> 6, c = i & 63; int m = m0 + r;
        As[r][c] = (m < NROOT) ? g_RW[m * HDIM + c] : 0.f;
        Bs[r][c] = g_k[((size_t)b * SEQ + t0 + r) * DMODEL + h * HDIM + c];
    }
    __syncthreads();
    float acc[4][4] = {};
#pragma unroll
    for (int d = 0; d < 64; d++) {
        float a[4], bb[4];
#pragma unroll
        for (int i = 0; i < 4; i++) a[i] = As[ty * 4 + i][d];
#pragma unroll
        for (int j = 0; j < 4; j++) bb[j] = Bs[tx * 4 + j][d];
#pragma unroll
        for (int i = 0; i < 4; i++)
#pragma unroll
            for (int j = 0; j < 4; j++) acc[i][j] += a[i] * bb[j];
    }
    float* Rb = g_E + (size_t)bh * NROOT * SEQ;
#pragma unroll
    for (int i = 0; i < 4; i++) {
        int m = m0 + ty * 4 + i;
        if (m < NROOT)
#pragma unroll
            for (int j = 0; j < 4; j++)
                Rb[(size_t)m * SEQ + t0 + tx * 4 + j] = acc[i][j];
    }
}

// ===========================================================================
// per-row (full-row) max, then E = tf32(exp(R - max)) in place. 1 warp/row.
// ===========================================================================
__global__ __launch_bounds__(256) void rowmax_exp() {
    int row = blockIdx.x * 8 + (threadIdx.x >> 5);
    int lane = threadIdx.x & 31;
    float* p = g_E + (size_t)row * SEQ;
    float mx = -INFINITY;
    for (int i = lane; i < SEQ; i += 32) mx = fmaxf(mx, p[i]);
#pragma unroll
    for (int o = 16; o; o >>= 1) mx = fmaxf(mx, __shfl_xor_sync(0xffffffffu, mx, o));
    for (int i = lane; i < SEQ; i += 32)
        p[i] = rtf32(__expf(p[i] - mx));
}

// round V to tf32 in place
__global__ __launch_bounds__(256) void round_v() {
    int i = blockIdx.x * 256 + threadIdx.x;
    g_v[i] = rtf32(g_v[i]);
}

// ===========================================================================
// Attention: gather P rows from E by root index, causal-zero, rowsum,
// O = (P@V)/l via single-tf32 mma.sync. CTA = 64 q-rows x (b,h). 128 thr.
// ===========================================================================
#define PST 68
#define VST 72
__global__ __launch_bounds__(128) void attn_pv() {
    __shared__ float Ps[64 * PST];
    __shared__ float Vs[64 * VST];
    __shared__ float lsum[64];
    __shared__ int   sidx[64];

    int tid = threadIdx.x;
    int lane = tid & 31, w = tid >> 5;
    int lq = lane & 3, lr = lane >> 2;
    int mblk = blockIdx.x, h = blockIdx.y, b = blockIdx.z;
    int bh = b * NHEAD + h;
    int m0 = mblk * 64;

    if (tid < 64) {
        sidx[tid] = g_idx[bh * SEQ + m0 + tid];
        lsum[tid] = 0.f;
    }
    __syncthreads();

    int row = tid >> 1, half = tid & 1;
    const float* Erow = g_E + ((size_t)bh * NROOT + sidx[row]) * SEQ;
    int qglob = m0 + row;

    float acc[8][4];
#pragma unroll
    for (int nt = 0; nt < 8; nt++)
#pragma unroll
        for (int j = 0; j < 4; j++) acc[nt][j] = 0.f;

    int ntiles = mblk + 1;
    for (int nt0 = 0; nt0 < ntiles; nt0++) {
        int n0 = nt0 * 64;
        const float* src  = Erow + n0 + half * 32;
        const float* vsrc = g_v + ((size_t)b * SEQ + n0 + row) * DMODEL + h * HDIM + half * 32;
        float s = 0.f;
#pragma unroll
        for (int u = 0; u < 8; u++) {
            float4 p = *(const float4*)(src + u * 4);
            int kb = n0 + half * 32 + u * 4;
            if (kb + 3 > qglob) {
                if (kb + 0 > qglob) p.x = 0.f;
                if (kb + 1 > qglob) p.y = 0.f;
                if (kb + 2 > qglob) p.z = 0.f;
                if (kb + 3 > qglob) p.w = 0.f;
            }
            s += (p.x + p.y) + (p.z + p.w);
            *(float4*)(&Ps[row * PST + half * 32 + u * 4]) = p;
            float4 v4 = *(const float4*)(vsrc + u * 4);
            *(float4*)(&Vs[row * VST + half * 32 + u * 4]) = v4;
        }
        s += __shfl_xor_sync(0xffffffffu, s, 1);
        if (!half) lsum[row] += s;
        __syncthreads();

        int wm = w * 16;
#pragma unroll
        for (int ks = 0; ks < 8; ks++) {
            uint32_t a[4];
            a[0] = __float_as_uint(Ps[(wm + lr) * PST + ks * 8 + lq]);
            a[1] = __float_as_uint(Ps[(wm + lr + 8) * PST + ks * 8 + lq]);
            a[2] = __float_as_uint(Ps[(wm + lr) * PST + ks * 8 + lq + 4]);
            a[3] = __float_as_uint(Ps[(wm + lr + 8) * PST + ks * 8 + lq + 4]);
#pragma unroll
            for (int nt = 0; nt < 8; nt++) {
                uint32_t bb[2];
                bb[0] = __float_as_uint(Vs[(ks * 8 + lq) * VST + nt * 8 + lr]);
                bb[1] = __float_as_uint(Vs[(ks * 8 + lq + 4) * VST + nt * 8 + lr]);
                MMA8(acc[nt], a, bb);
            }
        }
        __syncthreads();
    }

    int wm = w * 16;
    int r0 = wm + lr, r1 = r0 + 8;
    float inv0 = 1.0f / lsum[r0], inv1 = 1.0f / lsum[r1];
#pragma unroll
    for (int nt = 0; nt < 8; nt++) {
        int d = h * HDIM + nt * 8 + 2 * lq;
        size_t o0 = ((size_t)b * SEQ + m0 + r0) * DMODEL + d;
        size_t o1 = ((size_t)b * SEQ + m0 + r1) * DMODEL + d;
        g_o[o0] = acc[nt][0] * inv0; g_o[o0 + 1] = acc[nt][1] * inv0;
        g_o[o1] = acc[nt][2] * inv1; g_o[o1 + 1] = acc[nt][3] * inv1;
    }
}

// ---------------------------------------------------------------------------
// Launch
// ---------------------------------------------------------------------------
extern "C" void kernel_launch(void* const* d_in, const int* in_sizes, int n_in,
                              void* d_out, int out_size) {
    const float* x     = (const float*)d_in[0];
    const float* Wq    = (const float*)d_in[1];
    const float* Wk    = (const float*)d_in[2];
    const float* Wv    = (const float*)d_in[3];
    const float* Wte8  = (const float*)d_in[4];
    const float* Wfe8  = (const float*)d_in[5];
    const float* Wout  = (const float*)d_in[6];
    float* out = (float*)d_out;

    float *k, *v, *o, *coords, *wqe8;
    cudaGetSymbolAddress((void**)&k, g_k);
    cudaGetSymbolAddress((void**)&v, g_v);
    cudaGetSymbolAddress((void**)&o, g_o);
    cudaGetSymbolAddress((void**)&coords, g_coords);
    cudaGetSymbolAddress((void**)&wqe8, g_Wqe8);

    cudaFuncSetAttribute(gemm_mma, cudaFuncAttributeMaxDynamicSharedMemorySize, GM_SMEM);

    build_wqe8<<<512, 256>>>(Wq, Wte8);
    build_tables<<<1, 256>>>(Wfe8);

    gemm_mma<<<dim3(1, 32), 256, GM_SMEM>>>(x, wqe8, coords, 128, DMODEL);
    e8_argmin<<<256, 256>>>();

    gemm_mma<<<dim3(8, 32), 256, GM_SMEM>>>(x, Wk, k, DMODEL, DMODEL);
    gemm_mma<<<dim3(8, 32), 256, GM_SMEM>>>(x, Wv, v, DMODEL, DMODEL);
    round_v<<<MROWS * DMODEL / 256, 256>>>();

    rgemm<<<dim3(32, 4, 32), 256>>>();
    rowmax_exp<<<NBH * NROOT / 8, 256>>>();

    attn_pv<<<dim3(32, 16, 2), 128>>>();

    gemm_mma<<<dim3(8, 32), 256, GM_SMEM>>>(o, Wout, out, DMODEL, DMODEL);
}

// round 6
// speedup vs baseline: 2.5364x; 1.3279x over previous
#include <cuda_runtime.h>
#include <cuda_bf16.h>
#include <math.h>
#include <stdint.h>

#define BATCH 2
#define SEQ   2048
#define DMODEL 1024
#define NHEAD 16
#define HDIM  64
#define MROWS (BATCH*SEQ)          // 4096
#define NBH   (BATCH*NHEAD)        // 32
#define NROOT 240

// Scratch (device globals; no allocation allowed)
__device__ float g_k[MROWS*DMODEL];
__device__ float g_v[MROWS*DMODEL];
__device__ float g_o[MROWS*DMODEL];
__device__ float g_E[NBH*NROOT*SEQ];      // 62.9 MB: R then exp(R-max) as tf32
__device__ float g_coords[MROWS*128];
__device__ int   g_idx[NBH*SEQ];
__device__ float g_Wqe8[DMODEL*128];
__device__ float g_RW[NROOT*HDIM];
__device__ float g_roots[NROOT*8];

// ===========================================================================
// helpers
// ===========================================================================
__device__ __forceinline__ uint32_t smem_u32(const void* p) {
    uint32_t a;
    asm("{ .reg .u64 t; cvta.to.shared.u64 t, %1; cvt.u32.u64 %0, t; }"
        : "=r"(a) : "l"(p));
    return a;
}
#define CP16(dst, src) \
    asm volatile("cp.async.cg.shared.global [%0], [%1], 16;" :: "r"(dst), "l"(src) : "memory")
#define CP_COMMIT() asm volatile("cp.async.commit_group;" ::: "memory")
#define CP_WAIT(n)  asm volatile("cp.async.wait_group %0;" :: "n"(n) : "memory")

__device__ __forceinline__ void cvt3(float x, uint32_t& hi, uint32_t& lo) {
    asm("cvt.rna.tf32.f32 %0, %1;" : "=r"(hi) : "f"(x));
    float r = x - __uint_as_float(hi);
    asm("cvt.rna.tf32.f32 %0, %1;" : "=r"(lo) : "f"(r));
}
__device__ __forceinline__ uint32_t cvt1(float x) {
    uint32_t t;
    asm("cvt.rna.tf32.f32 %0, %1;" : "=r"(t) : "f"(x));
    return t;
}
__device__ __forceinline__ float rtf32(float x) { return __uint_as_float(cvt1(x)); }

#define MMA8(c, a, b) \
    asm volatile("mma.sync.aligned.m16n8k8.row.col.f32.tf32.tf32.f32 " \
        "{%0,%1,%2,%3}, {%4,%5,%6,%7}, {%8,%9}, {%0,%1,%2,%3};" \
        : "+f"((c)[0]), "+f"((c)[1]), "+f"((c)[2]), "+f"((c)[3]) \
        : "r"((a)[0]), "r"((a)[1]), "r"((a)[2]), "r"((a)[3]), \
          "r"((b)[0]), "r"((b)[1]))

// ===========================================================================
// mma.sync tf32 GEMM, templated precision: C[M,N] = A[M,K] @ B[K,N]
// SPLIT3=true: 3-product hi/lo split (~1e-7 rel). false: single tf32 (~2e-4).
// 128x128 tile/CTA, 8 warps, K-chunks of 32, cp.async double-buffered.
// blockIdx.z selects (B0,C0) vs (B1,C1) so two GEMMs can share one launch.
// ===========================================================================
#define AS_STRIDE 36
#define BS_STRIDE 132
#define AS_F (128 * AS_STRIDE)
#define BS_F (32 * BS_STRIDE)
#define STG_F (AS_F + BS_F)
#define GM_SMEM (2 * STG_F * 4)

extern __shared__ float smf[];

template <bool SPLIT3>
__global__ __launch_bounds__(256, 1) void gemm_mma(const float* __restrict__ A,
                                                   const float* __restrict__ B0,
                                                   float* __restrict__ C0,
                                                   const float* __restrict__ B1,
                                                   float* __restrict__ C1,
                                                   int N, int K) {
    const float* B = blockIdx.z ? B1 : B0;
    float* C = blockIdx.z ? C1 : C0;
    int tid = threadIdx.x;
    int lane = tid & 31, w = tid >> 5;
    int lq = lane & 3, lr = lane >> 2;
    int wm = (w & 3) * 32, wn = (w >> 2) * 64;
    int n0 = blockIdx.x * 128, m0 = blockIdx.y * 128;
    uint32_t sb = smem_u32(smf);

    float acc[2][8][4];
#pragma unroll
    for (int mt = 0; mt < 2; mt++)
#pragma unroll
        for (int nt = 0; nt < 8; nt++)
#pragma unroll
            for (int j = 0; j < 4; j++) acc[mt][nt][j] = 0.f;

    int ar[4], aq[4], bk[4], bn[4];
#pragma unroll
    for (int i = 0; i < 4; i++) {
        int idx = tid + i * 256;
        ar[i] = idx >> 3; aq[i] = idx & 7;
        bk[i] = idx >> 5; bn[i] = idx & 31;
    }

    auto issue_chunk = [&](int c) {
        int k0 = c * 32;
        uint32_t base = sb + (uint32_t)(c & 1) * (STG_F * 4);
#pragma unroll
        for (int i = 0; i < 4; i++)
            CP16(base + (uint32_t)(ar[i] * AS_STRIDE + aq[i] * 4) * 4,
                 A + (size_t)(m0 + ar[i]) * K + k0 + aq[i] * 4);
#pragma unroll
        for (int i = 0; i < 4; i++)
            CP16(base + (uint32_t)(AS_F + bk[i] * BS_STRIDE + bn[i] * 4) * 4,
                 B + (size_t)(k0 + bk[i]) * N + n0 + bn[i] * 4);
        CP_COMMIT();
    };

    issue_chunk(0);
    int nchunk = K >> 5;

    for (int c = 0; c < nchunk; c++) {
        if (c < nchunk - 1) { issue_chunk(c + 1); CP_WAIT(1); }
        else                { CP_WAIT(0); }
        __syncthreads();

        const float* As = smf + (c & 1) * STG_F;
        const float* Bs = As + AS_F;

#pragma unroll
        for (int ks = 0; ks < 4; ks++) {
            int kk = ks * 8;
            uint32_t Ah[2][4], Al[2][4];
#pragma unroll
            for (int mt = 0; mt < 2; mt++) {
                int rb = wm + mt * 16 + lr;
                if (SPLIT3) {
                    cvt3(As[rb * AS_STRIDE + kk + lq],           Ah[mt][0], Al[mt][0]);
                    cvt3(As[(rb + 8) * AS_STRIDE + kk + lq],     Ah[mt][1], Al[mt][1]);
                    cvt3(As[rb * AS_STRIDE + kk + lq + 4],       Ah[mt][2], Al[mt][2]);
                    cvt3(As[(rb + 8) * AS_STRIDE + kk + lq + 4], Ah[mt][3], Al[mt][3]);
                } else {
                    Ah[mt][0] = cvt1(As[rb * AS_STRIDE + kk + lq]);
                    Ah[mt][1] = cvt1(As[(rb + 8) * AS_STRIDE + kk + lq]);
                    Ah[mt][2] = cvt1(As[rb * AS_STRIDE + kk + lq + 4]);
                    Ah[mt][3] = cvt1(As[(rb + 8) * AS_STRIDE + kk + lq + 4]);
                }
            }
            uint32_t Bh[8][2], Bl[8][2];
#pragma unroll
            for (int nt = 0; nt < 8; nt++) {
                int cc = wn + nt * 8 + lr;
                if (SPLIT3) {
                    cvt3(Bs[(kk + lq) * BS_STRIDE + cc],     Bh[nt][0], Bl[nt][0]);
                    cvt3(Bs[(kk + lq + 4) * BS_STRIDE + cc], Bh[nt][1], Bl[nt][1]);
                } else {
                    Bh[nt][0] = cvt1(Bs[(kk + lq) * BS_STRIDE + cc]);
                    Bh[nt][1] = cvt1(Bs[(kk + lq + 4) * BS_STRIDE + cc]);
                }
            }
#pragma unroll
            for (int mt = 0; mt < 2; mt++)
#pragma unroll
                for (int nt = 0; nt < 8; nt++) {
                    MMA8(acc[mt][nt], Ah[mt], Bh[nt]);
                    if (SPLIT3) {
                        MMA8(acc[mt][nt], Al[mt], Bh[nt]);
                        MMA8(acc[mt][nt], Ah[mt], Bl[nt]);
                    }
                }
        }
        __syncthreads();
    }

#pragma unroll
    for (int mt = 0; mt < 2; mt++) {
        int row = m0 + wm + mt * 16 + lr;
#pragma unroll
        for (int nt = 0; nt < 8; nt++) {
            int col = n0 + wn + nt * 8 + lq * 2;
            *(float2*)(C + (size_t)row * N + col) =
                make_float2(acc[mt][nt][0], acc[mt][nt][1]);
            *(float2*)(C + (size_t)(row + 8) * N + col) =
                make_float2(acc[mt][nt][2], acc[mt][nt][3]);
        }
    }
}

// ===========================================================================
// Wqe8[in][h*8+j] = sum_e Wq[in][h*64+e] * Wt[e][j]   (folded Q->E8 projection)
// ===========================================================================
__global__ __launch_bounds__(256) void build_wqe8(const float* __restrict__ Wq,
                                                  const float* __restrict__ Wt) {
    int i = blockIdx.x * 256 + threadIdx.x;      // < 1024*128
    int in = i >> 7, c = i & 127, h = c >> 3, j = c & 7;
    float s = 0.f;
#pragma unroll
    for (int e = 0; e < 64; e++) s += Wq[(size_t)in * DMODEL + h * 64 + e] * Wt[e * 8 + j];
    g_Wqe8[i] = s;
}

// ===========================================================================
// roots (exact reference enumeration) and RW = 0.125 * roots @ Wf
// ===========================================================================
__global__ __launch_bounds__(256) void build_tables(const float* __restrict__ Wf) {
    __shared__ float roots[NROOT * 8];
    int tid = threadIdx.x;
    for (int i = tid; i < NROOT * 8; i += 256) {
        int r = i >> 3, d = i & 7;
        float v;
        if (r < 112) {
            int p = r >> 2, s = r & 3;
            int a = 0, b = 1, cnt = 0; bool done = false;
            for (a = 0; a < 8 && !done; a++) {
                for (b = a + 1; b < 8; b++) {
                    if (cnt == p) { done = true; break; }
                    cnt++;
                }
            }
            a--;
            float si = (s & 2) ? -1.f : 1.f;
            float sj = (s & 1) ? -1.f : 1.f;
            v = (d == a) ? si : ((d == b) ? sj : 0.f);
        } else {
            int k = r - 112;
            int mask = (k << 1) | (__popc(k) & 1);
            v = ((mask >> d) & 1) ? -0.5f : 0.5f;
        }
        roots[i] = v;
        g_roots[i] = v;
    }
    __syncthreads();
    for (int i = tid; i < NROOT * HDIM; i += 256) {
        int r = i >> 6, d = i & 63;
        float s = 0.f;
#pragma unroll
        for (int j = 0; j < 8; j++) s += roots[r * 8 + j] * Wf[j * HDIM + d];
        g_RW[i] = 0.125f * s;
    }
}

// ===========================================================================
// argmin over 240 roots; coords = g_coords[(b*T+t)*128 + h*8]
// ===========================================================================
__global__ __launch_bounds__(256) void e8_argmin() {
    __shared__ float roots[NROOT * 8];
    int tid = threadIdx.x;
    for (int i = tid; i < NROOT * 8; i += 256) roots[i] = g_roots[i];
    __syncthreads();
    int id = blockIdx.x * 256 + tid;             // (b, h, t)
    int t = id & (SEQ - 1), h = (id >> 11) & 15, b = id >> 15;
    const float* cp = g_coords + ((size_t)(b * SEQ + t)) * 128 + h * 8;
    float x[8];
#pragma unroll
    for (int j = 0; j < 8; j++) x[j] = cp[j];
    int best = 0; float bs = 3.4e38f;
    for (int r = 0; r < NROOT; r++) {
        float dot = 0.f;
#pragma unroll
        for (int j = 0; j < 8; j++) dot += x[j] * roots[r * 8 + j];
        float sc = -2.f * dot + 2.f;
        if (sc < bs) { bs = sc; best = r; }
    }
    g_idx[id] = best;
}

// ===========================================================================
// R[bh][m][t] = sum_d RW[m][d] * K[b][t][h*64+d]   (240 x 2048 per bh)
// ===========================================================================
__global__ __launch_bounds__(256) void rgemm() {
    __shared__ float As[64][65], Bs[64][65];
    int tid = threadIdx.x, ty = tid >> 4, tx = tid & 15;
    int t0 = blockIdx.x * 64, m0 = blockIdx.y * 64, bh = blockIdx.z;
    int b = bh >> 4, h = bh & 15;
    for (int i = tid; i < 4096; i += 256) {
        int r = i >> 6, c = i & 63; int m = m0 + r;
        As[r][c] = (m < NROOT) ? g_RW[m * HDIM + c] : 0.f;
        Bs[r][c] = g_k[((size_t)b * SEQ + t0 + r) * DMODEL + h * HDIM + c];
    }
    __syncthreads();
    float acc[4][4] = {};
#pragma unroll
    for (int d = 0; d < 64; d++) {
        float a[4], bb[4];
#pragma unroll
        for (int i = 0; i < 4; i++) a[i] = As[ty * 4 + i][d];
#pragma unroll
        for (int j = 0; j < 4; j++) bb[j] = Bs[tx * 4 + j][d];
#pragma unroll
        for (int i = 0; i < 4; i++)
#pragma unroll
            for (int j = 0; j < 4; j++) acc[i][j] += a[i] * bb[j];
    }
    float* Rb = g_E + (size_t)bh * NROOT * SEQ;
#pragma unroll
    for (int i = 0; i < 4; i++) {
        int m = m0 + ty * 4 + i;
        if (m < NROOT)
#pragma unroll
            for (int j = 0; j < 4; j++)
                Rb[(size_t)m * SEQ + t0 + tx * 4 + j] = acc[i][j];
    }
}

// ===========================================================================
// per-row (full-row) max, then E = tf32(exp(R - max)) in place. 1 warp/row.
// ===========================================================================
__global__ __launch_bounds__(256) void rowmax_exp() {
    int row = blockIdx.x * 8 + (threadIdx.x >> 5);
    int lane = threadIdx.x & 31;
    float* p = g_E + (size_t)row * SEQ;
    float mx = -INFINITY;
    for (int i = lane; i < SEQ; i += 32) mx = fmaxf(mx, p[i]);
#pragma unroll
    for (int o = 16; o; o >>= 1) mx = fmaxf(mx, __shfl_xor_sync(0xffffffffu, mx, o));
    for (int i = lane; i < SEQ; i += 32)
        p[i] = rtf32(__expf(p[i] - mx));
}

// round V to tf32 in place
__global__ __launch_bounds__(256) void round_v() {
    int i = blockIdx.x * 256 + threadIdx.x;
    g_v[i] = rtf32(g_v[i]);
}

// ===========================================================================
// Attention: gather P rows from E by root index, causal-zero, rowsum,
// O = (P@V)/l via single-tf32 mma.sync. CTA = 64 q-rows x (b,h). 128 thr.
// ===========================================================================
#define PST 68
#define VST 72
__global__ __launch_bounds__(128) void attn_pv() {
    __shared__ float Ps[64 * PST];
    __shared__ float Vs[64 * VST];
    __shared__ float lsum[64];
    __shared__ int   sidx[64];

    int tid = threadIdx.x;
    int lane = tid & 31, w = tid >> 5;
    int lq = lane & 3, lr = lane >> 2;
    int mblk = blockIdx.x, h = blockIdx.y, b = blockIdx.z;
    int bh = b * NHEAD + h;
    int m0 = mblk * 64;

    if (tid < 64) {
        sidx[tid] = g_idx[bh * SEQ + m0 + tid];
        lsum[tid] = 0.f;
    }
    __syncthreads();

    int row = tid >> 1, half = tid & 1;
    const float* Erow = g_E + ((size_t)bh * NROOT + sidx[row]) * SEQ;
    int qglob = m0 + row;

    float acc[8][4];
#pragma unroll
    for (int nt = 0; nt < 8; nt++)
#pragma unroll
        for (int j = 0; j < 4; j++) acc[nt][j] = 0.f;

    int ntiles = mblk + 1;
    for (int nt0 = 0; nt0 < ntiles; nt0++) {
        int n0 = nt0 * 64;
        const float* src  = Erow + n0 + half * 32;
        const float* vsrc = g_v + ((size_t)b * SEQ + n0 + row) * DMODEL + h * HDIM + half * 32;
        float s = 0.f;
#pragma unroll
        for (int u = 0; u < 8; u++) {
            float4 p = *(const float4*)(src + u * 4);
            int kb = n0 + half * 32 + u * 4;
            if (kb + 3 > qglob) {
                if (kb + 0 > qglob) p.x = 0.f;
                if (kb + 1 > qglob) p.y = 0.f;
                if (kb + 2 > qglob) p.z = 0.f;
                if (kb + 3 > qglob) p.w = 0.f;
            }
            s += (p.x + p.y) + (p.z + p.w);
            *(float4*)(&Ps[row * PST + half * 32 + u * 4]) = p;
            float4 v4 = *(const float4*)(vsrc + u * 4);
            *(float4*)(&Vs[row * VST + half * 32 + u * 4]) = v4;
        }
        s += __shfl_xor_sync(0xffffffffu, s, 1);
        if (!half) lsum[row] += s;
        __syncthreads();

        int wm = w * 16;
#pragma unroll
        for (int ks = 0; ks < 8; ks++) {
            uint32_t a[4];
            a[0] = __float_as_uint(Ps[(wm + lr) * PST + ks * 8 + lq]);
            a[1] = __float_as_uint(Ps[(wm + lr + 8) * PST + ks * 8 + lq]);
            a[2] = __float_as_uint(Ps[(wm + lr) * PST + ks * 8 + lq + 4]);
            a[3] = __float_as_uint(Ps[(wm + lr + 8) * PST + ks * 8 + lq + 4]);
#pragma unroll
            for (int nt = 0; nt < 8; nt++) {
                uint32_t bb[2];
                bb[0] = __float_as_uint(Vs[(ks * 8 + lq) * VST + nt * 8 + lr]);
                bb[1] = __float_as_uint(Vs[(ks * 8 + lq + 4) * VST + nt * 8 + lr]);
                MMA8(acc[nt], a, bb);
            }
        }
        __syncthreads();
    }

    int wm = w * 16;
    int r0 = wm + lr, r1 = r0 + 8;
    float inv0 = 1.0f / lsum[r0], inv1 = 1.0f / lsum[r1];
#pragma unroll
    for (int nt = 0; nt < 8; nt++) {
        int d = h * HDIM + nt * 8 + 2 * lq;
        size_t o0 = ((size_t)b * SEQ + m0 + r0) * DMODEL + d;
        size_t o1 = ((size_t)b * SEQ + m0 + r1) * DMODEL + d;
        g_o[o0] = acc[nt][0] * inv0; g_o[o0 + 1] = acc[nt][1] * inv0;
        g_o[o1] = acc[nt][2] * inv1; g_o[o1 + 1] = acc[nt][3] * inv1;
    }
}

// ---------------------------------------------------------------------------
// Launch
// ---------------------------------------------------------------------------
extern "C" void kernel_launch(void* const* d_in, const int* in_sizes, int n_in,
                              void* d_out, int out_size) {
    const float* x     = (const float*)d_in[0];
    const float* Wq    = (const float*)d_in[1];
    const float* Wk    = (const float*)d_in[2];
    const float* Wv    = (const float*)d_in[3];
    const float* Wte8  = (const float*)d_in[4];
    const float* Wfe8  = (const float*)d_in[5];
    const float* Wout  = (const float*)d_in[6];
    float* out = (float*)d_out;

    float *k, *v, *o, *coords, *wqe8;
    cudaGetSymbolAddress((void**)&k, g_k);
    cudaGetSymbolAddress((void**)&v, g_v);
    cudaGetSymbolAddress((void**)&o, g_o);
    cudaGetSymbolAddress((void**)&coords, g_coords);
    cudaGetSymbolAddress((void**)&wqe8, g_Wqe8);

    cudaFuncSetAttribute(gemm_mma<true>,  cudaFuncAttributeMaxDynamicSharedMemorySize, GM_SMEM);
    cudaFuncSetAttribute(gemm_mma<false>, cudaFuncAttributeMaxDynamicSharedMemorySize, GM_SMEM);

    build_wqe8<<<512, 256>>>(Wq, Wte8);
    build_tables<<<1, 256>>>(Wfe8);

    // coords: high precision (feeds the argmin cliff)
    gemm_mma<true><<<dim3(1, 32, 1), 256, GM_SMEM>>>(x, wqe8, coords,
                                                     wqe8, coords, 128, DMODEL);
    e8_argmin<<<256, 256>>>();

    // K and V in one launch (grid.z picks weight/output), single tf32
    gemm_mma<false><<<dim3(8, 32, 2), 256, GM_SMEM>>>(x, Wk, k, Wv, v, DMODEL, DMODEL);
    round_v<<<MROWS * DMODEL / 256, 256>>>();

    rgemm<<<dim3(32, 4, 32), 256>>>();
    rowmax_exp<<<NBH * NROOT / 8, 256>>>();

    attn_pv<<<dim3(32, 16, 2), 128>>>();

    // output projection, single tf32
    gemm_mma<false><<<dim3(8, 32, 1), 256, GM_SMEM>>>(o, Wout, out,
                                                      Wout, out, DMODEL, DMODEL);
}

// round 7
// speedup vs baseline: 3.1990x; 1.2612x over previous
#include <cuda_runtime.h>
#include <cuda_bf16.h>
#include <math.h>
#include <stdint.h>

#define BATCH 2
#define SEQ   2048
#define DMODEL 1024
#define NHEAD 16
#define HDIM  64
#define MROWS (BATCH*SEQ)          // 4096
#define NBH   (BATCH*NHEAD)        // 32
#define NROOT 240
#define NTILE 32                   // key tiles of 64

// Scratch (device globals; no allocation allowed)
__device__ float g_k[MROWS*DMODEL];
__device__ float g_v[MROWS*DMODEL];
__device__ float g_o[MROWS*DMODEL];
__device__ float g_E[NBH*NROOT*SEQ];        // 62.9 MB: R then exp(R-max), fp32
__device__ float g_P[NBH*NTILE*NROOT*64];   // 62.9 MB: per-tile PV partials -> cumsum
__device__ float g_lp[NBH*NROOT*NTILE];     // per-tile E-row sums, cumsummed
__device__ float g_coords[MROWS*128];
__device__ int   g_idx[NBH*SEQ];
__device__ float g_Wqe8[DMODEL*128];
__device__ float g_RW[NROOT*HDIM];
__device__ float g_roots[NROOT*8];

// ===========================================================================
// helpers
// ===========================================================================
__device__ __forceinline__ uint32_t smem_u32(const void* p) {
    uint32_t a;
    asm("{ .reg .u64 t; cvta.to.shared.u64 t, %1; cvt.u32.u64 %0, t; }"
        : "=r"(a) : "l"(p));
    return a;
}
#define CP16(dst, src) \
    asm volatile("cp.async.cg.shared.global [%0], [%1], 16;" :: "r"(dst), "l"(src) : "memory")
#define CP_COMMIT() asm volatile("cp.async.commit_group;" ::: "memory")
#define CP_WAIT(n)  asm volatile("cp.async.wait_group %0;" :: "n"(n) : "memory")

__device__ __forceinline__ void cvt3(float x, uint32_t& hi, uint32_t& lo) {
    asm("cvt.rna.tf32.f32 %0, %1;" : "=r"(hi) : "f"(x));
    float r = x - __uint_as_float(hi);
    asm("cvt.rna.tf32.f32 %0, %1;" : "=r"(lo) : "f"(r));
}
__device__ __forceinline__ uint32_t cvt1(float x) {
    uint32_t t;
    asm("cvt.rna.tf32.f32 %0, %1;" : "=r"(t) : "f"(x));
    return t;
}

#define MMA8(c, a, b) \
    asm volatile("mma.sync.aligned.m16n8k8.row.col.f32.tf32.tf32.f32 " \
        "{%0,%1,%2,%3}, {%4,%5,%6,%7}, {%8,%9}, {%0,%1,%2,%3};" \
        : "+f"((c)[0]), "+f"((c)[1]), "+f"((c)[2]), "+f"((c)[3]) \
        : "r"((a)[0]), "r"((a)[1]), "r"((a)[2]), "r"((a)[3]), \
          "r"((b)[0]), "r"((b)[1]))

// ===========================================================================
// mma.sync tf32 GEMM, templated precision: C[M,N] = A[M,K] @ B[K,N]
// ===========================================================================
#define AS_STRIDE 36
#define BS_STRIDE 132
#define AS_F (128 * AS_STRIDE)
#define BS_F (32 * BS_STRIDE)
#define STG_F (AS_F + BS_F)
#define GM_SMEM (2 * STG_F * 4)

extern __shared__ float smf[];

template <bool SPLIT3>
__global__ __launch_bounds__(256, 1) void gemm_mma(const float* __restrict__ A,
                                                   const float* __restrict__ B0,
                                                   float* __restrict__ C0,
                                                   const float* __restrict__ B1,
                                                   float* __restrict__ C1,
                                                   int N, int K) {
    const float* B = blockIdx.z ? B1 : B0;
    float* C = blockIdx.z ? C1 : C0;
    int tid = threadIdx.x;
    int lane = tid & 31, w = tid >> 5;
    int lq = lane & 3, lr = lane >> 2;
    int wm = (w & 3) * 32, wn = (w >> 2) * 64;
    int n0 = blockIdx.x * 128, m0 = blockIdx.y * 128;
    uint32_t sb = smem_u32(smf);

    float acc[2][8][4];
#pragma unroll
    for (int mt = 0; mt < 2; mt++)
#pragma unroll
        for (int nt = 0; nt < 8; nt++)
#pragma unroll
            for (int j = 0; j < 4; j++) acc[mt][nt][j] = 0.f;

    int ar[4], aq[4], bk[4], bn[4];
#pragma unroll
    for (int i = 0; i < 4; i++) {
        int idx = tid + i * 256;
        ar[i] = idx >> 3; aq[i] = idx & 7;
        bk[i] = idx >> 5; bn[i] = idx & 31;
    }

    auto issue_chunk = [&](int c) {
        int k0 = c * 32;
        uint32_t base = sb + (uint32_t)(c & 1) * (STG_F * 4);
#pragma unroll
        for (int i = 0; i < 4; i++)
            CP16(base + (uint32_t)(ar[i] * AS_STRIDE + aq[i] * 4) * 4,
                 A + (size_t)(m0 + ar[i]) * K + k0 + aq[i] * 4);
#pragma unroll
        for (int i = 0; i < 4; i++)
            CP16(base + (uint32_t)(AS_F + bk[i] * BS_STRIDE + bn[i] * 4) * 4,
                 B + (size_t)(k0 + bk[i]) * N + n0 + bn[i] * 4);
        CP_COMMIT();
    };

    issue_chunk(0);
    int nchunk = K >> 5;

    for (int c = 0; c < nchunk; c++) {
        if (c < nchunk - 1) { issue_chunk(c + 1); CP_WAIT(1); }
        else                { CP_WAIT(0); }
        __syncthreads();

        const float* As = smf + (c & 1) * STG_F;
        const float* Bs = As + AS_F;

#pragma unroll
        for (int ks = 0; ks < 4; ks++) {
            int kk = ks * 8;
            uint32_t Ah[2][4], Al[2][4];
#pragma unroll
            for (int mt = 0; mt < 2; mt++) {
                int rb = wm + mt * 16 + lr;
                if (SPLIT3) {
                    cvt3(As[rb * AS_STRIDE + kk + lq],           Ah[mt][0], Al[mt][0]);
                    cvt3(As[(rb + 8) * AS_STRIDE + kk + lq],     Ah[mt][1], Al[mt][1]);
                    cvt3(As[rb * AS_STRIDE + kk + lq + 4],       Ah[mt][2], Al[mt][2]);
                    cvt3(As[(rb + 8) * AS_STRIDE + kk + lq + 4], Ah[mt][3], Al[mt][3]);
                } else {
                    Ah[mt][0] = cvt1(As[rb * AS_STRIDE + kk + lq]);
                    Ah[mt][1] = cvt1(As[(rb + 8) * AS_STRIDE + kk + lq]);
                    Ah[mt][2] = cvt1(As[rb * AS_STRIDE + kk + lq + 4]);
                    Ah[mt][3] = cvt1(As[(rb + 8) * AS_STRIDE + kk + lq + 4]);
                }
            }
            uint32_t Bh[8][2], Bl[8][2];
#pragma unroll
            for (int nt = 0; nt < 8; nt++) {
                int cc = wn + nt * 8 + lr;
                if (SPLIT3) {
                    cvt3(Bs[(kk + lq) * BS_STRIDE + cc],     Bh[nt][0], Bl[nt][0]);
                    cvt3(Bs[(kk + lq + 4) * BS_STRIDE + cc], Bh[nt][1], Bl[nt][1]);
                } else {
                    Bh[nt][0] = cvt1(Bs[(kk + lq) * BS_STRIDE + cc]);
                    Bh[nt][1] = cvt1(Bs[(kk + lq + 4) * BS_STRIDE + cc]);
                }
            }
#pragma unroll
            for (int mt = 0; mt < 2; mt++)
#pragma unroll
                for (int nt = 0; nt < 8; nt++) {
                    MMA8(acc[mt][nt], Ah[mt], Bh[nt]);
                    if (SPLIT3) {
                        MMA8(acc[mt][nt], Al[mt], Bh[nt]);
                        MMA8(acc[mt][nt], Ah[mt], Bl[nt]);
                    }
                }
        }
        __syncthreads();
    }

#pragma unroll
    for (int mt = 0; mt < 2; mt++) {
        int row = m0 + wm + mt * 16 + lr;
#pragma unroll
        for (int nt = 0; nt < 8; nt++) {
            int col = n0 + wn + nt * 8 + lq * 2;
            *(float2*)(C + (size_t)row * N + col) =
                make_float2(acc[mt][nt][0], acc[mt][nt][1]);
            *(float2*)(C + (size_t)(row + 8) * N + col) =
                make_float2(acc[mt][nt][2], acc[mt][nt][3]);
        }
    }
}

// ===========================================================================
// Wqe8[in][h*8+j] = sum_e Wq[in][h*64+e] * Wt[e][j]
// ===========================================================================
__global__ __launch_bounds__(256) void build_wqe8(const float* __restrict__ Wq,
                                                  const float* __restrict__ Wt) {
    int i = blockIdx.x * 256 + threadIdx.x;
    int in = i >> 7, c = i & 127, h = c >> 3, j = c & 7;
    float s = 0.f;
#pragma unroll
    for (int e = 0; e < 64; e++) s += Wq[(size_t)in * DMODEL + h * 64 + e] * Wt[e * 8 + j];
    g_Wqe8[i] = s;
}

// ===========================================================================
// roots (exact reference enumeration) and RW = 0.125 * roots @ Wf
// ===========================================================================
__global__ __launch_bounds__(256) void build_tables(const float* __restrict__ Wf) {
    __shared__ float roots[NROOT * 8];
    int tid = threadIdx.x;
    for (int i = tid; i < NROOT * 8; i += 256) {
        int r = i >> 3, d = i & 7;
        float v;
        if (r < 112) {
            int p = r >> 2, s = r & 3;
            int a = 0, b = 1, cnt = 0; bool done = false;
            for (a = 0; a < 8 && !done; a++) {
                for (b = a + 1; b < 8; b++) {
                    if (cnt == p) { done = true; break; }
                    cnt++;
                }
            }
            a--;
            float si = (s & 2) ? -1.f : 1.f;
            float sj = (s & 1) ? -1.f : 1.f;
            v = (d == a) ? si : ((d == b) ? sj : 0.f);
        } else {
            int k = r - 112;
            int mask = (k << 1) | (__popc(k) & 1);
            v = ((mask >> d) & 1) ? -0.5f : 0.5f;
        }
        roots[i] = v;
        g_roots[i] = v;
    }
    __syncthreads();
    for (int i = tid; i < NROOT * HDIM; i += 256) {
        int r = i >> 6, d = i & 63;
        float s = 0.f;
#pragma unroll
        for (int j = 0; j < 8; j++) s += roots[r * 8 + j] * Wf[j * HDIM + d];
        g_RW[i] = 0.125f * s;
    }
}

// ===========================================================================
// argmin over 240 roots
// ===========================================================================
__global__ __launch_bounds__(256) void e8_argmin() {
    __shared__ float roots[NROOT * 8];
    int tid = threadIdx.x;
    for (int i = tid; i < NROOT * 8; i += 256) roots[i] = g_roots[i];
    __syncthreads();
    int id = blockIdx.x * 256 + tid;
    int t = id & (SEQ - 1), h = (id >> 11) & 15, b = id >> 15;
    const float* cp = g_coords + ((size_t)(b * SEQ + t)) * 128 + h * 8;
    float x[8];
#pragma unroll
    for (int j = 0; j < 8; j++) x[j] = cp[j];
    int best = 0; float bs = 3.4e38f;
    for (int r = 0; r < NROOT; r++) {
        float dot = 0.f;
#pragma unroll
        for (int j = 0; j < 8; j++) dot += x[j] * roots[r * 8 + j];
        float sc = -2.f * dot + 2.f;
        if (sc < bs) { bs = sc; best = r; }
    }
    g_idx[id] = best;
}

// ===========================================================================
// R[bh][m][t] = sum_d RW[m][d] * K[b][t][h*64+d]
// ===========================================================================
__global__ __launch_bounds__(256) void rgemm() {
    __shared__ float As[64][65], Bs[64][65];
    int tid = threadIdx.x, ty = tid >> 4, tx = tid & 15;
    int t0 = blockIdx.x * 64, m0 = blockIdx.y * 64, bh = blockIdx.z;
    int b = bh >> 4, h = bh & 15;
    for (int i = tid; i < 4096; i += 256) {
        int r = i >> 6, c = i & 63; int m = m0 + r;
        As[r][c] = (m < NROOT) ? g_RW[m * HDIM + c] : 0.f;
        Bs[r][c] = g_k[((size_t)b * SEQ + t0 + r) * DMODEL + h * HDIM + c];
    }
    __syncthreads();
    float acc[4][4] = {};
#pragma unroll
    for (int d = 0; d < 64; d++) {
        float a[4], bb[4];
#pragma unroll
        for (int i = 0; i < 4; i++) a[i] = As[ty * 4 + i][d];
#pragma unroll
        for (int j = 0; j < 4; j++) bb[j] = Bs[tx * 4 + j][d];
#pragma unroll
        for (int i = 0; i < 4; i++)
#pragma unroll
            for (int j = 0; j < 4; j++) acc[i][j] += a[i] * bb[j];
    }
    float* Rb = g_E + (size_t)bh * NROOT * SEQ;
#pragma unroll
    for (int i = 0; i < 4; i++) {
        int m = m0 + ty * 4 + i;
        if (m < NROOT)
#pragma unroll
            for (int j = 0; j < 4; j++)
                Rb[(size_t)m * SEQ + t0 + tx * 4 + j] = acc[i][j];
    }
}

// ===========================================================================
// row max; E = exp(R - max) fp32; per-64-tile sums cumsummed into g_lp.
// 1 warp per (bh, m) row.
// ===========================================================================
__global__ __launch_bounds__(256) void rowmax_exp_lp() {
    int row = blockIdx.x * 8 + (threadIdx.x >> 5);   // < NBH*NROOT
    int lane = threadIdx.x & 31;
    float* p = g_E + (size_t)row * SEQ;
    float mx = -INFINITY;
    for (int i = lane; i < SEQ; i += 32) mx = fmaxf(mx, p[i]);
#pragma unroll
    for (int o = 16; o; o >>= 1) mx = fmaxf(mx, __shfl_xor_sync(0xffffffffu, mx, o));
    float run = 0.f;
    for (int j = 0; j < NTILE; j++) {
        float e1 = __expf(p[64 * j + lane] - mx);
        float e2 = __expf(p[64 * j + 32 + lane] - mx);
        p[64 * j + lane] = e1;
        p[64 * j + 32 + lane] = e2;
        float ts = e1 + e2;
#pragma unroll
        for (int o = 16; o; o >>= 1) ts += __shfl_xor_sync(0xffffffffu, ts, o);
        run += ts;
        if (lane == 0) g_lp[row * NTILE + j] = run;   // inclusive cumsum
    }
}

// ===========================================================================
// partial[bh][j][m][d] = sum_{s in tile j} E[bh][m][s] * V[b][s][h*64+d]
// 64x64 tile per CTA, K=64, fp32 FFMA.
// ===========================================================================
__global__ __launch_bounds__(256) void partial_pv() {
    __shared__ float As[64][65];    // E rows [m][s]
    __shared__ float Bs[64][68];    // V [s][d], float4-aligned stride
    int tid = threadIdx.x, ty = tid >> 4, tx = tid & 15;
    int j = blockIdx.x, m0 = blockIdx.y * 64, bh = blockIdx.z;
    int b = bh >> 4, h = bh & 15;
    int s0 = j * 64;
    for (int i = tid; i < 4096; i += 256) {
        int r = i >> 6, c = i & 63; int m = m0 + r;
        As[r][c] = (m < NROOT) ? g_E[((size_t)bh * NROOT + m) * SEQ + s0 + c] : 0.f;
        Bs[r][c] = g_v[((size_t)b * SEQ + s0 + r) * DMODEL + h * HDIM + c];
    }
    __syncthreads();
    float acc[4][4] = {};
#pragma unroll
    for (int s = 0; s < 64; s++) {
        float a[4];
#pragma unroll
        for (int i = 0; i < 4; i++) a[i] = As[ty * 4 + i][s];
        float4 b4 = *(const float4*)(&Bs[s][tx * 4]);
        float bb[4] = {b4.x, b4.y, b4.z, b4.w};
#pragma unroll
        for (int i = 0; i < 4; i++)
#pragma unroll
            for (int jj = 0; jj < 4; jj++) acc[i][jj] += a[i] * bb[jj];
    }
#pragma unroll
    for (int i = 0; i < 4; i++) {
        int m = m0 + ty * 4 + i;
        if (m < NROOT) {
            float* dst = g_P + ((size_t)(bh * NTILE + j) * NROOT + m) * 64 + tx * 4;
            *(float4*)dst = make_float4(acc[i][0], acc[i][1], acc[i][2], acc[i][3]);
        }
    }
}

// ===========================================================================
// in-place inclusive cumsum of g_P over j. thread per (bh, m, d).
// ===========================================================================
__global__ __launch_bounds__(256) void cumsum_pv() {
    int idx = blockIdx.x * 256 + threadIdx.x;   // 0..15359 (240*64)
    int bh = blockIdx.y;
    float* base = g_P + (size_t)bh * NTILE * NROOT * 64 + idx;
    float run = 0.f;
#pragma unroll 4
    for (int j = 0; j < NTILE; j++) {
        float* p = base + (size_t)j * NROOT * 64;
        run += *p;
        *p = run;
    }
}

// ===========================================================================
// Final: O(t) = (C[bh][jt-1][m] + diag)/(lp[jt-1] + ldiag).
// CTA = (q-tile of 64, bh). 256 threads: 4 per q-row, 16 dims each.
// ===========================================================================
#define VS4 68
__global__ __launch_bounds__(256) void attn_diag() {
    __shared__ float Vs[64 * VS4];
    __shared__ float Es[64 * 65];
    __shared__ int sidx[64];
    int tid = threadIdx.x;
    int mblk = blockIdx.x, bh = blockIdx.y;
    int b = bh >> 4, h = bh & 15;
    int m0 = mblk * 64;
    if (tid < 64) sidx[tid] = g_idx[bh * SEQ + m0 + tid];
    __syncthreads();

    // stage diagonal V tile [64 keys][64 dims]
#pragma unroll
    for (int k = 0; k < 4; k++) {
        int fl = tid + k * 256; int s = fl >> 4, c4 = (fl & 15) * 4;
        float4 v = *(const float4*)(g_v + ((size_t)b * SEQ + m0 + s) * DMODEL + h * HDIM + c4);
        *(float4*)(Vs + s * VS4 + c4) = v;
    }
    // stage E diagonal values per q-row (root-gathered)
    int row = tid >> 2, tg = tid & 3;
    {
        const float* er = g_E + ((size_t)bh * NROOT + sidx[row]) * SEQ + m0 + tg * 16;
#pragma unroll
        for (int u = 0; u < 16; u++) Es[row * 65 + tg * 16 + u] = er[u];
    }
    __syncthreads();

    float4 a0 = {0,0,0,0}, a1 = {0,0,0,0}, a2 = {0,0,0,0}, a3 = {0,0,0,0};
    float l = 0.f;
    for (int s = 0; s <= row; s++) {
        float w = Es[row * 65 + s];
        l += w;
        const float* vp = Vs + s * VS4 + tg * 16;
        float4 v0 = *(const float4*)(vp + 0);
        float4 v1 = *(const float4*)(vp + 4);
        float4 v2 = *(const float4*)(vp + 8);
        float4 v3 = *(const float4*)(vp + 12);
        a0.x += w * v0.x; a0.y += w * v0.y; a0.z += w * v0.z; a0.w += w * v0.w;
        a1.x += w * v1.x; a1.y += w * v1.y; a1.z += w * v1.z; a1.w += w * v1.w;
        a2.x += w * v2.x; a2.y += w * v2.y; a2.z += w * v2.z; a2.w += w * v2.w;
        a3.x += w * v3.x; a3.y += w * v3.y; a3.z += w * v3.z; a3.w += w * v3.w;
    }
    int m = sidx[row];
    if (mblk > 0) {
        const float* cp = g_P + ((size_t)(bh * NTILE + mblk - 1) * NROOT + m) * 64 + tg * 16;
        float4 c0 = *(const float4*)(cp + 0);
        float4 c1 = *(const float4*)(cp + 4);
        float4 c2 = *(const float4*)(cp + 8);
        float4 c3 = *(const float4*)(cp + 12);
        a0.x += c0.x; a0.y += c0.y; a0.z += c0.z; a0.w += c0.w;
        a1.x += c1.x; a1.y += c1.y; a1.z += c1.z; a1.w += c1.w;
        a2.x += c2.x; a2.y += c2.y; a2.z += c2.z; a2.w += c2.w;
        a3.x += c3.x; a3.y += c3.y; a3.z += c3.z; a3.w += c3.w;
        l += g_lp[(bh * NROOT + m) * NTILE + mblk - 1];
    }
    float inv = 1.0f / l;
    float* op = g_o + ((size_t)b * SEQ + m0 + row) * DMODEL + h * HDIM + tg * 16;
    *(float4*)(op + 0)  = make_float4(a0.x * inv, a0.y * inv, a0.z * inv, a0.w * inv);
    *(float4*)(op + 4)  = make_float4(a1.x * inv, a1.y * inv, a1.z * inv, a1.w * inv);
    *(float4*)(op + 8)  = make_float4(a2.x * inv, a2.y * inv, a2.z * inv, a2.w * inv);
    *(float4*)(op + 12) = make_float4(a3.x * inv, a3.y * inv, a3.z * inv, a3.w * inv);
}

// ---------------------------------------------------------------------------
// Launch
// ---------------------------------------------------------------------------
extern "C" void kernel_launch(void* const* d_in, const int* in_sizes, int n_in,
                              void* d_out, int out_size) {
    const float* x     = (const float*)d_in[0];
    const float* Wq    = (const float*)d_in[1];
    const float* Wk    = (const float*)d_in[2];
    const float* Wv    = (const float*)d_in[3];
    const float* Wte8  = (const float*)d_in[4];
    const float* Wfe8  = (const float*)d_in[5];
    const float* Wout  = (const float*)d_in[6];
    float* out = (float*)d_out;

    float *k, *v, *o, *coords, *wqe8;
    cudaGetSymbolAddress((void**)&k, g_k);
    cudaGetSymbolAddress((void**)&v, g_v);
    cudaGetSymbolAddress((void**)&o, g_o);
    cudaGetSymbolAddress((void**)&coords, g_coords);
    cudaGetSymbolAddress((void**)&wqe8, g_Wqe8);

    cudaFuncSetAttribute(gemm_mma<true>,  cudaFuncAttributeMaxDynamicSharedMemorySize, GM_SMEM);
    cudaFuncSetAttribute(gemm_mma<false>, cudaFuncAttributeMaxDynamicSharedMemorySize, GM_SMEM);

    build_wqe8<<<512, 256>>>(Wq, Wte8);
    build_tables<<<1, 256>>>(Wfe8);

    // coords: high precision (feeds the argmin cliff)
    gemm_mma<true><<<dim3(1, 32, 1), 256, GM_SMEM>>>(x, wqe8, coords,
                                                     wqe8, coords, 128, DMODEL);
    e8_argmin<<<256, 256>>>();

    // K and V in one launch, single tf32
    gemm_mma<false><<<dim3(8, 32, 2), 256, GM_SMEM>>>(x, Wk, k, Wv, v, DMODEL, DMODEL);

    rgemm<<<dim3(32, 4, 32), 256>>>();
    rowmax_exp_lp<<<NBH * NROOT / 8, 256>>>();

    partial_pv<<<dim3(NTILE, 4, NBH), 256>>>();
    cumsum_pv<<<dim3(60, NBH), 256>>>();
    attn_diag<<<dim3(32, NBH), 256>>>();

    // output projection, single tf32
    gemm_mma<false><<<dim3(8, 32, 1), 256, GM_SMEM>>>(o, Wout, out,
                                                      Wout, out, DMODEL, DMODEL);
}

// round 8
// speedup vs baseline: 3.9312x; 1.2289x over previous
#include <cuda_runtime.h>
#include <cuda_bf16.h>
#include <math.h>
#include <stdint.h>

#define BATCH 2
#define SEQ   2048
#define DMODEL 1024
#define NHEAD 16
#define HDIM  64
#define MROWS (BATCH*SEQ)          // 4096
#define NBH   (BATCH*NHEAD)        // 32
#define NROOT 240
#define NTILE 32                   // key tiles of 64

// Scratch (device globals; no allocation allowed)
__device__ float g_k[MROWS*DMODEL];
__device__ float g_v[MROWS*DMODEL];
__device__ float g_o[MROWS*DMODEL];
__device__ float g_E[NBH*NROOT*SEQ];        // 62.9 MB: exp(S), fp32 (no max shift)
__device__ float g_P[NBH*NTILE*NROOT*64];   // 62.9 MB: per-tile PV partials -> cumsum
__device__ float g_lp[NBH*NROOT*NTILE];     // per-tile E-row sums -> cumsummed
__device__ float g_coords[MROWS*128];
__device__ int   g_idx[NBH*SEQ];
__device__ float g_Wqe8[DMODEL*128];
__device__ float g_RW[NROOT*HDIM];
__device__ float g_roots[NROOT*8];

// ===========================================================================
// helpers
// ===========================================================================
__device__ __forceinline__ uint32_t smem_u32(const void* p) {
    uint32_t a;
    asm("{ .reg .u64 t; cvta.to.shared.u64 t, %1; cvt.u32.u64 %0, t; }"
        : "=r"(a) : "l"(p));
    return a;
}
#define CP16(dst, src) \
    asm volatile("cp.async.cg.shared.global [%0], [%1], 16;" :: "r"(dst), "l"(src) : "memory")
#define CP_COMMIT() asm volatile("cp.async.commit_group;" ::: "memory")
#define CP_WAIT(n)  asm volatile("cp.async.wait_group %0;" :: "n"(n) : "memory")

__device__ __forceinline__ void cvt3(float x, uint32_t& hi, uint32_t& lo) {
    asm("cvt.rna.tf32.f32 %0, %1;" : "=r"(hi) : "f"(x));
    float r = x - __uint_as_float(hi);
    asm("cvt.rna.tf32.f32 %0, %1;" : "=r"(lo) : "f"(r));
}
__device__ __forceinline__ uint32_t cvt1(float x) {
    uint32_t t;
    asm("cvt.rna.tf32.f32 %0, %1;" : "=r"(t) : "f"(x));
    return t;
}

#define MMA8(c, a, b) \
    asm volatile("mma.sync.aligned.m16n8k8.row.col.f32.tf32.tf32.f32 " \
        "{%0,%1,%2,%3}, {%4,%5,%6,%7}, {%8,%9}, {%0,%1,%2,%3};" \
        : "+f"((c)[0]), "+f"((c)[1]), "+f"((c)[2]), "+f"((c)[3]) \
        : "r"((a)[0]), "r"((a)[1]), "r"((a)[2]), "r"((a)[3]), \
          "r"((b)[0]), "r"((b)[1]))

// ===========================================================================
// mma.sync tf32 GEMM, templated precision: C[M,N] = A[M,K] @ B[K,N]
// ===========================================================================
#define AS_STRIDE 36
#define BS_STRIDE 132
#define AS_F (128 * AS_STRIDE)
#define BS_F (32 * BS_STRIDE)
#define STG_F (AS_F + BS_F)
#define GM_SMEM (2 * STG_F * 4)

extern __shared__ float smf[];

template <bool SPLIT3>
__global__ __launch_bounds__(256, 1) void gemm_mma(const float* __restrict__ A,
                                                   const float* __restrict__ B0,
                                                   float* __restrict__ C0,
                                                   const float* __restrict__ B1,
                                                   float* __restrict__ C1,
                                                   int N, int K) {
    const float* B = blockIdx.z ? B1 : B0;
    float* C = blockIdx.z ? C1 : C0;
    int tid = threadIdx.x;
    int lane = tid & 31, w = tid >> 5;
    int lq = lane & 3, lr = lane >> 2;
    int wm = (w & 3) * 32, wn = (w >> 2) * 64;
    int n0 = blockIdx.x * 128, m0 = blockIdx.y * 128;
    uint32_t sb = smem_u32(smf);

    float acc[2][8][4];
#pragma unroll
    for (int mt = 0; mt < 2; mt++)
#pragma unroll
        for (int nt = 0; nt < 8; nt++)
#pragma unroll
            for (int j = 0; j < 4; j++) acc[mt][nt][j] = 0.f;

    int ar[4], aq[4], bk[4], bn[4];
#pragma unroll
    for (int i = 0; i < 4; i++) {
        int idx = tid + i * 256;
        ar[i] = idx >> 3; aq[i] = idx & 7;
        bk[i] = idx >> 5; bn[i] = idx & 31;
    }

    auto issue_chunk = [&](int c) {
        int k0 = c * 32;
        uint32_t base = sb + (uint32_t)(c & 1) * (STG_F * 4);
#pragma unroll
        for (int i = 0; i < 4; i++)
            CP16(base + (uint32_t)(ar[i] * AS_STRIDE + aq[i] * 4) * 4,
                 A + (size_t)(m0 + ar[i]) * K + k0 + aq[i] * 4);
#pragma unroll
        for (int i = 0; i < 4; i++)
            CP16(base + (uint32_t)(AS_F + bk[i] * BS_STRIDE + bn[i] * 4) * 4,
                 B + (size_t)(k0 + bk[i]) * N + n0 + bn[i] * 4);
        CP_COMMIT();
    };

    issue_chunk(0);
    int nchunk = K >> 5;

    for (int c = 0; c < nchunk; c++) {
        if (c < nchunk - 1) { issue_chunk(c + 1); CP_WAIT(1); }
        else                { CP_WAIT(0); }
        __syncthreads();

        const float* As = smf + (c & 1) * STG_F;
        const float* Bs = As + AS_F;

#pragma unroll
        for (int ks = 0; ks < 4; ks++) {
            int kk = ks * 8;
            uint32_t Ah[2][4], Al[2][4];
#pragma unroll
            for (int mt = 0; mt < 2; mt++) {
                int rb = wm + mt * 16 + lr;
                if (SPLIT3) {
                    cvt3(As[rb * AS_STRIDE + kk + lq],           Ah[mt][0], Al[mt][0]);
                    cvt3(As[(rb + 8) * AS_STRIDE + kk + lq],     Ah[mt][1], Al[mt][1]);
                    cvt3(As[rb * AS_STRIDE + kk + lq + 4],       Ah[mt][2], Al[mt][2]);
                    cvt3(As[(rb + 8) * AS_STRIDE + kk + lq + 4], Ah[mt][3], Al[mt][3]);
                } else {
                    Ah[mt][0] = cvt1(As[rb * AS_STRIDE + kk + lq]);
                    Ah[mt][1] = cvt1(As[(rb + 8) * AS_STRIDE + kk + lq]);
                    Ah[mt][2] = cvt1(As[rb * AS_STRIDE + kk + lq + 4]);
                    Ah[mt][3] = cvt1(As[(rb + 8) * AS_STRIDE + kk + lq + 4]);
                }
            }
            uint32_t Bh[8][2], Bl[8][2];
#pragma unroll
            for (int nt = 0; nt < 8; nt++) {
                int cc = wn + nt * 8 + lr;
                if (SPLIT3) {
                    cvt3(Bs[(kk + lq) * BS_STRIDE + cc],     Bh[nt][0], Bl[nt][0]);
                    cvt3(Bs[(kk + lq + 4) * BS_STRIDE + cc], Bh[nt][1], Bl[nt][1]);
                } else {
                    Bh[nt][0] = cvt1(Bs[(kk + lq) * BS_STRIDE + cc]);
                    Bh[nt][1] = cvt1(Bs[(kk + lq + 4) * BS_STRIDE + cc]);
                }
            }
#pragma unroll
            for (int mt = 0; mt < 2; mt++)
#pragma unroll
                for (int nt = 0; nt < 8; nt++) {
                    MMA8(acc[mt][nt], Ah[mt], Bh[nt]);
                    if (SPLIT3) {
                        MMA8(acc[mt][nt], Al[mt], Bh[nt]);
                        MMA8(acc[mt][nt], Ah[mt], Bl[nt]);
                    }
                }
        }
        __syncthreads();
    }

#pragma unroll
    for (int mt = 0; mt < 2; mt++) {
        int row = m0 + wm + mt * 16 + lr;
#pragma unroll
        for (int nt = 0; nt < 8; nt++) {
            int col = n0 + wn + nt * 8 + lq * 2;
            *(float2*)(C + (size_t)row * N + col) =
                make_float2(acc[mt][nt][0], acc[mt][nt][1]);
            *(float2*)(C + (size_t)(row + 8) * N + col) =
                make_float2(acc[mt][nt][2], acc[mt][nt][3]);
        }
    }
}

// ===========================================================================
// Wqe8[in][h*8+j] = sum_e Wq[in][h*64+e] * Wt[e][j]
// ===========================================================================
__global__ __launch_bounds__(256) void build_wqe8(const float* __restrict__ Wq,
                                                  const float* __restrict__ Wt) {
    int i = blockIdx.x * 256 + threadIdx.x;
    int in = i >> 7, c = i & 127, h = c >> 3, j = c & 7;
    float s = 0.f;
#pragma unroll
    for (int e = 0; e < 64; e++) s += Wq[(size_t)in * DMODEL + h * 64 + e] * Wt[e * 8 + j];
    g_Wqe8[i] = s;
}

// ===========================================================================
// roots (exact reference enumeration) and RW = 0.125 * roots @ Wf
// ===========================================================================
__global__ __launch_bounds__(256) void build_tables(const float* __restrict__ Wf) {
    __shared__ float roots[NROOT * 8];
    int tid = threadIdx.x;
    for (int i = tid; i < NROOT * 8; i += 256) {
        int r = i >> 3, d = i & 7;
        float v;
        if (r < 112) {
            int p = r >> 2, s = r & 3;
            int a = 0, b = 1, cnt = 0; bool done = false;
            for (a = 0; a < 8 && !done; a++) {
                for (b = a + 1; b < 8; b++) {
                    if (cnt == p) { done = true; break; }
                    cnt++;
                }
            }
            a--;
            float si = (s & 2) ? -1.f : 1.f;
            float sj = (s & 1) ? -1.f : 1.f;
            v = (d == a) ? si : ((d == b) ? sj : 0.f);
        } else {
            int k = r - 112;
            int mask = (k << 1) | (__popc(k) & 1);
            v = ((mask >> d) & 1) ? -0.5f : 0.5f;
        }
        roots[i] = v;
        g_roots[i] = v;
    }
    __syncthreads();
    for (int i = tid; i < NROOT * HDIM; i += 256) {
        int r = i >> 6, d = i & 63;
        float s = 0.f;
#pragma unroll
        for (int j = 0; j < 8; j++) s += roots[r * 8 + j] * Wf[j * HDIM + d];
        g_RW[i] = 0.125f * s;
    }
}

// ===========================================================================
// argmin over 240 roots
// ===========================================================================
__global__ __launch_bounds__(256) void e8_argmin() {
    __shared__ float roots[NROOT * 8];
    int tid = threadIdx.x;
    for (int i = tid; i < NROOT * 8; i += 256) roots[i] = g_roots[i];
    __syncthreads();
    int id = blockIdx.x * 256 + tid;
    int t = id & (SEQ - 1), h = (id >> 11) & 15, b = id >> 15;
    const float* cp = g_coords + ((size_t)(b * SEQ + t)) * 128 + h * 8;
    float x[8];
#pragma unroll
    for (int j = 0; j < 8; j++) x[j] = cp[j];
    int best = 0; float bs = 3.4e38f;
    for (int r = 0; r < NROOT; r++) {
        float dot = 0.f;
#pragma unroll
        for (int j = 0; j < 8; j++) dot += x[j] * roots[r * 8 + j];
        float sc = -2.f * dot + 2.f;
        if (sc < bs) { bs = sc; best = r; }
    }
    g_idx[id] = best;
}

// ===========================================================================
// rgemm_mma: E[bh][m][t] = exp( sum_d RW[m][d] * K[b][t][h*64+d] ), tf32 mma.
// Also writes per-tile row sums (raw) to g_lp[(bh*NROOT+m)*NTILE + j].
// CTA = (t-tile 64, m-tile 64, bh), 256 threads / 8 warps (4 over m, 2 over t).
// ===========================================================================
__global__ __launch_bounds__(256) void rgemm_mma() {
    __shared__ float As[64 * 68];   // RW tile [m][d]
    __shared__ float Bs[64 * 68];   // K tile  [t][d]   (B frag: [n=t][k=d])
    __shared__ float rsum[64];
    int tid = threadIdx.x;
    int lane = tid & 31, w = tid >> 5;
    int lq = lane & 3, lr = lane >> 2;
    int wm = (w & 3) * 16, wt = (w >> 2) * 32;
    int j = blockIdx.x, m0 = blockIdx.y * 64, bh = blockIdx.z;
    int b = bh >> 4, h = bh & 15;
    int t0 = j * 64;

    if (tid < 64) rsum[tid] = 0.f;
#pragma unroll
    for (int i = 0; i < 4; i++) {
        int idx = tid + i * 256;               // 1024 float4s
        int r = idx >> 4, c4 = (idx & 15) * 4;
        int m = m0 + r;
        float4 a = (m < NROOT) ? *(const float4*)(g_RW + m * HDIM + c4)
                               : make_float4(0, 0, 0, 0);
        *(float4*)(As + r * 68 + c4) = a;
        float4 kk = *(const float4*)(g_k + ((size_t)b * SEQ + t0 + r) * DMODEL + h * HDIM + c4);
        *(float4*)(Bs + r * 68 + c4) = kk;
    }
    __syncthreads();

    float acc[4][4];
#pragma unroll
    for (int nt = 0; nt < 4; nt++)
#pragma unroll
        for (int q = 0; q < 4; q++) acc[nt][q] = 0.f;

#pragma unroll
    for (int ks = 0; ks < 8; ks++) {
        int kk = ks * 8;
        uint32_t a[4];
        a[0] = cvt1(As[(wm + lr) * 68 + kk + lq]);
        a[1] = cvt1(As[(wm + lr + 8) * 68 + kk + lq]);
        a[2] = cvt1(As[(wm + lr) * 68 + kk + lq + 4]);
        a[3] = cvt1(As[(wm + lr + 8) * 68 + kk + lq + 4]);
#pragma unroll
        for (int nt = 0; nt < 4; nt++) {
            int cc = wt + nt * 8 + lr;
            uint32_t bb[2];
            bb[0] = cvt1(Bs[cc * 68 + kk + lq]);
            bb[1] = cvt1(Bs[cc * 68 + kk + lq + 4]);
            MMA8(acc[nt], a, bb);
        }
    }

    // exp + store + per-row partial sums
    int mA = m0 + wm + lr, mB = mA + 8;
    float sA = 0.f, sB = 0.f;
#pragma unroll
    for (int nt = 0; nt < 4; nt++) {
        float e0 = __expf(acc[nt][0]);
        float e1 = __expf(acc[nt][1]);
        float e2 = __expf(acc[nt][2]);
        float e3 = __expf(acc[nt][3]);
        sA += e0 + e1; sB += e2 + e3;
        int col = t0 + wt + nt * 8 + lq * 2;
        if (mA < NROOT)
            *(float2*)(g_E + ((size_t)bh * NROOT + mA) * SEQ + col) = make_float2(e0, e1);
        if (mB < NROOT)
            *(float2*)(g_E + ((size_t)bh * NROOT + mB) * SEQ + col) = make_float2(e2, e3);
    }
    // reduce over the 4 lanes sharing a row (lanes lr*4 + lq)
    sA += __shfl_xor_sync(0xffffffffu, sA, 1);
    sA += __shfl_xor_sync(0xffffffffu, sA, 2);
    sB += __shfl_xor_sync(0xffffffffu, sB, 1);
    sB += __shfl_xor_sync(0xffffffffu, sB, 2);
    if (lq == 0) {
        atomicAdd(&rsum[wm + lr], sA);
        atomicAdd(&rsum[wm + lr + 8], sB);
    }
    __syncthreads();
    if (tid < 64) {
        int m = m0 + tid;
        if (m < NROOT) g_lp[(bh * NROOT + m) * NTILE + j] = rsum[tid];
    }
}

// inclusive cumsum of g_lp over j. one thread per (bh, m) row.
__global__ __launch_bounds__(256) void cumsum_lp() {
    int row = blockIdx.x * 256 + threadIdx.x;
    if (row >= NBH * NROOT) return;
    float* p = g_lp + row * NTILE;
    float run = 0.f;
#pragma unroll
    for (int j = 0; j < NTILE; j++) { run += p[j]; p[j] = run; }
}

// ===========================================================================
// partial_mma: partial[bh][j][m][d] = sum_{s in tile j} E[m][s] * V[s][d], tf32.
// CTA = (j, m-tile 64, bh), 8 warps (4 over m, 2 over d).
// ===========================================================================
__global__ __launch_bounds__(256) void partial_mma() {
    __shared__ float As[64 * 68];   // E tile [m][s]
    __shared__ float Bs[64 * 72];   // V tile [s][d]  (B frag: [k=s][n=d])
    int tid = threadIdx.x;
    int lane = tid & 31, w = tid >> 5;
    int lq = lane & 3, lr = lane >> 2;
    int wm = (w & 3) * 16, wd = (w >> 2) * 32;
    int j = blockIdx.x, m0 = blockIdx.y * 64, bh = blockIdx.z;
    int b = bh >> 4, h = bh & 15;
    int s0 = j * 64;

#pragma unroll
    for (int i = 0; i < 4; i++) {
        int idx = tid + i * 256;
        int r = idx >> 4, c4 = (idx & 15) * 4;
        int m = m0 + r;
        float4 e = (m < NROOT)
            ? *(const float4*)(g_E + ((size_t)bh * NROOT + m) * SEQ + s0 + c4)
            : make_float4(0, 0, 0, 0);
        *(float4*)(As + r * 68 + c4) = e;
        float4 v = *(const float4*)(g_v + ((size_t)b * SEQ + s0 + r) * DMODEL + h * HDIM + c4);
        *(float4*)(Bs + r * 72 + c4) = v;
    }
    __syncthreads();

    float acc[4][4];
#pragma unroll
    for (int nt = 0; nt < 4; nt++)
#pragma unroll
        for (int q = 0; q < 4; q++) acc[nt][q] = 0.f;

#pragma unroll
    for (int ks = 0; ks < 8; ks++) {
        int kk = ks * 8;
        uint32_t a[4];
        a[0] = cvt1(As[(wm + lr) * 68 + kk + lq]);
        a[1] = cvt1(As[(wm + lr + 8) * 68 + kk + lq]);
        a[2] = cvt1(As[(wm + lr) * 68 + kk + lq + 4]);
        a[3] = cvt1(As[(wm + lr + 8) * 68 + kk + lq + 4]);
#pragma unroll
        for (int nt = 0; nt < 4; nt++) {
            int cc = wd + nt * 8 + lr;
            uint32_t bb[2];
            bb[0] = cvt1(Bs[(kk + lq) * 72 + cc]);
            bb[1] = cvt1(Bs[(kk + lq + 4) * 72 + cc]);
            MMA8(acc[nt], a, bb);
        }
    }

    int mA = m0 + wm + lr, mB = mA + 8;
    float* base = g_P + (size_t)(bh * NTILE + j) * NROOT * 64;
#pragma unroll
    for (int nt = 0; nt < 4; nt++) {
        int d = wd + nt * 8 + lq * 2;
        if (mA < NROOT) *(float2*)(base + mA * 64 + d) = make_float2(acc[nt][0], acc[nt][1]);
        if (mB < NROOT) *(float2*)(base + mB * 64 + d) = make_float2(acc[nt][2], acc[nt][3]);
    }
}

// ===========================================================================
// in-place inclusive cumsum of g_P over j. thread per (bh, m, d).
// ===========================================================================
__global__ __launch_bounds__(256) void cumsum_pv() {
    int idx = blockIdx.x * 256 + threadIdx.x;   // 0..15359 (240*64)
    int bh = blockIdx.y;
    float* base = g_P + (size_t)bh * NTILE * NROOT * 64 + idx;
    float run = 0.f;
#pragma unroll 4
    for (int j = 0; j < NTILE; j++) {
        float* p = base + (size_t)j * NROOT * 64;
        run += *p;
        *p = run;
    }
}

// ===========================================================================
// Final: O(t) = (C[bh][jt-1][m] + diag)/(lp[jt-1] + ldiag).
// CTA = (q-tile of 64, bh). 256 threads: 4 per q-row, 16 dims each.
// ===========================================================================
#define VS4 68
__global__ __launch_bounds__(256) void attn_diag() {
    __shared__ float Vs[64 * VS4];
    __shared__ float Es[64 * 65];
    __shared__ int sidx[64];
    int tid = threadIdx.x;
    int mblk = blockIdx.x, bh = blockIdx.y;
    int b = bh >> 4, h = bh & 15;
    int m0 = mblk * 64;
    if (tid < 64) sidx[tid] = g_idx[bh * SEQ + m0 + tid];
    __syncthreads();

#pragma unroll
    for (int k = 0; k < 4; k++) {
        int fl = tid + k * 256; int s = fl >> 4, c4 = (fl & 15) * 4;
        float4 v = *(const float4*)(g_v + ((size_t)b * SEQ + m0 + s) * DMODEL + h * HDIM + c4);
        *(float4*)(Vs + s * VS4 + c4) = v;
    }
    int row = tid >> 2, tg = tid & 3;
    {
        const float* er = g_E + ((size_t)bh * NROOT + sidx[row]) * SEQ + m0 + tg * 16;
#pragma unroll
        for (int u = 0; u < 16; u++) Es[row * 65 + tg * 16 + u] = er[u];
    }
    __syncthreads();

    float4 a0 = {0,0,0,0}, a1 = {0,0,0,0}, a2 = {0,0,0,0}, a3 = {0,0,0,0};
    float l = 0.f;
    for (int s = 0; s <= row; s++) {
        float w = Es[row * 65 + s];
        l += w;
        const float* vp = Vs + s * VS4 + tg * 16;
        float4 v0 = *(const float4*)(vp + 0);
        float4 v1 = *(const float4*)(vp + 4);
        float4 v2 = *(const float4*)(vp + 8);
        float4 v3 = *(const float4*)(vp + 12);
        a0.x += w * v0.x; a0.y += w * v0.y; a0.z += w * v0.z; a0.w += w * v0.w;
        a1.x += w * v1.x; a1.y += w * v1.y; a1.z += w * v1.z; a1.w += w * v1.w;
        a2.x += w * v2.x; a2.y += w * v2.y; a2.z += w * v2.z; a2.w += w * v2.w;
        a3.x += w * v3.x; a3.y += w * v3.y; a3.z += w * v3.z; a3.w += w * v3.w;
    }
    int m = sidx[row];
    if (mblk > 0) {
        const float* cp = g_P + ((size_t)(bh * NTILE + mblk - 1) * NROOT + m) * 64 + tg * 16;
        float4 c0 = *(const float4*)(cp + 0);
        float4 c1 = *(const float4*)(cp + 4);
        float4 c2 = *(const float4*)(cp + 8);
        float4 c3 = *(const float4*)(cp + 12);
        a0.x += c0.x; a0.y += c0.y; a0.z += c0.z; a0.w += c0.w;
        a1.x += c1.x; a1.y += c1.y; a1.z += c1.z; a1.w += c1.w;
        a2.x += c2.x; a2.y += c2.y; a2.z += c2.z; a2.w += c2.w;
        a3.x += c3.x; a3.y += c3.y; a3.z += c3.z; a3.w += c3.w;
        l += g_lp[(bh * NROOT + m) * NTILE + mblk - 1];
    }
    float inv = 1.0f / l;
    float* op = g_o + ((size_t)b * SEQ + m0 + row) * DMODEL + h * HDIM + tg * 16;
    *(float4*)(op + 0)  = make_float4(a0.x * inv, a0.y * inv, a0.z * inv, a0.w * inv);
    *(float4*)(op + 4)  = make_float4(a1.x * inv, a1.y * inv, a1.z * inv, a1.w * inv);
    *(float4*)(op + 8)  = make_float4(a2.x * inv, a2.y * inv, a2.z * inv, a2.w * inv);
    *(float4*)(op + 12) = make_float4(a3.x * inv, a3.y * inv, a3.z * inv, a3.w * inv);
}

// ---------------------------------------------------------------------------
// Launch
// ---------------------------------------------------------------------------
extern "C" void kernel_launch(void* const* d_in, const int* in_sizes, int n_in,
                              void* d_out, int out_size) {
    const float* x     = (const float*)d_in[0];
    const float* Wq    = (const float*)d_in[1];
    const float* Wk    = (const float*)d_in[2];
    const float* Wv    = (const float*)d_in[3];
    const float* Wte8  = (const float*)d_in[4];
    const float* Wfe8  = (const float*)d_in[5];
    const float* Wout  = (const float*)d_in[6];
    float* out = (float*)d_out;

    float *k, *v, *o, *coords, *wqe8;
    cudaGetSymbolAddress((void**)&k, g_k);
    cudaGetSymbolAddress((void**)&v, g_v);
    cudaGetSymbolAddress((void**)&o, g_o);
    cudaGetSymbolAddress((void**)&coords, g_coords);
    cudaGetSymbolAddress((void**)&wqe8, g_Wqe8);

    cudaFuncSetAttribute(gemm_mma<true>,  cudaFuncAttributeMaxDynamicSharedMemorySize, GM_SMEM);
    cudaFuncSetAttribute(gemm_mma<false>, cudaFuncAttributeMaxDynamicSharedMemorySize, GM_SMEM);

    build_wqe8<<<512, 256>>>(Wq, Wte8);
    build_tables<<<1, 256>>>(Wfe8);

    // coords: high precision (feeds the argmin cliff)
    gemm_mma<true><<<dim3(1, 32, 1), 256, GM_SMEM>>>(x, wqe8, coords,
                                                     wqe8, coords, 128, DMODEL);
    e8_argmin<<<256, 256>>>();

    // K and V in one launch, single tf32
    gemm_mma<false><<<dim3(8, 32, 2), 256, GM_SMEM>>>(x, Wk, k, Wv, v, DMODEL, DMODEL);

    rgemm_mma<<<dim3(NTILE, 4, NBH), 256>>>();
    cumsum_lp<<<30, 256>>>();

    partial_mma<<<dim3(NTILE, 4, NBH), 256>>>();
    cumsum_pv<<<dim3(60, NBH), 256>>>();
    attn_diag<<<dim3(32, NBH), 256>>>();

    // output projection, single tf32
    gemm_mma<false><<<dim3(8, 32, 1), 256, GM_SMEM>>>(o, Wout, out,
                                                      Wout, out, DMODEL, DMODEL);
}

// round 9
// speedup vs baseline: 4.2567x; 1.0828x over previous
#include <cuda_runtime.h>
#include <cuda_bf16.h>
#include <math.h>
#include <stdint.h>

#define BATCH 2
#define SEQ   2048
#define DMODEL 1024
#define NHEAD 16
#define HDIM  64
#define MROWS (BATCH*SEQ)          // 4096
#define NBH   (BATCH*NHEAD)        // 32
#define NROOT 240
#define NTILE 32                   // key tiles of 64

// Scratch (device globals; no allocation allowed)
__device__ float g_k[MROWS*DMODEL];
__device__ float g_v[MROWS*DMODEL];
__device__ float g_o[MROWS*DMODEL];
__device__ float g_xr[MROWS*DMODEL];        // tf32-rounded x
__device__ float g_wkr[DMODEL*DMODEL];
__device__ float g_wvr[DMODEL*DMODEL];
__device__ float g_wor[DMODEL*DMODEL];
__device__ float g_E[NBH*NROOT*SEQ];        // exp(S), tf32-rounded fp32
__device__ float g_P[NBH*NTILE*NROOT*64];   // per-tile PV partials -> cumsum
__device__ float g_lp[NBH*NROOT*NTILE];     // per-tile E-row sums -> cumsummed
__device__ float g_coords[MROWS*128];
__device__ float g_coords2[MROWS*128];
__device__ int   g_idx[NBH*SEQ];
__device__ float g_Wqe8[DMODEL*128];
__device__ float g_RW[NROOT*HDIM];
__device__ float g_roots[NROOT*8];

// ===========================================================================
// helpers
// ===========================================================================
__device__ __forceinline__ uint32_t smem_u32(const void* p) {
    uint32_t a;
    asm("{ .reg .u64 t; cvta.to.shared.u64 t, %1; cvt.u32.u64 %0, t; }"
        : "=r"(a) : "l"(p));
    return a;
}
#define CP16(dst, src) \
    asm volatile("cp.async.cg.shared.global [%0], [%1], 16;" :: "r"(dst), "l"(src) : "memory")
#define CP_COMMIT() asm volatile("cp.async.commit_group;" ::: "memory")
#define CP_WAIT(n)  asm volatile("cp.async.wait_group %0;" :: "n"(n) : "memory")

__device__ __forceinline__ void cvt3(float x, uint32_t& hi, uint32_t& lo) {
    asm("cvt.rna.tf32.f32 %0, %1;" : "=r"(hi) : "f"(x));
    float r = x - __uint_as_float(hi);
    asm("cvt.rna.tf32.f32 %0, %1;" : "=r"(lo) : "f"(r));
}
__device__ __forceinline__ uint32_t cvt1(float x) {
    uint32_t t;
    asm("cvt.rna.tf32.f32 %0, %1;" : "=r"(t) : "f"(x));
    return t;
}
__device__ __forceinline__ float rtf32(float x) { return __uint_as_float(cvt1(x)); }

#define MMA8(c, a, b) \
    asm volatile("mma.sync.aligned.m16n8k8.row.col.f32.tf32.tf32.f32 " \
        "{%0,%1,%2,%3}, {%4,%5,%6,%7}, {%8,%9}, {%0,%1,%2,%3};" \
        : "+f"((c)[0]), "+f"((c)[1]), "+f"((c)[2]), "+f"((c)[3]) \
        : "r"((a)[0]), "r"((a)[1]), "r"((a)[2]), "r"((a)[3]), \
          "r"((b)[0]), "r"((b)[1]))

// ===========================================================================
// elementwise tf32 rounding
// ===========================================================================
__global__ __launch_bounds__(256) void round_x(const float* __restrict__ src) {
    int i = blockIdx.x * 256 + threadIdx.x;
    g_xr[i] = rtf32(src[i]);
}
__global__ __launch_bounds__(256) void round_w(const float* __restrict__ a,
                                               const float* __restrict__ b,
                                               const float* __restrict__ c) {
    int i = blockIdx.x * 256 + threadIdx.x;
    const float* s = (blockIdx.y == 0) ? a : (blockIdx.y == 1) ? b : c;
    float* d = (blockIdx.y == 0) ? g_wkr : (blockIdx.y == 1) ? g_wvr : g_wor;
    d[i] = rtf32(s[i]);
}

// ===========================================================================
// mma.sync tf32 GEMM: C[M,N] = A[M,K(lda)] @ B[K,N]
// SPLIT3=true : in-loop cvt3, 3-product split (~1e-7). raw-C store.
// SPLIT3=false: operands PRE-ROUNDED tf32, no in-loop cvt. tf32-rounded C.
// A += blockIdx.z * koff (split-K support). B/C via z-selected slots.
// ===========================================================================
#define AS_STRIDE 36
#define BS_STRIDE 132
#define AS_F (128 * AS_STRIDE)
#define BS_F (32 * BS_STRIDE)
#define STG_F (AS_F + BS_F)
#define GM_SMEM (2 * STG_F * 4)

extern __shared__ float smf[];

template <bool SPLIT3>
__global__ __launch_bounds__(256, SPLIT3 ? 1 : 2)
void gemm_mma(const float* __restrict__ A,
              const float* __restrict__ B0, float* __restrict__ C0,
              const float* __restrict__ B1, float* __restrict__ C1,
              int N, int K, int lda, int koff) {
    const float* B = blockIdx.z ? B1 : B0;
    float* C = blockIdx.z ? C1 : C0;
    A += (size_t)blockIdx.z * koff;
    int tid = threadIdx.x;
    int lane = tid & 31, w = tid >> 5;
    int lq = lane & 3, lr = lane >> 2;
    int wm = (w & 3) * 32, wn = (w >> 2) * 64;
    int n0 = blockIdx.x * 128, m0 = blockIdx.y * 128;
    uint32_t sb = smem_u32(smf);

    float acc[2][8][4];
#pragma unroll
    for (int mt = 0; mt < 2; mt++)
#pragma unroll
        for (int nt = 0; nt < 8; nt++)
#pragma unroll
            for (int j = 0; j < 4; j++) acc[mt][nt][j] = 0.f;

    int ar[4], aq[4], bk[4], bn[4];
#pragma unroll
    for (int i = 0; i < 4; i++) {
        int idx = tid + i * 256;
        ar[i] = idx >> 3; aq[i] = idx & 7;
        bk[i] = idx >> 5; bn[i] = idx & 31;
    }

    auto issue_chunk = [&](int c) {
        int k0 = c * 32;
        uint32_t base = sb + (uint32_t)(c & 1) * (STG_F * 4);
#pragma unroll
        for (int i = 0; i < 4; i++)
            CP16(base + (uint32_t)(ar[i] * AS_STRIDE + aq[i] * 4) * 4,
                 A + (size_t)(m0 + ar[i]) * lda + k0 + aq[i] * 4);
#pragma unroll
        for (int i = 0; i < 4; i++)
            CP16(base + (uint32_t)(AS_F + bk[i] * BS_STRIDE + bn[i] * 4) * 4,
                 B + (size_t)(k0 + bk[i]) * N + n0 + bn[i] * 4);
        CP_COMMIT();
    };

    issue_chunk(0);
    int nchunk = K >> 5;

    for (int c = 0; c < nchunk; c++) {
        if (c < nchunk - 1) { issue_chunk(c + 1); CP_WAIT(1); }
        else                { CP_WAIT(0); }
        __syncthreads();

        const float* As = smf + (c & 1) * STG_F;
        const float* Bs = As + AS_F;

#pragma unroll
        for (int ks = 0; ks < 4; ks++) {
            int kk = ks * 8;
            uint32_t Ah[2][4], Al[2][4];
#pragma unroll
            for (int mt = 0; mt < 2; mt++) {
                int rb = wm + mt * 16 + lr;
                if (SPLIT3) {
                    cvt3(As[rb * AS_STRIDE + kk + lq],           Ah[mt][0], Al[mt][0]);
                    cvt3(As[(rb + 8) * AS_STRIDE + kk + lq],     Ah[mt][1], Al[mt][1]);
                    cvt3(As[rb * AS_STRIDE + kk + lq + 4],       Ah[mt][2], Al[mt][2]);
                    cvt3(As[(rb + 8) * AS_STRIDE + kk + lq + 4], Ah[mt][3], Al[mt][3]);
                } else {
                    Ah[mt][0] = __float_as_uint(As[rb * AS_STRIDE + kk + lq]);
                    Ah[mt][1] = __float_as_uint(As[(rb + 8) * AS_STRIDE + kk + lq]);
                    Ah[mt][2] = __float_as_uint(As[rb * AS_STRIDE + kk + lq + 4]);
                    Ah[mt][3] = __float_as_uint(As[(rb + 8) * AS_STRIDE + kk + lq + 4]);
                }
            }
            uint32_t Bh[8][2], Bl[8][2];
#pragma unroll
            for (int nt = 0; nt < 8; nt++) {
                int cc = wn + nt * 8 + lr;
                if (SPLIT3) {
                    cvt3(Bs[(kk + lq) * BS_STRIDE + cc],     Bh[nt][0], Bl[nt][0]);
                    cvt3(Bs[(kk + lq + 4) * BS_STRIDE + cc], Bh[nt][1], Bl[nt][1]);
                } else {
                    Bh[nt][0] = __float_as_uint(Bs[(kk + lq) * BS_STRIDE + cc]);
                    Bh[nt][1] = __float_as_uint(Bs[(kk + lq + 4) * BS_STRIDE + cc]);
                }
            }
#pragma unroll
            for (int mt = 0; mt < 2; mt++)
#pragma unroll
                for (int nt = 0; nt < 8; nt++) {
                    MMA8(acc[mt][nt], Ah[mt], Bh[nt]);
                    if (SPLIT3) {
                        MMA8(acc[mt][nt], Al[mt], Bh[nt]);
                        MMA8(acc[mt][nt], Ah[mt], Bl[nt]);
                    }
                }
        }
        __syncthreads();
    }

#pragma unroll
    for (int mt = 0; mt < 2; mt++) {
        int row = m0 + wm + mt * 16 + lr;
#pragma unroll
        for (int nt = 0; nt < 8; nt++) {
            int col = n0 + wn + nt * 8 + lq * 2;
            if (SPLIT3) {
                *(float2*)(C + (size_t)row * N + col) =
                    make_float2(acc[mt][nt][0], acc[mt][nt][1]);
                *(float2*)(C + (size_t)(row + 8) * N + col) =
                    make_float2(acc[mt][nt][2], acc[mt][nt][3]);
            } else {
                *(float2*)(C + (size_t)row * N + col) =
                    make_float2(rtf32(acc[mt][nt][0]), rtf32(acc[mt][nt][1]));
                *(float2*)(C + (size_t)(row + 8) * N + col) =
                    make_float2(rtf32(acc[mt][nt][2]), rtf32(acc[mt][nt][3]));
            }
        }
    }
}

// ===========================================================================
// Wqe8[in][h*8+j] = sum_e Wq[in][h*64+e] * Wt[e][j]
// ===========================================================================
__global__ __launch_bounds__(256) void build_wqe8(const float* __restrict__ Wq,
                                                  const float* __restrict__ Wt) {
    int i = blockIdx.x * 256 + threadIdx.x;
    int in = i >> 7, c = i & 127, h = c >> 3, j = c & 7;
    float s = 0.f;
#pragma unroll
    for (int e = 0; e < 64; e++) s += Wq[(size_t)in * DMODEL + h * 64 + e] * Wt[e * 8 + j];
    g_Wqe8[i] = s;
}

// ===========================================================================
// roots (exact reference enumeration) and RW = rtf32(0.125 * roots @ Wf)
// ===========================================================================
__global__ __launch_bounds__(256) void build_tables(const float* __restrict__ Wf) {
    __shared__ float roots[NROOT * 8];
    int tid = threadIdx.x;
    for (int i = tid; i < NROOT * 8; i += 256) {
        int r = i >> 3, d = i & 7;
        float v;
        if (r < 112) {
            int p = r >> 2, s = r & 3;
            int a = 0, b = 1, cnt = 0; bool done = false;
            for (a = 0; a < 8 && !done; a++) {
                for (b = a + 1; b < 8; b++) {
                    if (cnt == p) { done = true; break; }
                    cnt++;
                }
            }
            a--;
            float si = (s & 2) ? -1.f : 1.f;
            float sj = (s & 1) ? -1.f : 1.f;
            v = (d == a) ? si : ((d == b) ? sj : 0.f);
        } else {
            int k = r - 112;
            int mask = (k << 1) | (__popc(k) & 1);
            v = ((mask >> d) & 1) ? -0.5f : 0.5f;
        }
        roots[i] = v;
        g_roots[i] = v;
    }
    __syncthreads();
    for (int i = tid; i < NROOT * HDIM; i += 256) {
        int r = i >> 6, d = i & 63;
        float s = 0.f;
#pragma unroll
        for (int j = 0; j < 8; j++) s += roots[r * 8 + j] * Wf[j * HDIM + d];
        g_RW[i] = rtf32(0.125f * s);
    }
}

// ===========================================================================
// argmin over 240 roots (coords = coords_half0 + coords_half1)
// ===========================================================================
__global__ __launch_bounds__(256) void e8_argmin() {
    __shared__ float roots[NROOT * 8];
    int tid = threadIdx.x;
    for (int i = tid; i < NROOT * 8; i += 256) roots[i] = g_roots[i];
    __syncthreads();
    int id = blockIdx.x * 256 + tid;
    int t = id & (SEQ - 1), h = (id >> 11) & 15, b = id >> 15;
    size_t off = ((size_t)(b * SEQ + t)) * 128 + h * 8;
    const float* cp0 = g_coords + off;
    const float* cp1 = g_coords2 + off;
    float x[8];
#pragma unroll
    for (int j = 0; j < 8; j++) x[j] = cp0[j] + cp1[j];
    int best = 0; float bs = 3.4e38f;
    for (int r = 0; r < NROOT; r++) {
        float dot = 0.f;
#pragma unroll
        for (int j = 0; j < 8; j++) dot += x[j] * roots[r * 8 + j];
        float sc = -2.f * dot + 2.f;
        if (sc < bs) { bs = sc; best = r; }
    }
    g_idx[id] = best;
}

// ===========================================================================
// rgemm_mma: E[bh][m][t] = rtf32(exp( RW[m,:] . K[b][t][h*64:] )), tf32 mma.
// Inputs pre-rounded (RW in build_tables, K in gemm_mma epilogue) -> no cvt.
// Also writes per-tile row sums of rounded E to g_lp.
// ===========================================================================
__global__ __launch_bounds__(256) void rgemm_mma() {
    __shared__ float As[64 * 68];   // RW tile [m][d]
    __shared__ float Bs[64 * 68];   // K tile  [t][d]
    __shared__ float rsum[64];
    int tid = threadIdx.x;
    int lane = tid & 31, w = tid >> 5;
    int lq = lane & 3, lr = lane >> 2;
    int wm = (w & 3) * 16, wt = (w >> 2) * 32;
    int j = blockIdx.x, m0 = blockIdx.y * 64, bh = blockIdx.z;
    int b = bh >> 4, h = bh & 15;
    int t0 = j * 64;

    if (tid < 64) rsum[tid] = 0.f;
#pragma unroll
    for (int i = 0; i < 4; i++) {
        int idx = tid + i * 256;
        int r = idx >> 4, c4 = (idx & 15) * 4;
        int m = m0 + r;
        float4 a = (m < NROOT) ? *(const float4*)(g_RW + m * HDIM + c4)
                               : make_float4(0, 0, 0, 0);
        *(float4*)(As + r * 68 + c4) = a;
        float4 kk = *(const float4*)(g_k + ((size_t)b * SEQ + t0 + r) * DMODEL + h * HDIM + c4);
        *(float4*)(Bs + r * 68 + c4) = kk;
    }
    __syncthreads();

    float acc[4][4];
#pragma unroll
    for (int nt = 0; nt < 4; nt++)
#pragma unroll
        for (int q = 0; q < 4; q++) acc[nt][q] = 0.f;

#pragma unroll
    for (int ks = 0; ks < 8; ks++) {
        int kk = ks * 8;
        uint32_t a[4];
        a[0] = __float_as_uint(As[(wm + lr) * 68 + kk + lq]);
        a[1] = __float_as_uint(As[(wm + lr + 8) * 68 + kk + lq]);
        a[2] = __float_as_uint(As[(wm + lr) * 68 + kk + lq + 4]);
        a[3] = __float_as_uint(As[(wm + lr + 8) * 68 + kk + lq + 4]);
#pragma unroll
        for (int nt = 0; nt < 4; nt++) {
            int cc = wt + nt * 8 + lr;
            uint32_t bb[2];
            bb[0] = __float_as_uint(Bs[cc * 68 + kk + lq]);
            bb[1] = __float_as_uint(Bs[cc * 68 + kk + lq + 4]);
            MMA8(acc[nt], a, bb);
        }
    }

    int mA = m0 + wm + lr, mB = mA + 8;
    float sA = 0.f, sB = 0.f;
#pragma unroll
    for (int nt = 0; nt < 4; nt++) {
        float e0 = rtf32(__expf(acc[nt][0]));
        float e1 = rtf32(__expf(acc[nt][1]));
        float e2 = rtf32(__expf(acc[nt][2]));
        float e3 = rtf32(__expf(acc[nt][3]));
        sA += e0 + e1; sB += e2 + e3;
        int col = t0 + wt + nt * 8 + lq * 2;
        if (mA < NROOT)
            *(float2*)(g_E + ((size_t)bh * NROOT + mA) * SEQ + col) = make_float2(e0, e1);
        if (mB < NROOT)
            *(float2*)(g_E + ((size_t)bh * NROOT + mB) * SEQ + col) = make_float2(e2, e3);
    }
    sA += __shfl_xor_sync(0xffffffffu, sA, 1);
    sA += __shfl_xor_sync(0xffffffffu, sA, 2);
    sB += __shfl_xor_sync(0xffffffffu, sB, 1);
    sB += __shfl_xor_sync(0xffffffffu, sB, 2);
    if (lq == 0) {
        atomicAdd(&rsum[wm + lr], sA);
        atomicAdd(&rsum[wm + lr + 8], sB);
    }
    __syncthreads();
    if (tid < 64) {
        int m = m0 + tid;
        if (m < NROOT) g_lp[(bh * NROOT + m) * NTILE + j] = rsum[tid];
    }
}

// inclusive cumsum of g_lp over j
__global__ __launch_bounds__(256) void cumsum_lp() {
    int row = blockIdx.x * 256 + threadIdx.x;
    if (row >= NBH * NROOT) return;
    float* p = g_lp + row * NTILE;
    float run = 0.f;
#pragma unroll
    for (int j = 0; j < NTILE; j++) { run += p[j]; p[j] = run; }
}

// ===========================================================================
// partial_mma: partial[bh][j][m][d] = sum_{s in tile j} E[m][s]*V[s][d], tf32.
// Inputs pre-rounded -> no cvt.
// ===========================================================================
__global__ __launch_bounds__(256) void partial_mma() {
    __shared__ float As[64 * 68];
    __shared__ float Bs[64 * 72];
    int tid = threadIdx.x;
    int lane = tid & 31, w = tid >> 5;
    int lq = lane & 3, lr = lane >> 2;
    int wm = (w & 3) * 16, wd = (w >> 2) * 32;
    int j = blockIdx.x, m0 = blockIdx.y * 64, bh = blockIdx.z;
    int b = bh >> 4, h = bh & 15;
    int s0 = j * 64;

#pragma unroll
    for (int i = 0; i < 4; i++) {
        int idx = tid + i * 256;
        int r = idx >> 4, c4 = (idx & 15) * 4;
        int m = m0 + r;
        float4 e = (m < NROOT)
            ? *(const float4*)(g_E + ((size_t)bh * NROOT + m) * SEQ + s0 + c4)
            : make_float4(0, 0, 0, 0);
        *(float4*)(As + r * 68 + c4) = e;
        float4 v = *(const float4*)(g_v + ((size_t)b * SEQ + s0 + r) * DMODEL + h * HDIM + c4);
        *(float4*)(Bs + r * 72 + c4) = v;
    }
    __syncthreads();

    float acc[4][4];
#pragma unroll
    for (int nt = 0; nt < 4; nt++)
#pragma unroll
        for (int q = 0; q < 4; q++) acc[nt][q] = 0.f;

#pragma unroll
    for (int ks = 0; ks < 8; ks++) {
        int kk = ks * 8;
        uint32_t a[4];
        a[0] = __float_as_uint(As[(wm + lr) * 68 + kk + lq]);
        a[1] = __float_as_uint(As[(wm + lr + 8) * 68 + kk + lq]);
        a[2] = __float_as_uint(As[(wm + lr) * 68 + kk + lq + 4]);
        a[3] = __float_as_uint(As[(wm + lr + 8) * 68 + kk + lq + 4]);
#pragma unroll
        for (int nt = 0; nt < 4; nt++) {
            int cc = wd + nt * 8 + lr;
            uint32_t bb[2];
            bb[0] = __float_as_uint(Bs[(kk + lq) * 72 + cc]);
            bb[1] = __float_as_uint(Bs[(kk + lq + 4) * 72 + cc]);
            MMA8(acc[nt], a, bb);
        }
    }

    int mA = m0 + wm + lr, mB = mA + 8;
    float* base = g_P + (size_t)(bh * NTILE + j) * NROOT * 64;
#pragma unroll
    for (int nt = 0; nt < 4; nt++) {
        int d = wd + nt * 8 + lq * 2;
        if (mA < NROOT) *(float2*)(base + mA * 64 + d) = make_float2(acc[nt][0], acc[nt][1]);
        if (mB < NROOT) *(float2*)(base + mB * 64 + d) = make_float2(acc[nt][2], acc[nt][3]);
    }
}

// ===========================================================================
// in-place inclusive cumsum of g_P over j
// ===========================================================================
__global__ __launch_bounds__(256) void cumsum_pv() {
    int idx = blockIdx.x * 256 + threadIdx.x;
    int bh = blockIdx.y;
    float* base = g_P + (size_t)bh * NTILE * NROOT * 64 + idx;
    float run = 0.f;
#pragma unroll 4
    for (int j = 0; j < NTILE; j++) {
        float* p = base + (size_t)j * NROOT * 64;
        run += *p;
        *p = run;
    }
}

// ===========================================================================
// Final: O(t) = rtf32((C[jt-1][m] + diag)/(lp[jt-1] + ldiag))
// ===========================================================================
#define VS4 68
__global__ __launch_bounds__(256) void attn_diag() {
    __shared__ float Vs[64 * VS4];
    __shared__ float Es[64 * 65];
    __shared__ int sidx[64];
    int tid = threadIdx.x;
    int mblk = blockIdx.x, bh = blockIdx.y;
    int b = bh >> 4, h = bh & 15;
    int m0 = mblk * 64;
    if (tid < 64) sidx[tid] = g_idx[bh * SEQ + m0 + tid];
    __syncthreads();

#pragma unroll
    for (int k = 0; k < 4; k++) {
        int fl = tid + k * 256; int s = fl >> 4, c4 = (fl & 15) * 4;
        float4 v = *(const float4*)(g_v + ((size_t)b * SEQ + m0 + s) * DMODEL + h * HDIM + c4);
        *(float4*)(Vs + s * VS4 + c4) = v;
    }
    int row = tid >> 2, tg = tid & 3;
    {
        const float* er = g_E + ((size_t)bh * NROOT + sidx[row]) * SEQ + m0 + tg * 16;
#pragma unroll
        for (int u = 0; u < 16; u++) Es[row * 65 + tg * 16 + u] = er[u];
    }
    __syncthreads();

    float4 a0 = {0,0,0,0}, a1 = {0,0,0,0}, a2 = {0,0,0,0}, a3 = {0,0,0,0};
    float l = 0.f;
    for (int s = 0; s <= row; s++) {
        float w = Es[row * 65 + s];
        l += w;
        const float* vp = Vs + s * VS4 + tg * 16;
        float4 v0 = *(const float4*)(vp + 0);
        float4 v1 = *(const float4*)(vp + 4);
        float4 v2 = *(const float4*)(vp + 8);
        float4 v3 = *(const float4*)(vp + 12);
        a0.x += w * v0.x; a0.y += w * v0.y; a0.z += w * v0.z; a0.w += w * v0.w;
        a1.x += w * v1.x; a1.y += w * v1.y; a1.z += w * v1.z; a1.w += w * v1.w;
        a2.x += w * v2.x; a2.y += w * v2.y; a2.z += w * v2.z; a2.w += w * v2.w;
        a3.x += w * v3.x; a3.y += w * v3.y; a3.z += w * v3.z; a3.w += w * v3.w;
    }
    int m = sidx[row];
    if (mblk > 0) {
        const float* cp = g_P + ((size_t)(bh * NTILE + mblk - 1) * NROOT + m) * 64 + tg * 16;
        float4 c0 = *(const float4*)(cp + 0);
        float4 c1 = *(const float4*)(cp + 4);
        float4 c2 = *(const float4*)(cp + 8);
        float4 c3 = *(const float4*)(cp + 12);
        a0.x += c0.x; a0.y += c0.y; a0.z += c0.z; a0.w += c0.w;
        a1.x += c1.x; a1.y += c1.y; a1.z += c1.z; a1.w += c1.w;
        a2.x += c2.x; a2.y += c2.y; a2.z += c2.z; a2.w += c2.w;
        a3.x += c3.x; a3.y += c3.y; a3.z += c3.z; a3.w += c3.w;
        l += g_lp[(bh * NROOT + m) * NTILE + mblk - 1];
    }
    float inv = 1.0f / l;
    float* op = g_o + ((size_t)b * SEQ + m0 + row) * DMODEL + h * HDIM + tg * 16;
    *(float4*)(op + 0)  = make_float4(rtf32(a0.x * inv), rtf32(a0.y * inv), rtf32(a0.z * inv), rtf32(a0.w * inv));
    *(float4*)(op + 4)  = make_float4(rtf32(a1.x * inv), rtf32(a1.y * inv), rtf32(a1.z * inv), rtf32(a1.w * inv));
    *(float4*)(op + 8)  = make_float4(rtf32(a2.x * inv), rtf32(a2.y * inv), rtf32(a2.z * inv), rtf32(a2.w * inv));
    *(float4*)(op + 12) = make_float4(rtf32(a3.x * inv), rtf32(a3.y * inv), rtf32(a3.z * inv), rtf32(a3.w * inv));
}

// ---------------------------------------------------------------------------
// Launch
// ---------------------------------------------------------------------------
extern "C" void kernel_launch(void* const* d_in, const int* in_sizes, int n_in,
                              void* d_out, int out_size) {
    const float* x     = (const float*)d_in[0];
    const float* Wq    = (const float*)d_in[1];
    const float* Wk    = (const float*)d_in[2];
    const float* Wv    = (const float*)d_in[3];
    const float* Wte8  = (const float*)d_in[4];
    const float* Wfe8  = (const float*)d_in[5];
    const float* Wout  = (const float*)d_in[6];
    float* out = (float*)d_out;

    float *k, *v, *o, *coords, *coords2, *wqe8, *xr, *wkr, *wvr, *wor;
    cudaGetSymbolAddress((void**)&k, g_k);
    cudaGetSymbolAddress((void**)&v, g_v);
    cudaGetSymbolAddress((void**)&o, g_o);
    cudaGetSymbolAddress((void**)&coords, g_coords);
    cudaGetSymbolAddress((void**)&coords2, g_coords2);
    cudaGetSymbolAddress((void**)&wqe8, g_Wqe8);
    cudaGetSymbolAddress((void**)&xr, g_xr);
    cudaGetSymbolAddress((void**)&wkr, g_wkr);
    cudaGetSymbolAddress((void**)&wvr, g_wvr);
    cudaGetSymbolAddress((void**)&wor, g_wor);

    cudaFuncSetAttribute(gemm_mma<true>,  cudaFuncAttributeMaxDynamicSharedMemorySize, GM_SMEM);
    cudaFuncSetAttribute(gemm_mma<false>, cudaFuncAttributeMaxDynamicSharedMemorySize, GM_SMEM);

    round_x<<<MROWS * DMODEL / 256, 256>>>(x);
    round_w<<<dim3(DMODEL * DMODEL / 256, 3), 256>>>(Wk, Wv, Wout);
    build_wqe8<<<512, 256>>>(Wq, Wte8);
    build_tables<<<1, 256>>>(Wfe8);

    // coords: high precision, split-K halves (64 CTAs)
    gemm_mma<true><<<dim3(1, 32, 2), 256, GM_SMEM>>>(
        x, wqe8, coords, wqe8 + 512 * 128, coords2, 128, 512, DMODEL, 512);
    e8_argmin<<<256, 256>>>();

    // K and V in one launch, pre-rounded tf32 operands (no in-loop cvt)
    gemm_mma<false><<<dim3(8, 32, 2), 256, GM_SMEM>>>(
        xr, wkr, k, wvr, v, DMODEL, DMODEL, DMODEL, 0);

    rgemm_mma<<<dim3(NTILE, 4, NBH), 256>>>();
    cumsum_lp<<<30, 256>>>();

    partial_mma<<<dim3(NTILE, 4, NBH), 256>>>();
    cumsum_pv<<<dim3(60, NBH), 256>>>();
    attn_diag<<<dim3(32, NBH), 256>>>();

    // output projection
    gemm_mma<false><<<dim3(8, 32, 1), 256, GM_SMEM>>>(
        o, wor, out, wor, out, DMODEL, DMODEL, DMODEL, 0);
}

// round 10
// speedup vs baseline: 5.2129x; 1.2247x over previous
#include <cuda_runtime.h>
#include <cuda_bf16.h>
#include <math.h>
#include <stdint.h>

#define BATCH 2
#define SEQ   2048
#define DMODEL 1024
#define NHEAD 16
#define HDIM  64
#define MROWS (BATCH*SEQ)          // 4096
#define NBH   (BATCH*NHEAD)        // 32
#define NROOT 240
#define NTILE 32                   // key tiles of 64

// Scratch (device globals; no allocation allowed)
__device__ float g_k[MROWS*DMODEL];
__device__ float g_v[MROWS*DMODEL];
__device__ float g_o[MROWS*DMODEL];
__device__ float g_xr[MROWS*DMODEL];        // tf32-rounded x
__device__ float g_wkr[DMODEL*DMODEL];
__device__ float g_wvr[DMODEL*DMODEL];
__device__ float g_wor[DMODEL*DMODEL];
__device__ float g_E[NBH*NROOT*SEQ];        // exp(S), tf32-rounded fp32
__device__ float g_P[NBH*NTILE*NROOT*64];   // per-tile PV partials -> cumsum
__device__ float g_lp[NBH*NROOT*NTILE];     // per-tile E-row sums -> cumsummed
__device__ float g_coords[MROWS*128];
__device__ float g_coords2[MROWS*128];
__device__ int   g_idx[NBH*SEQ];
__device__ float g_Wqe8[DMODEL*128];
__device__ float g_RW[NROOT*HDIM];

// ===========================================================================
// helpers
// ===========================================================================
__device__ __forceinline__ uint32_t smem_u32(const void* p) {
    uint32_t a;
    asm("{ .reg .u64 t; cvta.to.shared.u64 t, %1; cvt.u32.u64 %0, t; }"
        : "=r"(a) : "l"(p));
    return a;
}
#define CP16(dst, src) \
    asm volatile("cp.async.cg.shared.global [%0], [%1], 16;" :: "r"(dst), "l"(src) : "memory")
#define CP_COMMIT() asm volatile("cp.async.commit_group;" ::: "memory")
#define CP_WAIT(n)  asm volatile("cp.async.wait_group %0;" :: "n"(n) : "memory")

__device__ __forceinline__ void cvt3(float x, uint32_t& hi, uint32_t& lo) {
    asm("cvt.rna.tf32.f32 %0, %1;" : "=r"(hi) : "f"(x));
    float r = x - __uint_as_float(hi);
    asm("cvt.rna.tf32.f32 %0, %1;" : "=r"(lo) : "f"(r));
}
__device__ __forceinline__ uint32_t cvt1(float x) {
    uint32_t t;
    asm("cvt.rna.tf32.f32 %0, %1;" : "=r"(t) : "f"(x));
    return t;
}
__device__ __forceinline__ float rtf32(float x) { return __uint_as_float(cvt1(x)); }

#define MMA8(c, a, b) \
    asm volatile("mma.sync.aligned.m16n8k8.row.col.f32.tf32.tf32.f32 " \
        "{%0,%1,%2,%3}, {%4,%5,%6,%7}, {%8,%9}, {%0,%1,%2,%3};" \
        : "+f"((c)[0]), "+f"((c)[1]), "+f"((c)[2]), "+f"((c)[3]) \
        : "r"((a)[0]), "r"((a)[1]), "r"((a)[2]), "r"((a)[3]), \
          "r"((b)[0]), "r"((b)[1]))

// ===========================================================================
// fused prep: round x, round Wk/Wv/Wout, build Wqe8, build RW tables
// ===========================================================================
#define PB_X (MROWS * DMODEL / 256)      // 16384
#define PB_W (DMODEL * DMODEL / 256)     // 4096
#define PB_Q 512
#define PB_T 8
#define PREP_BLKS (PB_X + 3 * PB_W + PB_Q + PB_T)

__global__ __launch_bounds__(256) void prep(const float* __restrict__ x,
                                            const float* __restrict__ Wq,
                                            const float* __restrict__ Wk,
                                            const float* __restrict__ Wv,
                                            const float* __restrict__ Wt,
                                            const float* __restrict__ Wf) {
    int tid = threadIdx.x;
    int blk = blockIdx.x;
    if (blk < PB_X) {
        int i = blk * 256 + tid;
        g_xr[i] = rtf32(x[i]);
        return;
    }
    blk -= PB_X;
    if (blk < 3 * PB_W) {
        int sel = blk / PB_W;
        int i = (blk % PB_W) * 256 + tid;
        const float* s = (sel == 0) ? Wk : (sel == 1) ? Wv : nullptr;
        if (sel == 2) s = nullptr;
        float* d = (sel == 0) ? g_wkr : (sel == 1) ? g_wvr : g_wor;
        // note: Wout passed via Wv slot trick avoided; recompute pointer:
        const float* src = (sel == 0) ? Wk : (sel == 1) ? Wv : Wq /*placeholder*/;
        (void)s; (void)src;
        const float* real = (sel == 0) ? Wk : (sel == 1) ? Wv : Wf /*unused*/;
        (void)real;
        // proper selection done below (Wout passed separately in launch args via Wt? no):
        return; // replaced by prep2 path — see prep_w
    }
    blk -= 3 * PB_W;
    if (blk < PB_Q) {
        int i = blk * 256 + tid;           // < 1024*128
        int in = i >> 7, c = i & 127, h = c >> 3, j = c & 7;
        float s = 0.f;
#pragma unroll
        for (int e = 0; e < 64; e++) s += Wq[(size_t)in * DMODEL + h * 64 + e] * Wt[e * 8 + j];
        g_Wqe8[i] = s;
        return;
    }
    blk -= PB_Q;
    {
        // tables: 8 blocks, each derives roots locally then fills 1/8 of RW
        __shared__ float roots[NROOT * 8];
        for (int i = tid; i < NROOT * 8; i += 256) {
            int r = i >> 3, d = i & 7;
            float v;
            if (r < 112) {
                int p = r >> 2, s = r & 3;
                int a = 0, b = 1, cnt = 0; bool done = false;
                for (a = 0; a < 8 && !done; a++) {
                    for (b = a + 1; b < 8; b++) {
                        if (cnt == p) { done = true; break; }
                        cnt++;
                    }
                }
                a--;
                float si = (s & 2) ? -1.f : 1.f;
                float sj = (s & 1) ? -1.f : 1.f;
                v = (d == a) ? si : ((d == b) ? sj : 0.f);
            } else {
                int k = r - 112;
                int mask = (k << 1) | (__popc(k) & 1);
                v = ((mask >> d) & 1) ? -0.5f : 0.5f;
            }
            roots[i] = v;
        }
        __syncthreads();
        int base = blk * (NROOT * HDIM / PB_T);    // 1920 per block
        for (int t = tid; t < NROOT * HDIM / PB_T; t += 256) {
            int i = base + t;
            int r = i >> 6, d = i & 63;
            float s = 0.f;
#pragma unroll
            for (int j = 0; j < 8; j++) s += roots[r * 8 + j] * Wf[j * HDIM + d];
            g_RW[i] = rtf32(0.125f * s);
        }
    }
}

// separate weight-rounding kernel (keeps prep simple/correct)
__global__ __launch_bounds__(256) void prep_w(const float* __restrict__ Wk,
                                              const float* __restrict__ Wv,
                                              const float* __restrict__ Wo) {
    int i = blockIdx.x * 256 + threadIdx.x;
    const float* s = (blockIdx.y == 0) ? Wk : (blockIdx.y == 1) ? Wv : Wo;
    float* d = (blockIdx.y == 0) ? g_wkr : (blockIdx.y == 1) ? g_wvr : g_wor;
    d[i] = rtf32(s[i]);
}

// ===========================================================================
// mma.sync tf32 GEMM: C[M,N] = A[M,K(lda)] @ B[K,N]
// ===========================================================================
#define AS_STRIDE 36
#define BS_STRIDE 132
#define AS_F (128 * AS_STRIDE)
#define BS_F (32 * BS_STRIDE)
#define STG_F (AS_F + BS_F)
#define GM_SMEM (2 * STG_F * 4)

extern __shared__ float smf[];

template <bool SPLIT3>
__global__ __launch_bounds__(256, SPLIT3 ? 1 : 2)
void gemm_mma(const float* __restrict__ A,
              const float* __restrict__ B0, float* __restrict__ C0,
              const float* __restrict__ B1, float* __restrict__ C1,
              int N, int K, int lda, int koff) {
    const float* B = blockIdx.z ? B1 : B0;
    float* C = blockIdx.z ? C1 : C0;
    A += (size_t)blockIdx.z * koff;
    int tid = threadIdx.x;
    int lane = tid & 31, w = tid >> 5;
    int lq = lane & 3, lr = lane >> 2;
    int wm = (w & 3) * 32, wn = (w >> 2) * 64;
    int n0 = blockIdx.x * 128, m0 = blockIdx.y * 128;
    uint32_t sb = smem_u32(smf);

    float acc[2][8][4];
#pragma unroll
    for (int mt = 0; mt < 2; mt++)
#pragma unroll
        for (int nt = 0; nt < 8; nt++)
#pragma unroll
            for (int j = 0; j < 4; j++) acc[mt][nt][j] = 0.f;

    int ar[4], aq[4], bk[4], bn[4];
#pragma unroll
    for (int i = 0; i < 4; i++) {
        int idx = tid + i * 256;
        ar[i] = idx >> 3; aq[i] = idx & 7;
        bk[i] = idx >> 5; bn[i] = idx & 31;
    }

    auto issue_chunk = [&](int c) {
        int k0 = c * 32;
        uint32_t base = sb + (uint32_t)(c & 1) * (STG_F * 4);
#pragma unroll
        for (int i = 0; i < 4; i++)
            CP16(base + (uint32_t)(ar[i] * AS_STRIDE + aq[i] * 4) * 4,
                 A + (size_t)(m0 + ar[i]) * lda + k0 + aq[i] * 4);
#pragma unroll
        for (int i = 0; i < 4; i++)
            CP16(base + (uint32_t)(AS_F + bk[i] * BS_STRIDE + bn[i] * 4) * 4,
                 B + (size_t)(k0 + bk[i]) * N + n0 + bn[i] * 4);
        CP_COMMIT();
    };

    issue_chunk(0);
    int nchunk = K >> 5;

    for (int c = 0; c < nchunk; c++) {
        if (c < nchunk - 1) { issue_chunk(c + 1); CP_WAIT(1); }
        else                { CP_WAIT(0); }
        __syncthreads();

        const float* As = smf + (c & 1) * STG_F;
        const float* Bs = As + AS_F;

#pragma unroll
        for (int ks = 0; ks < 4; ks++) {
            int kk = ks * 8;
            uint32_t Ah[2][4], Al[2][4];
#pragma unroll
            for (int mt = 0; mt < 2; mt++) {
                int rb = wm + mt * 16 + lr;
                if (SPLIT3) {
                    cvt3(As[rb * AS_STRIDE + kk + lq],           Ah[mt][0], Al[mt][0]);
                    cvt3(As[(rb + 8) * AS_STRIDE + kk + lq],     Ah[mt][1], Al[mt][1]);
                    cvt3(As[rb * AS_STRIDE + kk + lq + 4],       Ah[mt][2], Al[mt][2]);
                    cvt3(As[(rb + 8) * AS_STRIDE + kk + lq + 4], Ah[mt][3], Al[mt][3]);
                } else {
                    Ah[mt][0] = __float_as_uint(As[rb * AS_STRIDE + kk + lq]);
                    Ah[mt][1] = __float_as_uint(As[(rb + 8) * AS_STRIDE + kk + lq]);
                    Ah[mt][2] = __float_as_uint(As[rb * AS_STRIDE + kk + lq + 4]);
                    Ah[mt][3] = __float_as_uint(As[(rb + 8) * AS_STRIDE + kk + lq + 4]);
                }
            }
            uint32_t Bh[8][2], Bl[8][2];
#pragma unroll
            for (int nt = 0; nt < 8; nt++) {
                int cc = wn + nt * 8 + lr;
                if (SPLIT3) {
                    cvt3(Bs[(kk + lq) * BS_STRIDE + cc],     Bh[nt][0], Bl[nt][0]);
                    cvt3(Bs[(kk + lq + 4) * BS_STRIDE + cc], Bh[nt][1], Bl[nt][1]);
                } else {
                    Bh[nt][0] = __float_as_uint(Bs[(kk + lq) * BS_STRIDE + cc]);
                    Bh[nt][1] = __float_as_uint(Bs[(kk + lq + 4) * BS_STRIDE + cc]);
                }
            }
#pragma unroll
            for (int mt = 0; mt < 2; mt++)
#pragma unroll
                for (int nt = 0; nt < 8; nt++) {
                    MMA8(acc[mt][nt], Ah[mt], Bh[nt]);
                    if (SPLIT3) {
                        MMA8(acc[mt][nt], Al[mt], Bh[nt]);
                        MMA8(acc[mt][nt], Ah[mt], Bl[nt]);
                    }
                }
        }
        __syncthreads();
    }

#pragma unroll
    for (int mt = 0; mt < 2; mt++) {
        int row = m0 + wm + mt * 16 + lr;
#pragma unroll
        for (int nt = 0; nt < 8; nt++) {
            int col = n0 + wn + nt * 8 + lq * 2;
            if (SPLIT3) {
                *(float2*)(C + (size_t)row * N + col) =
                    make_float2(acc[mt][nt][0], acc[mt][nt][1]);
                *(float2*)(C + (size_t)(row + 8) * N + col) =
                    make_float2(acc[mt][nt][2], acc[mt][nt][3]);
            } else {
                *(float2*)(C + (size_t)row * N + col) =
                    make_float2(rtf32(acc[mt][nt][0]), rtf32(acc[mt][nt][1]));
                *(float2*)(C + (size_t)(row + 8) * N + col) =
                    make_float2(rtf32(acc[mt][nt][2]), rtf32(acc[mt][nt][3]));
            }
        }
    }
}

// ===========================================================================
// closed-form E8 argmin: best pair root = top-2 |x|; best half root =
// sign mask with parity fix at min |x|. Index recovered analytically.
// ===========================================================================
__global__ __launch_bounds__(256) void e8_argmin_fast() {
    int id = blockIdx.x * 256 + threadIdx.x;
    int t = id & (SEQ - 1), h = (id >> 11) & 15, b = id >> 15;
    size_t off = ((size_t)(b * SEQ + t)) * 128 + h * 8;
    float x[8];
#pragma unroll
    for (int j = 0; j < 8; j++) x[j] = g_coords[off + j] + g_coords2[off + j];

    // pair root: top-2 |x| (first index on ties)
    int i1 = 0, i2 = -1;
    float m1 = fabsf(x[0]), m2 = -1.f;
#pragma unroll
    for (int j = 1; j < 8; j++) {
        float a = fabsf(x[j]);
        if (a > m1) { m2 = m1; i2 = i1; m1 = a; i1 = j; }
        else if (a > m2) { m2 = a; i2 = j; }
    }
    int a = min(i1, i2), bb = max(i1, i2);
    float dotp = m1 + m2;
    int p = a * 7 - (a * (a - 1)) / 2 + (bb - a - 1);
    int s = ((x[a] < 0.f) ? 2 : 0) | ((x[bb] < 0.f) ? 1 : 0);
    int idx_pair = p * 4 + s;

    // half root
    float S = 0.f, mn = 3.4e38f;
    int mni = 0, mask = 0, cnt = 0;
#pragma unroll
    for (int j = 0; j < 8; j++) {
        float aa = fabsf(x[j]);
        S += aa;
        if (aa < mn) { mn = aa; mni = j; }
        if (x[j] < 0.f) { mask |= 1 << j; cnt++; }
    }
    if (cnt & 1) mask ^= (1 << mni);
    float doth = 0.5f * S - ((cnt & 1) ? mn : 0.f);

    g_idx[id] = (dotp >= doth) ? idx_pair : (112 + (mask >> 1));
}

// ===========================================================================
// rgemm_mma: E[bh][m][t] = rtf32(exp( RW[m,:] . K[b][t][h*64:] )), tf32 mma.
// ===========================================================================
__global__ __launch_bounds__(256) void rgemm_mma() {
    __shared__ float As[64 * 68];
    __shared__ float Bs[64 * 68];
    __shared__ float rsum[64];
    int tid = threadIdx.x;
    int lane = tid & 31, w = tid >> 5;
    int lq = lane & 3, lr = lane >> 2;
    int wm = (w & 3) * 16, wt = (w >> 2) * 32;
    int j = blockIdx.x, m0 = blockIdx.y * 64, bh = blockIdx.z;
    int b = bh >> 4, h = bh & 15;
    int t0 = j * 64;

    if (tid < 64) rsum[tid] = 0.f;
#pragma unroll
    for (int i = 0; i < 4; i++) {
        int idx = tid + i * 256;
        int r = idx >> 4, c4 = (idx & 15) * 4;
        int m = m0 + r;
        float4 a = (m < NROOT) ? *(const float4*)(g_RW + m * HDIM + c4)
                               : make_float4(0, 0, 0, 0);
        *(float4*)(As + r * 68 + c4) = a;
        float4 kk = *(const float4*)(g_k + ((size_t)b * SEQ + t0 + r) * DMODEL + h * HDIM + c4);
        *(float4*)(Bs + r * 68 + c4) = kk;
    }
    __syncthreads();

    float acc[4][4];
#pragma unroll
    for (int nt = 0; nt < 4; nt++)
#pragma unroll
        for (int q = 0; q < 4; q++) acc[nt][q] = 0.f;

#pragma unroll
    for (int ks = 0; ks < 8; ks++) {
        int kk = ks * 8;
        uint32_t a[4];
        a[0] = __float_as_uint(As[(wm + lr) * 68 + kk + lq]);
        a[1] = __float_as_uint(As[(wm + lr + 8) * 68 + kk + lq]);
        a[2] = __float_as_uint(As[(wm + lr) * 68 + kk + lq + 4]);
        a[3] = __float_as_uint(As[(wm + lr + 8) * 68 + kk + lq + 4]);
#pragma unroll
        for (int nt = 0; nt < 4; nt++) {
            int cc = wt + nt * 8 + lr;
            uint32_t bb[2];
            bb[0] = __float_as_uint(Bs[cc * 68 + kk + lq]);
            bb[1] = __float_as_uint(Bs[cc * 68 + kk + lq + 4]);
            MMA8(acc[nt], a, bb);
        }
    }

    int mA = m0 + wm + lr, mB = mA + 8;
    float sA = 0.f, sB = 0.f;
#pragma unroll
    for (int nt = 0; nt < 4; nt++) {
        float e0 = rtf32(__expf(acc[nt][0]));
        float e1 = rtf32(__expf(acc[nt][1]));
        float e2 = rtf32(__expf(acc[nt][2]));
        float e3 = rtf32(__expf(acc[nt][3]));
        sA += e0 + e1; sB += e2 + e3;
        int col = t0 + wt + nt * 8 + lq * 2;
        if (mA < NROOT)
            *(float2*)(g_E + ((size_t)bh * NROOT + mA) * SEQ + col) = make_float2(e0, e1);
        if (mB < NROOT)
            *(float2*)(g_E + ((size_t)bh * NROOT + mB) * SEQ + col) = make_float2(e2, e3);
    }
    sA += __shfl_xor_sync(0xffffffffu, sA, 1);
    sA += __shfl_xor_sync(0xffffffffu, sA, 2);
    sB += __shfl_xor_sync(0xffffffffu, sB, 1);
    sB += __shfl_xor_sync(0xffffffffu, sB, 2);
    if (lq == 0) {
        atomicAdd(&rsum[wm + lr], sA);
        atomicAdd(&rsum[wm + lr + 8], sB);
    }
    __syncthreads();
    if (tid < 64) {
        int m = m0 + tid;
        if (m < NROOT) g_lp[(bh * NROOT + m) * NTILE + j] = rsum[tid];
    }
}

// inclusive cumsum of g_lp over j
__global__ __launch_bounds__(256) void cumsum_lp() {
    int row = blockIdx.x * 256 + threadIdx.x;
    if (row >= NBH * NROOT) return;
    float* p = g_lp + row * NTILE;
    float run = 0.f;
#pragma unroll
    for (int j = 0; j < NTILE; j++) { run += p[j]; p[j] = run; }
}

// ===========================================================================
// partial_mma: partial[bh][j][m][d] = sum_{s in tile j} E[m][s]*V[s][d], tf32.
// ===========================================================================
__global__ __launch_bounds__(256) void partial_mma() {
    __shared__ float As[64 * 68];
    __shared__ float Bs[64 * 72];
    int tid = threadIdx.x;
    int lane = tid & 31, w = tid >> 5;
    int lq = lane & 3, lr = lane >> 2;
    int wm = (w & 3) * 16, wd = (w >> 2) * 32;
    int j = blockIdx.x, m0 = blockIdx.y * 64, bh = blockIdx.z;
    int b = bh >> 4, h = bh & 15;
    int s0 = j * 64;

#pragma unroll
    for (int i = 0; i < 4; i++) {
        int idx = tid + i * 256;
        int r = idx >> 4, c4 = (idx & 15) * 4;
        int m = m0 + r;
        float4 e = (m < NROOT)
            ? *(const float4*)(g_E + ((size_t)bh * NROOT + m) * SEQ + s0 + c4)
            : make_float4(0, 0, 0, 0);
        *(float4*)(As + r * 68 + c4) = e;
        float4 v = *(const float4*)(g_v + ((size_t)b * SEQ + s0 + r) * DMODEL + h * HDIM + c4);
        *(float4*)(Bs + r * 72 + c4) = v;
    }
    __syncthreads();

    float acc[4][4];
#pragma unroll
    for (int nt = 0; nt < 4; nt++)
#pragma unroll
        for (int q = 0; q < 4; q++) acc[nt][q] = 0.f;

#pragma unroll
    for (int ks = 0; ks < 8; ks++) {
        int kk = ks * 8;
        uint32_t a[4];
        a[0] = __float_as_uint(As[(wm + lr) * 68 + kk + lq]);
        a[1] = __float_as_uint(As[(wm + lr + 8) * 68 + kk + lq]);
        a[2] = __float_as_uint(As[(wm + lr) * 68 + kk + lq + 4]);
        a[3] = __float_as_uint(As[(wm + lr + 8) * 68 + kk + lq + 4]);
#pragma unroll
        for (int nt = 0; nt < 4; nt++) {
            int cc = wd + nt * 8 + lr;
            uint32_t bb[2];
            bb[0] = __float_as_uint(Bs[(kk + lq) * 72 + cc]);
            bb[1] = __float_as_uint(Bs[(kk + lq + 4) * 72 + cc]);
            MMA8(acc[nt], a, bb);
        }
    }

    int mA = m0 + wm + lr, mB = mA + 8;
    float* base = g_P + (size_t)(bh * NTILE + j) * NROOT * 64;
#pragma unroll
    for (int nt = 0; nt < 4; nt++) {
        int d = wd + nt * 8 + lq * 2;
        if (mA < NROOT) *(float2*)(base + mA * 64 + d) = make_float2(acc[nt][0], acc[nt][1]);
        if (mB < NROOT) *(float2*)(base + mB * 64 + d) = make_float2(acc[nt][2], acc[nt][3]);
    }
}

// in-place inclusive cumsum of g_P over j
__global__ __launch_bounds__(256) void cumsum_pv() {
    int idx = blockIdx.x * 256 + threadIdx.x;
    int bh = blockIdx.y;
    float* base = g_P + (size_t)bh * NTILE * NROOT * 64 + idx;
    float run = 0.f;
#pragma unroll 4
    for (int j = 0; j < NTILE; j++) {
        float* p = base + (size_t)j * NROOT * 64;
        run += *p;
        *p = run;
    }
}

// ===========================================================================
// attn_diag: diagonal tile via tf32 mma on causal-zeroed P, plus prefix add.
// CTA = (q-tile 64, bh). 256 threads / 8 warps (4 over m, 2 over d).
// ===========================================================================
__global__ __launch_bounds__(256) void attn_diag() {
    __shared__ float Ps[64 * 68];
    __shared__ float Vs[64 * 72];
    __shared__ float lsum[64];
    __shared__ int sidx[64];
    int tid = threadIdx.x;
    int lane = tid & 31, w = tid >> 5;
    int lq = lane & 3, lr = lane >> 2;
    int mblk = blockIdx.x, bh = blockIdx.y;
    int b = bh >> 4, h = bh & 15;
    int m0 = mblk * 64;
    if (tid < 64) sidx[tid] = g_idx[bh * SEQ + m0 + tid];
    __syncthreads();

    // V tile [s][d]
#pragma unroll
    for (int k = 0; k < 4; k++) {
        int fl = tid + k * 256; int s = fl >> 4, c4 = (fl & 15) * 4;
        float4 v = *(const float4*)(g_v + ((size_t)b * SEQ + m0 + s) * DMODEL + h * HDIM + c4);
        *(float4*)(Vs + s * 72 + c4) = v;
    }
    // causal-zeroed P tile + row sums (4 threads per row)
    {
        int row = tid >> 2, tg = tid & 3;
        const float* er = g_E + ((size_t)bh * NROOT + sidx[row]) * SEQ + m0 + tg * 16;
        float s = 0.f;
#pragma unroll
        for (int u = 0; u < 16; u++) {
            int sk = tg * 16 + u;
            float e = (sk <= row) ? er[u] : 0.f;
            Ps[row * 68 + sk] = e;
            s += e;
        }
        s += __shfl_xor_sync(0xffffffffu, s, 1);
        s += __shfl_xor_sync(0xffffffffu, s, 2);
        if (tg == 0) lsum[row] = s;
    }
    __syncthreads();

    int wm = (w & 3) * 16, wd = (w >> 2) * 32;
    float acc[4][4];
#pragma unroll
    for (int nt = 0; nt < 4; nt++)
#pragma unroll
        for (int q = 0; q < 4; q++) acc[nt][q] = 0.f;

#pragma unroll
    for (int ks = 0; ks < 8; ks++) {
        int kk = ks * 8;
        uint32_t a[4];
        a[0] = __float_as_uint(Ps[(wm + lr) * 68 + kk + lq]);
        a[1] = __float_as_uint(Ps[(wm + lr + 8) * 68 + kk + lq]);
        a[2] = __float_as_uint(Ps[(wm + lr) * 68 + kk + lq + 4]);
        a[3] = __float_as_uint(Ps[(wm + lr + 8) * 68 + kk + lq + 4]);
#pragma unroll
        for (int nt = 0; nt < 4; nt++) {
            int cc = wd + nt * 8 + lr;
            uint32_t bb[2];
            bb[0] = __float_as_uint(Vs[(kk + lq) * 72 + cc]);
            bb[1] = __float_as_uint(Vs[(kk + lq + 4) * 72 + cc]);
            MMA8(acc[nt], a, bb);
        }
    }

    int rA = wm + lr, rB = rA + 8;
    int rootA = sidx[rA], rootB = sidx[rB];
    float lA = lsum[rA], lB = lsum[rB];
    const float* cpA = nullptr;
    const float* cpB = nullptr;
    if (mblk > 0) {
        lA += g_lp[(bh * NROOT + rootA) * NTILE + mblk - 1];
        lB += g_lp[(bh * NROOT + rootB) * NTILE + mblk - 1];
        cpA = g_P + ((size_t)(bh * NTILE + mblk - 1) * NROOT + rootA) * 64;
        cpB = g_P + ((size_t)(bh * NTILE + mblk - 1) * NROOT + rootB) * 64;
    }
    float invA = 1.0f / lA, invB = 1.0f / lB;
    float* oA = g_o + ((size_t)b * SEQ + m0 + rA) * DMODEL + h * HDIM;
    float* oB = g_o + ((size_t)b * SEQ + m0 + rB) * DMODEL + h * HDIM;
#pragma unroll
    for (int nt = 0; nt < 4; nt++) {
        int d = wd + nt * 8 + lq * 2;
        float pa0 = 0.f, pa1 = 0.f, pb0 = 0.f, pb1 = 0.f;
        if (mblk > 0) {
            float2 t0 = *(const float2*)(cpA + d); pa0 = t0.x; pa1 = t0.y;
            float2 t1 = *(const float2*)(cpB + d); pb0 = t1.x; pb1 = t1.y;
        }
        *(float2*)(oA + d) = make_float2(rtf32((acc[nt][0] + pa0) * invA),
                                         rtf32((acc[nt][1] + pa1) * invA));
        *(float2*)(oB + d) = make_float2(rtf32((acc[nt][2] + pb0) * invB),
                                         rtf32((acc[nt][3] + pb1) * invB));
    }
}

// ---------------------------------------------------------------------------
// Launch
// ---------------------------------------------------------------------------
extern "C" void kernel_launch(void* const* d_in, const int* in_sizes, int n_in,
                              void* d_out, int out_size) {
    const float* x     = (const float*)d_in[0];
    const float* Wq    = (const float*)d_in[1];
    const float* Wk    = (const float*)d_in[2];
    const float* Wv    = (const float*)d_in[3];
    const float* Wte8  = (const float*)d_in[4];
    const float* Wfe8  = (const float*)d_in[5];
    const float* Wout  = (const float*)d_in[6];
    float* out = (float*)d_out;

    float *k, *v, *o, *coords, *coords2, *wqe8, *xr, *wkr, *wvr, *wor;
    cudaGetSymbolAddress((void**)&k, g_k);
    cudaGetSymbolAddress((void**)&v, g_v);
    cudaGetSymbolAddress((void**)&o, g_o);
    cudaGetSymbolAddress((void**)&coords, g_coords);
    cudaGetSymbolAddress((void**)&coords2, g_coords2);
    cudaGetSymbolAddress((void**)&wqe8, g_Wqe8);
    cudaGetSymbolAddress((void**)&xr, g_xr);
    cudaGetSymbolAddress((void**)&wkr, g_wkr);
    cudaGetSymbolAddress((void**)&wvr, g_wvr);
    cudaGetSymbolAddress((void**)&wor, g_wor);

    cudaFuncSetAttribute(gemm_mma<true>,  cudaFuncAttributeMaxDynamicSharedMemorySize, GM_SMEM);
    cudaFuncSetAttribute(gemm_mma<false>, cudaFuncAttributeMaxDynamicSharedMemorySize, GM_SMEM);

    // static side-stream + events (created on the pre-capture correctness call)
    static cudaStream_t s2 = nullptr;
    static cudaEvent_t evF = nullptr, evJ = nullptr;
    if (s2 == nullptr) {
        cudaStreamCreateWithFlags(&s2, cudaStreamNonBlocking);
        cudaEventCreateWithFlags(&evF, cudaEventDisableTiming);
        cudaEventCreateWithFlags(&evJ, cudaEventDisableTiming);
    }

    // fused prep: x-round, Wqe8, RW tables (weights rounded separately)
    prep<<<PREP_BLKS, 256>>>(x, Wq, Wk, Wv, Wte8, Wfe8);
    prep_w<<<dim3(PB_W, 3), 256>>>(Wk, Wv, Wout);

    // fork: coords (split-K, high precision) + argmin on side stream
    cudaEventRecord(evF, 0);
    cudaStreamWaitEvent(s2, evF, 0);
    gemm_mma<true><<<dim3(1, 32, 2), 256, GM_SMEM, s2>>>(
        x, wqe8, coords, wqe8 + 512 * 128, coords2, 128, 512, DMODEL, 512);
    e8_argmin_fast<<<256, 256, 0, s2>>>();
    cudaEventRecord(evJ, s2);

    // main stream: K/V, rgemm, partials
    gemm_mma<false><<<dim3(8, 32, 2), 256, GM_SMEM>>>(
        xr, wkr, k, wvr, v, DMODEL, DMODEL, DMODEL, 0);

    rgemm_mma<<<dim3(NTILE, 4, NBH), 256>>>();
    cumsum_lp<<<30, 256>>>();

    partial_mma<<<dim3(NTILE, 4, NBH), 256>>>();
    cumsum_pv<<<dim3(60, NBH), 256>>>();

    // join: attn_diag needs g_idx
    cudaStreamWaitEvent(0, evJ, 0);
    attn_diag<<<dim3(32, NBH), 256>>>();

    // output projection
    gemm_mma<false><<<dim3(8, 32, 1), 256, GM_SMEM>>>(
        o, wor, out, wor, out, DMODEL, DMODEL, DMODEL, 0);
}

// round 12
// speedup vs baseline: 5.6087x; 1.0759x over previous
#include <cuda_runtime.h>
#include <cuda_bf16.h>
#include <math.h>
#include <stdint.h>

#define BATCH 2
#define SEQ   2048
#define DMODEL 1024
#define NHEAD 16
#define HDIM  64
#define MROWS (BATCH*SEQ)          // 4096
#define NBH   (BATCH*NHEAD)        // 32
#define NROOT 240
#define NTILE 32                   // key tiles of 64

// Scratch (device globals; no allocation allowed)
__device__ float g_k[MROWS*DMODEL];
__device__ float g_v[MROWS*DMODEL];
__device__ float g_o[MROWS*DMODEL];
__device__ float g_xr[MROWS*DMODEL];        // tf32-rounded x
__device__ float g_wkr[DMODEL*DMODEL];
__device__ float g_wvr[DMODEL*DMODEL];
__device__ float g_wor[DMODEL*DMODEL];
__device__ float g_E[NBH*NROOT*SEQ];        // exp(S), tf32-rounded fp32
__device__ float g_P[NBH*NTILE*NROOT*64];   // CUMULATIVE per-tile PV partials
__device__ float g_lp[NBH*NROOT*NTILE];     // CUMULATIVE per-tile E-row sums
__device__ float g_coords[MROWS*128];
__device__ float g_coords2[MROWS*128];
__device__ int   g_idx[NBH*SEQ];
__device__ float g_Wqe8[DMODEL*128];
__device__ float g_RW[NROOT*HDIM];

// ===========================================================================
// helpers
// ===========================================================================
__device__ __forceinline__ uint32_t smem_u32(const void* p) {
    uint32_t a;
    asm("{ .reg .u64 t; cvta.to.shared.u64 t, %1; cvt.u32.u64 %0, t; }"
        : "=r"(a) : "l"(p));
    return a;
}
#define CP16(dst, src) \
    asm volatile("cp.async.cg.shared.global [%0], [%1], 16;" :: "r"(dst), "l"(src) : "memory")
#define CP_COMMIT() asm volatile("cp.async.commit_group;" ::: "memory")
#define CP_WAIT(n)  asm volatile("cp.async.wait_group %0;" :: "n"(n) : "memory")

__device__ __forceinline__ void cvt3(float x, uint32_t& hi, uint32_t& lo) {
    asm("cvt.rna.tf32.f32 %0, %1;" : "=r"(hi) : "f"(x));
    float r = x - __uint_as_float(hi);
    asm("cvt.rna.tf32.f32 %0, %1;" : "=r"(lo) : "f"(r));
}
__device__ __forceinline__ uint32_t cvt1(float x) {
    uint32_t t;
    asm("cvt.rna.tf32.f32 %0, %1;" : "=r"(t) : "f"(x));
    return t;
}
__device__ __forceinline__ float rtf32(float x) { return __uint_as_float(cvt1(x)); }

#define MMA8(c, a, b) \
    asm volatile("mma.sync.aligned.m16n8k8.row.col.f32.tf32.tf32.f32 " \
        "{%0,%1,%2,%3}, {%4,%5,%6,%7}, {%8,%9}, {%0,%1,%2,%3};" \
        : "+f"((c)[0]), "+f"((c)[1]), "+f"((c)[2]), "+f"((c)[3]) \
        : "r"((a)[0]), "r"((a)[1]), "r"((a)[2]), "r"((a)[3]), \
          "r"((b)[0]), "r"((b)[1]))

// ===========================================================================
// fused prep: round x, round Wk/Wv/Wout, build Wqe8, build RW tables
// ===========================================================================
#define PB_X (MROWS * DMODEL / 256)      // 16384
#define PB_W (DMODEL * DMODEL / 256)     // 4096
#define PB_Q 512
#define PB_T 8
#define PREP_BLKS (PB_X + 3 * PB_W + PB_Q + PB_T)

__global__ __launch_bounds__(256) void prep(const float* __restrict__ x,
                                            const float* __restrict__ Wq,
                                            const float* __restrict__ Wk,
                                            const float* __restrict__ Wv,
                                            const float* __restrict__ Wo,
                                            const float* __restrict__ Wt,
                                            const float* __restrict__ Wf) {
    int tid = threadIdx.x;
    int blk = blockIdx.x;
    if (blk < PB_X) {
        int i = blk * 256 + tid;
        g_xr[i] = rtf32(x[i]);
        return;
    }
    blk -= PB_X;
    if (blk < 3 * PB_W) {
        int sel = blk / PB_W;
        int i = (blk % PB_W) * 256 + tid;
        const float* s = (sel == 0) ? Wk : (sel == 1) ? Wv : Wo;
        float* d = (sel == 0) ? g_wkr : (sel == 1) ? g_wvr : g_wor;
        d[i] = rtf32(s[i]);
        return;
    }
    blk -= 3 * PB_W;
    if (blk < PB_Q) {
        int i = blk * 256 + tid;           // < 1024*128
        int in = i >> 7, c = i & 127, h = c >> 3, j = c & 7;
        float s = 0.f;
#pragma unroll
        for (int e = 0; e < 64; e++) s += Wq[(size_t)in * DMODEL + h * 64 + e] * Wt[e * 8 + j];
        g_Wqe8[i] = s;
        return;
    }
    blk -= PB_Q;
    {
        // tables: 8 blocks, each derives roots locally then fills 1/8 of RW
        __shared__ float roots[NROOT * 8];
        for (int i = tid; i < NROOT * 8; i += 256) {
            int r = i >> 3, d = i & 7;
            float v;
            if (r < 112) {
                int p = r >> 2, s = r & 3;
                int a = 0, b = 1, cnt = 0; bool done = false;
                for (a = 0; a < 8 && !done; a++) {
                    for (b = a + 1; b < 8; b++) {
                        if (cnt == p) { done = true; break; }
                        cnt++;
                    }
                }
                a--;
                float si = (s & 2) ? -1.f : 1.f;
                float sj = (s & 1) ? -1.f : 1.f;
                v = (d == a) ? si : ((d == b) ? sj : 0.f);
            } else {
                int k = r - 112;
                int mask = (k << 1) | (__popc(k) & 1);
                v = ((mask >> d) & 1) ? -0.5f : 0.5f;
            }
            roots[i] = v;
        }
        __syncthreads();
        int base = blk * (NROOT * HDIM / PB_T);    // 1920 per block
        for (int t = tid; t < NROOT * HDIM / PB_T; t += 256) {
            int i = base + t;
            int r = i >> 6, d = i & 63;
            float s = 0.f;
#pragma unroll
            for (int j = 0; j < 8; j++) s += roots[r * 8 + j] * Wf[j * HDIM + d];
            g_RW[i] = rtf32(0.125f * s);
        }
    }
}

// ===========================================================================
// mma.sync tf32 GEMM: C[M,N] = A[M,K(lda)] @ B[K,N]
// ===========================================================================
#define AS_STRIDE 36
#define BS_STRIDE 132
#define AS_F (128 * AS_STRIDE)
#define BS_F (32 * BS_STRIDE)
#define STG_F (AS_F + BS_F)
#define GM_SMEM (2 * STG_F * 4)

extern __shared__ float smf[];

template <bool SPLIT3>
__global__ __launch_bounds__(256, SPLIT3 ? 1 : 2)
void gemm_mma(const float* __restrict__ A,
              const float* __restrict__ B0, float* __restrict__ C0,
              const float* __restrict__ B1, float* __restrict__ C1,
              int N, int K, int lda, int koff) {
    const float* B = blockIdx.z ? B1 : B0;
    float* C = blockIdx.z ? C1 : C0;
    A += (size_t)blockIdx.z * koff;
    int tid = threadIdx.x;
    int lane = tid & 31, w = tid >> 5;
    int lq = lane & 3, lr = lane >> 2;
    int wm = (w & 3) * 32, wn = (w >> 2) * 64;
    int n0 = blockIdx.x * 128, m0 = blockIdx.y * 128;
    uint32_t sb = smem_u32(smf);

    float acc[2][8][4];
#pragma unroll
    for (int mt = 0; mt < 2; mt++)
#pragma unroll
        for (int nt = 0; nt < 8; nt++)
#pragma unroll
            for (int j = 0; j < 4; j++) acc[mt][nt][j] = 0.f;

    int ar[4], aq[4], bk[4], bn[4];
#pragma unroll
    for (int i = 0; i < 4; i++) {
        int idx = tid + i * 256;
        ar[i] = idx >> 3; aq[i] = idx & 7;
        bk[i] = idx >> 5; bn[i] = idx & 31;
    }

    auto issue_chunk = [&](int c) {
        int k0 = c * 32;
        uint32_t base = sb + (uint32_t)(c & 1) * (STG_F * 4);
#pragma unroll
        for (int i = 0; i < 4; i++)
            CP16(base + (uint32_t)(ar[i] * AS_STRIDE + aq[i] * 4) * 4,
                 A + (size_t)(m0 + ar[i]) * lda + k0 + aq[i] * 4);
#pragma unroll
        for (int i = 0; i < 4; i++)
            CP16(base + (uint32_t)(AS_F + bk[i] * BS_STRIDE + bn[i] * 4) * 4,
                 B + (size_t)(k0 + bk[i]) * N + n0 + bn[i] * 4);
        CP_COMMIT();
    };

    issue_chunk(0);
    int nchunk = K >> 5;

    for (int c = 0; c < nchunk; c++) {
        if (c < nchunk - 1) { issue_chunk(c + 1); CP_WAIT(1); }
        else                { CP_WAIT(0); }
        __syncthreads();

        const float* As = smf + (c & 1) * STG_F;
        const float* Bs = As + AS_F;

#pragma unroll
        for (int ks = 0; ks < 4; ks++) {
            int kk = ks * 8;
            uint32_t Ah[2][4], Al[2][4];
#pragma unroll
            for (int mt = 0; mt < 2; mt++) {
                int rb = wm + mt * 16 + lr;
                if (SPLIT3) {
                    cvt3(As[rb * AS_STRIDE + kk + lq],           Ah[mt][0], Al[mt][0]);
                    cvt3(As[(rb + 8) * AS_STRIDE + kk + lq],     Ah[mt][1], Al[mt][1]);
                    cvt3(As[rb * AS_STRIDE + kk + lq + 4],       Ah[mt][2], Al[mt][2]);
                    cvt3(As[(rb + 8) * AS_STRIDE + kk + lq + 4], Ah[mt][3], Al[mt][3]);
                } else {
                    Ah[mt][0] = __float_as_uint(As[rb * AS_STRIDE + kk + lq]);
                    Ah[mt][1] = __float_as_uint(As[(rb + 8) * AS_STRIDE + kk + lq]);
                    Ah[mt][2] = __float_as_uint(As[rb * AS_STRIDE + kk + lq + 4]);
                    Ah[mt][3] = __float_as_uint(As[(rb + 8) * AS_STRIDE + kk + lq + 4]);
                }
            }
            uint32_t Bh[8][2], Bl[8][2];
#pragma unroll
            for (int nt = 0; nt < 8; nt++) {
                int cc = wn + nt * 8 + lr;
                if (SPLIT3) {
                    cvt3(Bs[(kk + lq) * BS_STRIDE + cc],     Bh[nt][0], Bl[nt][0]);
                    cvt3(Bs[(kk + lq + 4) * BS_STRIDE + cc], Bh[nt][1], Bl[nt][1]);
                } else {
                    Bh[nt][0] = __float_as_uint(Bs[(kk + lq) * BS_STRIDE + cc]);
                    Bh[nt][1] = __float_as_uint(Bs[(kk + lq + 4) * BS_STRIDE + cc]);
                }
            }
#pragma unroll
            for (int mt = 0; mt < 2; mt++)
#pragma unroll
                for (int nt = 0; nt < 8; nt++) {
                    MMA8(acc[mt][nt], Ah[mt], Bh[nt]);
                    if (SPLIT3) {
                        MMA8(acc[mt][nt], Al[mt], Bh[nt]);
                        MMA8(acc[mt][nt], Ah[mt], Bl[nt]);
                    }
                }
        }
        __syncthreads();
    }

#pragma unroll
    for (int mt = 0; mt < 2; mt++) {
        int row = m0 + wm + mt * 16 + lr;
#pragma unroll
        for (int nt = 0; nt < 8; nt++) {
            int col = n0 + wn + nt * 8 + lq * 2;
            if (SPLIT3) {
                *(float2*)(C + (size_t)row * N + col) =
                    make_float2(acc[mt][nt][0], acc[mt][nt][1]);
                *(float2*)(C + (size_t)(row + 8) * N + col) =
                    make_float2(acc[mt][nt][2], acc[mt][nt][3]);
            } else {
                *(float2*)(C + (size_t)row * N + col) =
                    make_float2(rtf32(acc[mt][nt][0]), rtf32(acc[mt][nt][1]));
                *(float2*)(C + (size_t)(row + 8) * N + col) =
                    make_float2(rtf32(acc[mt][nt][2]), rtf32(acc[mt][nt][3]));
            }
        }
    }
}

// ===========================================================================
// closed-form E8 argmin
// ===========================================================================
__global__ __launch_bounds__(256) void e8_argmin_fast() {
    int id = blockIdx.x * 256 + threadIdx.x;
    int t = id & (SEQ - 1), h = (id >> 11) & 15, b = id >> 15;
    size_t off = ((size_t)(b * SEQ + t)) * 128 + h * 8;
    float x[8];
#pragma unroll
    for (int j = 0; j < 8; j++) x[j] = g_coords[off + j] + g_coords2[off + j];

    int i1 = 0, i2 = -1;
    float m1 = fabsf(x[0]), m2 = -1.f;
#pragma unroll
    for (int j = 1; j < 8; j++) {
        float a = fabsf(x[j]);
        if (a > m1) { m2 = m1; i2 = i1; m1 = a; i1 = j; }
        else if (a > m2) { m2 = a; i2 = j; }
    }
    int a = min(i1, i2), bb = max(i1, i2);
    float dotp = m1 + m2;
    int p = a * 7 - (a * (a - 1)) / 2 + (bb - a - 1);
    int s = ((x[a] < 0.f) ? 2 : 0) | ((x[bb] < 0.f) ? 1 : 0);
    int idx_pair = p * 4 + s;

    float S = 0.f, mn = 3.4e38f;
    int mni = 0, mask = 0, cnt = 0;
#pragma unroll
    for (int j = 0; j < 8; j++) {
        float aa = fabsf(x[j]);
        S += aa;
        if (aa < mn) { mn = aa; mni = j; }
        if (x[j] < 0.f) { mask |= 1 << j; cnt++; }
    }
    if (cnt & 1) mask ^= (1 << mni);
    float doth = 0.5f * S - ((cnt & 1) ? mn : 0.f);

    g_idx[id] = (dotp >= doth) ? idx_pair : (112 + (mask >> 1));
}

// ===========================================================================
// attn_mid: FUSED rgemm + exp + running lp + partial PV + running P cumsum.
// RACE FIX vs R11: next-tile cp.async is issued only AFTER the top-of-loop
// barrier, so no thread can overwrite the V buffer another warp is still
// reading in the previous iteration's PV mma.
// ===========================================================================
#define AM_AS 0
#define AM_ES (64 * 68)
#define AM_K  (AM_ES + 64 * 68)
#define AM_V  (AM_K + 2 * 64 * 68)
#define AM_RS (AM_V + 2 * 64 * 72)
#define AM_RUN (AM_RS + 64)
#define AM_SMEM ((AM_RUN + 64) * 4)

__global__ __launch_bounds__(256) void attn_mid() {
    float* As = smf + AM_AS;
    float* Es = smf + AM_ES;
    float* rsum = smf + AM_RS;
    float* running = smf + AM_RUN;
    uint32_t sb = smem_u32(smf);

    int tid = threadIdx.x;
    int lane = tid & 31, w = tid >> 5;
    int lq = lane & 3, lr = lane >> 2;
    int wm = (w & 3) * 16, wt = (w >> 2) * 32;
    int m0 = blockIdx.x * 64, bh = blockIdx.y;
    int b = bh >> 4, h = bh & 15;

    // load RW m-tile (one time)
#pragma unroll
    for (int i = 0; i < 4; i++) {
        int idx = tid + i * 256;
        int r = idx >> 4, c4 = (idx & 15) * 4;
        int m = m0 + r;
        float4 a = (m < NROOT) ? *(const float4*)(g_RW + m * HDIM + c4)
                               : make_float4(0, 0, 0, 0);
        *(float4*)(As + r * 68 + c4) = a;
    }
    if (tid < 64) { running[tid] = 0.f; rsum[tid] = 0.f; }

    auto load_kv = [&](int j, int buf) {
        int t0 = j * 64;
#pragma unroll
        for (int i = 0; i < 4; i++) {
            int idx = tid + i * 256;
            int r = idx >> 4, c4 = (idx & 15) * 4;
            const float* kp = g_k + ((size_t)b * SEQ + t0 + r) * DMODEL + h * HDIM + c4;
            const float* vp = g_v + ((size_t)b * SEQ + t0 + r) * DMODEL + h * HDIM + c4;
            CP16(sb + (uint32_t)(AM_K + buf * 64 * 68 + r * 68 + c4) * 4, kp);
            CP16(sb + (uint32_t)(AM_V + buf * 64 * 72 + r * 72 + c4) * 4, vp);
        }
        CP_COMMIT();
    };
    load_kv(0, 0);

    float pacc[4][4];
#pragma unroll
    for (int nt = 0; nt < 4; nt++)
#pragma unroll
        for (int q = 0; q < 4; q++) pacc[nt][q] = 0.f;

    int mA = m0 + wm + lr, mB = mA + 8;

    for (int j = 0; j < NTILE; j++) {
        CP_WAIT(0);        // current buffer complete (only j's group pending)
        __syncthreads();   // ALL threads done with iteration j-1 (incl. PV reads)
        if (j < NTILE - 1) load_kv(j + 1, (j + 1) & 1);  // safe: post-barrier

        const float* Kb = smf + AM_K + (j & 1) * 64 * 68;
        const float* Vb = smf + AM_V + (j & 1) * 64 * 72;
        int t0 = j * 64;

        // ---- S = RW x K_j ----
        float sacc[4][4];
#pragma unroll
        for (int nt = 0; nt < 4; nt++)
#pragma unroll
            for (int q = 0; q < 4; q++) sacc[nt][q] = 0.f;
#pragma unroll
        for (int ks = 0; ks < 8; ks++) {
            int kk = ks * 8;
            uint32_t a[4];
            a[0] = __float_as_uint(As[(wm + lr) * 68 + kk + lq]);
            a[1] = __float_as_uint(As[(wm + lr + 8) * 68 + kk + lq]);
            a[2] = __float_as_uint(As[(wm + lr) * 68 + kk + lq + 4]);
            a[3] = __float_as_uint(As[(wm + lr + 8) * 68 + kk + lq + 4]);
#pragma unroll
            for (int nt = 0; nt < 4; nt++) {
                int cc = wt + nt * 8 + lr;
                uint32_t bb[2];
                bb[0] = __float_as_uint(Kb[cc * 68 + kk + lq]);
                bb[1] = __float_as_uint(Kb[cc * 68 + kk + lq + 4]);
                MMA8(sacc[nt], a, bb);
            }
        }

        // ---- exp, store E (smem + gmem), row sums ----
        float sA = 0.f, sB = 0.f;
#pragma unroll
        for (int nt = 0; nt < 4; nt++) {
            float e0 = rtf32(__expf(sacc[nt][0]));
            float e1 = rtf32(__expf(sacc[nt][1]));
            float e2 = rtf32(__expf(sacc[nt][2]));
            float e3 = rtf32(__expf(sacc[nt][3]));
            sA += e0 + e1; sB += e2 + e3;
            int col = wt + nt * 8 + lq * 2;
            Es[(wm + lr) * 68 + col] = e0;
            Es[(wm + lr) * 68 + col + 1] = e1;
            Es[(wm + lr + 8) * 68 + col] = e2;
            Es[(wm + lr + 8) * 68 + col + 1] = e3;
            if (mA < NROOT)
                *(float2*)(g_E + ((size_t)bh * NROOT + mA) * SEQ + t0 + col) = make_float2(e0, e1);
            if (mB < NROOT)
                *(float2*)(g_E + ((size_t)bh * NROOT + mB) * SEQ + t0 + col) = make_float2(e2, e3);
        }
        sA += __shfl_xor_sync(0xffffffffu, sA, 1);
        sA += __shfl_xor_sync(0xffffffffu, sA, 2);
        sB += __shfl_xor_sync(0xffffffffu, sB, 1);
        sB += __shfl_xor_sync(0xffffffffu, sB, 2);
        if (lq == 0) {
            atomicAdd(&rsum[wm + lr], sA);
            atomicAdd(&rsum[wm + lr + 8], sB);
        }
        __syncthreads();   // Es + rsum visible

        // ---- pacc += Es x V_j ----
#pragma unroll
        for (int ks = 0; ks < 8; ks++) {
            int kk = ks * 8;
            uint32_t a[4];
            a[0] = __float_as_uint(Es[(wm + lr) * 68 + kk + lq]);
            a[1] = __float_as_uint(Es[(wm + lr + 8) * 68 + kk + lq]);
            a[2] = __float_as_uint(Es[(wm + lr) * 68 + kk + lq + 4]);
            a[3] = __float_as_uint(Es[(wm + lr + 8) * 68 + kk + lq + 4]);
#pragma unroll
            for (int nt = 0; nt < 4; nt++) {
                int cc = wt + nt * 8 + lr;
                uint32_t bb[2];
                bb[0] = __float_as_uint(Vb[(kk + lq) * 72 + cc]);
                bb[1] = __float_as_uint(Vb[(kk + lq + 4) * 72 + cc]);
                MMA8(pacc[nt], a, bb);
            }
        }

        // ---- cumulative lp + P stores ----
        if (tid < 64) {
            int m = m0 + tid;
            float r = running[tid] + rsum[tid];
            running[tid] = r;
            rsum[tid] = 0.f;
            if (m < NROOT) g_lp[(bh * NROOT + m) * NTILE + j] = r;
        }
        float* base = g_P + (size_t)(bh * NTILE + j) * NROOT * 64;
#pragma unroll
        for (int nt = 0; nt < 4; nt++) {
            int d = wt + nt * 8 + lq * 2;
            if (mA < NROOT) *(float2*)(base + mA * 64 + d) = make_float2(pacc[nt][0], pacc[nt][1]);
            if (mB < NROOT) *(float2*)(base + mB * 64 + d) = make_float2(pacc[nt][2], pacc[nt][3]);
        }
    }
}

// ===========================================================================
// attn_diag: diagonal tile via tf32 mma on causal-zeroed P, plus prefix add.
// ===========================================================================
__global__ __launch_bounds__(256) void attn_diag() {
    __shared__ float Ps[64 * 68];
    __shared__ float Vs[64 * 72];
    __shared__ float lsum[64];
    __shared__ int sidx[64];
    int tid = threadIdx.x;
    int lane = tid & 31, w = tid >> 5;
    int lq = lane & 3, lr = lane >> 2;
    int mblk = blockIdx.x, bh = blockIdx.y;
    int b = bh >> 4, h = bh & 15;
    int m0 = mblk * 64;
    if (tid < 64) sidx[tid] = g_idx[bh * SEQ + m0 + tid];
    __syncthreads();

#pragma unroll
    for (int k = 0; k < 4; k++) {
        int fl = tid + k * 256; int s = fl >> 4, c4 = (fl & 15) * 4;
        float4 v = *(const float4*)(g_v + ((size_t)b * SEQ + m0 + s) * DMODEL + h * HDIM + c4);
        *(float4*)(Vs + s * 72 + c4) = v;
    }
    {
        int row = tid >> 2, tg = tid & 3;
        const float* er = g_E + ((size_t)bh * NROOT + sidx[row]) * SEQ + m0 + tg * 16;
        float s = 0.f;
#pragma unroll
        for (int u = 0; u < 16; u++) {
            int sk = tg * 16 + u;
            float e = (sk <= row) ? er[u] : 0.f;
            Ps[row * 68 + sk] = e;
            s += e;
        }
        s += __shfl_xor_sync(0xffffffffu, s, 1);
        s += __shfl_xor_sync(0xffffffffu, s, 2);
        if (tg == 0) lsum[row] = s;
    }
    __syncthreads();

    int wm = (w & 3) * 16, wd = (w >> 2) * 32;
    float acc[4][4];
#pragma unroll
    for (int nt = 0; nt < 4; nt++)
#pragma unroll
        for (int q = 0; q < 4; q++) acc[nt][q] = 0.f;

#pragma unroll
    for (int ks = 0; ks < 8; ks++) {
        int kk = ks * 8;
        uint32_t a[4];
        a[0] = __float_as_uint(Ps[(wm + lr) * 68 + kk + lq]);
        a[1] = __float_as_uint(Ps[(wm + lr + 8) * 68 + kk + lq]);
        a[2] = __float_as_uint(Ps[(wm + lr) * 68 + kk + lq + 4]);
        a[3] = __float_as_uint(Ps[(wm + lr + 8) * 68 + kk + lq + 4]);
#pragma unroll
        for (int nt = 0; nt < 4; nt++) {
            int cc = wd + nt * 8 + lr;
            uint32_t bb[2];
            bb[0] = __float_as_uint(Vs[(kk + lq) * 72 + cc]);
            bb[1] = __float_as_uint(Vs[(kk + lq + 4) * 72 + cc]);
            MMA8(acc[nt], a, bb);
        }
    }

    int rA = wm + lr, rB = rA + 8;
    int rootA = sidx[rA], rootB = sidx[rB];
    float lA = lsum[rA], lB = lsum[rB];
    const float* cpA = nullptr;
    const float* cpB = nullptr;
    if (mblk > 0) {
        lA += g_lp[(bh * NROOT + rootA) * NTILE + mblk - 1];
        lB += g_lp[(bh * NROOT + rootB) * NTILE + mblk - 1];
        cpA = g_P + ((size_t)(bh * NTILE + mblk - 1) * NROOT + rootA) * 64;
        cpB = g_P + ((size_t)(bh * NTILE + mblk - 1) * NROOT + rootB) * 64;
    }
    float invA = 1.0f / lA, invB = 1.0f / lB;
    float* oA = g_o + ((size_t)b * SEQ + m0 + rA) * DMODEL + h * HDIM;
    float* oB = g_o + ((size_t)b * SEQ + m0 + rB) * DMODEL + h * HDIM;
#pragma unroll
    for (int nt = 0; nt < 4; nt++) {
        int d = wd + nt * 8 + lq * 2;
        float pa0 = 0.f, pa1 = 0.f, pb0 = 0.f, pb1 = 0.f;
        if (mblk > 0) {
            float2 t0 = *(const float2*)(cpA + d); pa0 = t0.x; pa1 = t0.y;
            float2 t1 = *(const float2*)(cpB + d); pb0 = t1.x; pb1 = t1.y;
        }
        *(float2*)(oA + d) = make_float2(rtf32((acc[nt][0] + pa0) * invA),
                                         rtf32((acc[nt][1] + pa1) * invA));
        *(float2*)(oB + d) = make_float2(rtf32((acc[nt][2] + pb0) * invB),
                                         rtf32((acc[nt][3] + pb1) * invB));
    }
}

// ---------------------------------------------------------------------------
// Launch
// ---------------------------------------------------------------------------
extern "C" void kernel_launch(void* const* d_in, const int* in_sizes, int n_in,
                              void* d_out, int out_size) {
    const float* x     = (const float*)d_in[0];
    const float* Wq    = (const float*)d_in[1];
    const float* Wk    = (const float*)d_in[2];
    const float* Wv    = (const float*)d_in[3];
    const float* Wte8  = (const float*)d_in[4];
    const float* Wfe8  = (const float*)d_in[5];
    const float* Wout  = (const float*)d_in[6];
    float* out = (float*)d_out;

    float *k, *v, *o, *coords, *coords2, *wqe8, *xr, *wkr, *wvr, *wor;
    cudaGetSymbolAddress((void**)&k, g_k);
    cudaGetSymbolAddress((void**)&v, g_v);
    cudaGetSymbolAddress((void**)&o, g_o);
    cudaGetSymbolAddress((void**)&coords, g_coords);
    cudaGetSymbolAddress((void**)&coords2, g_coords2);
    cudaGetSymbolAddress((void**)&wqe8, g_Wqe8);
    cudaGetSymbolAddress((void**)&xr, g_xr);
    cudaGetSymbolAddress((void**)&wkr, g_wkr);
    cudaGetSymbolAddress((void**)&wvr, g_wvr);
    cudaGetSymbolAddress((void**)&wor, g_wor);

    cudaFuncSetAttribute(gemm_mma<true>,  cudaFuncAttributeMaxDynamicSharedMemorySize, GM_SMEM);
    cudaFuncSetAttribute(gemm_mma<false>, cudaFuncAttributeMaxDynamicSharedMemorySize, GM_SMEM);
    cudaFuncSetAttribute(attn_mid, cudaFuncAttributeMaxDynamicSharedMemorySize, AM_SMEM);

    static cudaStream_t s2 = nullptr;
    static cudaEvent_t evF = nullptr, evJ = nullptr;
    if (s2 == nullptr) {
        cudaStreamCreateWithFlags(&s2, cudaStreamNonBlocking);
        cudaEventCreateWithFlags(&evF, cudaEventDisableTiming);
        cudaEventCreateWithFlags(&evJ, cudaEventDisableTiming);
    }

    // fused prep: x-round + weight rounds + Wqe8 + RW tables
    prep<<<PREP_BLKS, 256>>>(x, Wq, Wk, Wv, Wout, Wte8, Wfe8);

    // fork: coords (split-K, high precision) + argmin on side stream
    cudaEventRecord(evF, 0);
    cudaStreamWaitEvent(s2, evF, 0);
    gemm_mma<true><<<dim3(1, 32, 2), 256, GM_SMEM, s2>>>(
        x, wqe8, coords, wqe8 + 512 * 128, coords2, 128, 512, DMODEL, 512);
    e8_argmin_fast<<<256, 256, 0, s2>>>();
    cudaEventRecord(evJ, s2);

    // main stream: K/V then fused mid-chain
    gemm_mma<false><<<dim3(8, 32, 2), 256, GM_SMEM>>>(
        xr, wkr, k, wvr, v, DMODEL, DMODEL, DMODEL, 0);

    attn_mid<<<dim3(4, NBH), 256, AM_SMEM>>>();

    // join: attn_diag needs g_idx
    cudaStreamWaitEvent(0, evJ, 0);
    attn_diag<<<dim3(32, NBH), 256>>>();

    // output projection
    gemm_mma<false><<<dim3(8, 32, 1), 256, GM_SMEM>>>(
        o, wor, out, wor, out, DMODEL, DMODEL, DMODEL, 0);
}

// round 13
// speedup vs baseline: 6.2632x; 1.1167x over previous
#include <cuda_runtime.h>
#include <cuda_bf16.h>
#include <math.h>
#include <stdint.h>

#define BATCH 2
#define SEQ   2048
#define DMODEL 1024
#define NHEAD 16
#define HDIM  64
#define MROWS (BATCH*SEQ)          // 4096
#define NBH   (BATCH*NHEAD)        // 32
#define NROOT 240
#define NTILE 32                   // key tiles of 64

// Scratch (device globals; no allocation allowed)
__device__ float g_k[MROWS*DMODEL];
__device__ float g_v[MROWS*DMODEL];
__device__ float g_o[MROWS*DMODEL];
__device__ float g_xr[MROWS*DMODEL];        // tf32-rounded x
__device__ float g_wkr[DMODEL*DMODEL];
__device__ float g_wvr[DMODEL*DMODEL];
__device__ float g_wor[DMODEL*DMODEL];
__device__ float g_E[NBH*NROOT*SEQ];        // exp(S), tf32-rounded fp32
__device__ float g_P[NBH*NTILE*NROOT*64];   // CUMULATIVE per-tile PV partials
__device__ float g_lp[NBH*NROOT*NTILE];     // CUMULATIVE per-tile E-row sums
__device__ float g_coords[MROWS*128];
__device__ float g_coords2[MROWS*128];
__device__ int   g_idx[NBH*SEQ];
__device__ float g_Wqe8[DMODEL*128];
__device__ float g_RW[NROOT*HDIM];

// ===========================================================================
// helpers
// ===========================================================================
__device__ __forceinline__ uint32_t smem_u32(const void* p) {
    uint32_t a;
    asm("{ .reg .u64 t; cvta.to.shared.u64 t, %1; cvt.u32.u64 %0, t; }"
        : "=r"(a) : "l"(p));
    return a;
}
#define CP16(dst, src) \
    asm volatile("cp.async.cg.shared.global [%0], [%1], 16;" :: "r"(dst), "l"(src) : "memory")
#define CP_COMMIT() asm volatile("cp.async.commit_group;" ::: "memory")
#define CP_WAIT(n)  asm volatile("cp.async.wait_group %0;" :: "n"(n) : "memory")

__device__ __forceinline__ void cvt3(float x, uint32_t& hi, uint32_t& lo) {
    asm("cvt.rna.tf32.f32 %0, %1;" : "=r"(hi) : "f"(x));
    float r = x - __uint_as_float(hi);
    asm("cvt.rna.tf32.f32 %0, %1;" : "=r"(lo) : "f"(r));
}
__device__ __forceinline__ uint32_t cvt1(float x) {
    uint32_t t;
    asm("cvt.rna.tf32.f32 %0, %1;" : "=r"(t) : "f"(x));
    return t;
}
__device__ __forceinline__ float rtf32(float x) { return __uint_as_float(cvt1(x)); }

#define MMA8(c, a, b) \
    asm volatile("mma.sync.aligned.m16n8k8.row.col.f32.tf32.tf32.f32 " \
        "{%0,%1,%2,%3}, {%4,%5,%6,%7}, {%8,%9}, {%0,%1,%2,%3};" \
        : "+f"((c)[0]), "+f"((c)[1]), "+f"((c)[2]), "+f"((c)[3]) \
        : "r"((a)[0]), "r"((a)[1]), "r"((a)[2]), "r"((a)[3]), \
          "r"((b)[0]), "r"((b)[1]))

// ===========================================================================
// fused prep: round x, round Wk/Wv/Wout, build Wqe8, build RW tables
// ===========================================================================
#define PB_X (MROWS * DMODEL / 256)      // 16384
#define PB_W (DMODEL * DMODEL / 256)     // 4096
#define PB_Q 512
#define PB_T 8
#define PREP_BLKS (PB_X + 3 * PB_W + PB_Q + PB_T)

__global__ __launch_bounds__(256) void prep(const float* __restrict__ x,
                                            const float* __restrict__ Wq,
                                            const float* __restrict__ Wk,
                                            const float* __restrict__ Wv,
                                            const float* __restrict__ Wo,
                                            const float* __restrict__ Wt,
                                            const float* __restrict__ Wf) {
    int tid = threadIdx.x;
    int blk = blockIdx.x;
    if (blk < PB_X) {
        int i = blk * 256 + tid;
        g_xr[i] = rtf32(x[i]);
        return;
    }
    blk -= PB_X;
    if (blk < 3 * PB_W) {
        int sel = blk / PB_W;
        int i = (blk % PB_W) * 256 + tid;
        const float* s = (sel == 0) ? Wk : (sel == 1) ? Wv : Wo;
        float* d = (sel == 0) ? g_wkr : (sel == 1) ? g_wvr : g_wor;
        d[i] = rtf32(s[i]);
        return;
    }
    blk -= 3 * PB_W;
    if (blk < PB_Q) {
        int i = blk * 256 + tid;           // < 1024*128
        int in = i >> 7, c = i & 127, h = c >> 3, j = c & 7;
        float s = 0.f;
#pragma unroll
        for (int e = 0; e < 64; e++) s += Wq[(size_t)in * DMODEL + h * 64 + e] * Wt[e * 8 + j];
        g_Wqe8[i] = s;
        return;
    }
    blk -= PB_Q;
    {
        // tables: 8 blocks, each derives roots locally then fills 1/8 of RW
        __shared__ float roots[NROOT * 8];
        for (int i = tid; i < NROOT * 8; i += 256) {
            int r = i >> 3, d = i & 7;
            float v;
            if (r < 112) {
                int p = r >> 2, s = r & 3;
                int a = 0, b = 1, cnt = 0; bool done = false;
                for (a = 0; a < 8 && !done; a++) {
                    for (b = a + 1; b < 8; b++) {
                        if (cnt == p) { done = true; break; }
                        cnt++;
                    }
                }
                a--;
                float si = (s & 2) ? -1.f : 1.f;
                float sj = (s & 1) ? -1.f : 1.f;
                v = (d == a) ? si : ((d == b) ? sj : 0.f);
            } else {
                int k = r - 112;
                int mask = (k << 1) | (__popc(k) & 1);
                v = ((mask >> d) & 1) ? -0.5f : 0.5f;
            }
            roots[i] = v;
        }
        __syncthreads();
        int base = blk * (NROOT * HDIM / PB_T);    // 1920 per block
        for (int t = tid; t < NROOT * HDIM / PB_T; t += 256) {
            int i = base + t;
            int r = i >> 6, d = i & 63;
            float s = 0.f;
#pragma unroll
            for (int j = 0; j < 8; j++) s += roots[r * 8 + j] * Wf[j * HDIM + d];
            g_RW[i] = rtf32(0.125f * s);
        }
    }
}

// ===========================================================================
// mma.sync tf32 GEMM: C[M,N] = A[M,K(lda)] @ B[K,N]
// 128 threads / 4 warps, warp tile 64x64 (LDS/MMA = 1.0 vs 1.5 at 32x64).
// ===========================================================================
#define AS_STRIDE 36
#define BS_STRIDE 132
#define AS_F (128 * AS_STRIDE)
#define BS_F (32 * BS_STRIDE)
#define STG_F (AS_F + BS_F)
#define GM_SMEM (2 * STG_F * 4)

extern __shared__ float smf[];

template <bool SPLIT3>
__global__ __launch_bounds__(128, SPLIT3 ? 1 : 2)
void gemm_mma(const float* __restrict__ A,
              const float* __restrict__ B0, float* __restrict__ C0,
              const float* __restrict__ B1, float* __restrict__ C1,
              int N, int K, int lda, int koff) {
    const float* B = blockIdx.z ? B1 : B0;
    float* C = blockIdx.z ? C1 : C0;
    A += (size_t)blockIdx.z * koff;
    int tid = threadIdx.x;
    int lane = tid & 31, w = tid >> 5;
    int lq = lane & 3, lr = lane >> 2;
    int wm = (w & 1) * 64, wn = (w >> 1) * 64;
    int n0 = blockIdx.x * 128, m0 = blockIdx.y * 128;
    uint32_t sb = smem_u32(smf);

    float acc[4][8][4];
#pragma unroll
    for (int mt = 0; mt < 4; mt++)
#pragma unroll
        for (int nt = 0; nt < 8; nt++)
#pragma unroll
            for (int j = 0; j < 4; j++) acc[mt][nt][j] = 0.f;

    int ar[8], aq[8], bk[8], bn[8];
#pragma unroll
    for (int i = 0; i < 8; i++) {
        int idx = tid + i * 128;
        ar[i] = idx >> 3; aq[i] = idx & 7;
        bk[i] = idx >> 5; bn[i] = idx & 31;
    }

    auto issue_chunk = [&](int c) {
        int k0 = c * 32;
        uint32_t base = sb + (uint32_t)(c & 1) * (STG_F * 4);
#pragma unroll
        for (int i = 0; i < 8; i++)
            CP16(base + (uint32_t)(ar[i] * AS_STRIDE + aq[i] * 4) * 4,
                 A + (size_t)(m0 + ar[i]) * lda + k0 + aq[i] * 4);
#pragma unroll
        for (int i = 0; i < 8; i++)
            CP16(base + (uint32_t)(AS_F + bk[i] * BS_STRIDE + bn[i] * 4) * 4,
                 B + (size_t)(k0 + bk[i]) * N + n0 + bn[i] * 4);
        CP_COMMIT();
    };

    issue_chunk(0);
    int nchunk = K >> 5;

    for (int c = 0; c < nchunk; c++) {
        if (c < nchunk - 1) { issue_chunk(c + 1); CP_WAIT(1); }
        else                { CP_WAIT(0); }
        __syncthreads();

        const float* As = smf + (c & 1) * STG_F;
        const float* Bs = As + AS_F;

#pragma unroll
        for (int ks = 0; ks < 4; ks++) {
            int kk = ks * 8;
            uint32_t Ah[4][4], Al[4][4];
#pragma unroll
            for (int mt = 0; mt < 4; mt++) {
                int rb = wm + mt * 16 + lr;
                if (SPLIT3) {
                    cvt3(As[rb * AS_STRIDE + kk + lq],           Ah[mt][0], Al[mt][0]);
                    cvt3(As[(rb + 8) * AS_STRIDE + kk + lq],     Ah[mt][1], Al[mt][1]);
                    cvt3(As[rb * AS_STRIDE + kk + lq + 4],       Ah[mt][2], Al[mt][2]);
                    cvt3(As[(rb + 8) * AS_STRIDE + kk + lq + 4], Ah[mt][3], Al[mt][3]);
                } else {
                    Ah[mt][0] = __float_as_uint(As[rb * AS_STRIDE + kk + lq]);
                    Ah[mt][1] = __float_as_uint(As[(rb + 8) * AS_STRIDE + kk + lq]);
                    Ah[mt][2] = __float_as_uint(As[rb * AS_STRIDE + kk + lq + 4]);
                    Ah[mt][3] = __float_as_uint(As[(rb + 8) * AS_STRIDE + kk + lq + 4]);
                }
            }
            uint32_t Bh[8][2], Bl[8][2];
#pragma unroll
            for (int nt = 0; nt < 8; nt++) {
                int cc = wn + nt * 8 + lr;
                if (SPLIT3) {
                    cvt3(Bs[(kk + lq) * BS_STRIDE + cc],     Bh[nt][0], Bl[nt][0]);
                    cvt3(Bs[(kk + lq + 4) * BS_STRIDE + cc], Bh[nt][1], Bl[nt][1]);
                } else {
                    Bh[nt][0] = __float_as_uint(Bs[(kk + lq) * BS_STRIDE + cc]);
                    Bh[nt][1] = __float_as_uint(Bs[(kk + lq + 4) * BS_STRIDE + cc]);
                }
            }
#pragma unroll
            for (int mt = 0; mt < 4; mt++)
#pragma unroll
                for (int nt = 0; nt < 8; nt++) {
                    MMA8(acc[mt][nt], Ah[mt], Bh[nt]);
                    if (SPLIT3) {
                        MMA8(acc[mt][nt], Al[mt], Bh[nt]);
                        MMA8(acc[mt][nt], Ah[mt], Bl[nt]);
                    }
                }
        }
        __syncthreads();
    }

#pragma unroll
    for (int mt = 0; mt < 4; mt++) {
        int row = m0 + wm + mt * 16 + lr;
#pragma unroll
        for (int nt = 0; nt < 8; nt++) {
            int col = n0 + wn + nt * 8 + lq * 2;
            if (SPLIT3) {
                *(float2*)(C + (size_t)row * N + col) =
                    make_float2(acc[mt][nt][0], acc[mt][nt][1]);
                *(float2*)(C + (size_t)(row + 8) * N + col) =
                    make_float2(acc[mt][nt][2], acc[mt][nt][3]);
            } else {
                *(float2*)(C + (size_t)row * N + col) =
                    make_float2(rtf32(acc[mt][nt][0]), rtf32(acc[mt][nt][1]));
                *(float2*)(C + (size_t)(row + 8) * N + col) =
                    make_float2(rtf32(acc[mt][nt][2]), rtf32(acc[mt][nt][3]));
            }
        }
    }
}

// ===========================================================================
// closed-form E8 argmin
// ===========================================================================
__global__ __launch_bounds__(256) void e8_argmin_fast() {
    int id = blockIdx.x * 256 + threadIdx.x;
    int t = id & (SEQ - 1), h = (id >> 11) & 15, b = id >> 15;
    size_t off = ((size_t)(b * SEQ + t)) * 128 + h * 8;
    float x[8];
#pragma unroll
    for (int j = 0; j < 8; j++) x[j] = g_coords[off + j] + g_coords2[off + j];

    int i1 = 0, i2 = -1;
    float m1 = fabsf(x[0]), m2 = -1.f;
#pragma unroll
    for (int j = 1; j < 8; j++) {
        float a = fabsf(x[j]);
        if (a > m1) { m2 = m1; i2 = i1; m1 = a; i1 = j; }
        else if (a > m2) { m2 = a; i2 = j; }
    }
    int a = min(i1, i2), bb = max(i1, i2);
    float dotp = m1 + m2;
    int p = a * 7 - (a * (a - 1)) / 2 + (bb - a - 1);
    int s = ((x[a] < 0.f) ? 2 : 0) | ((x[bb] < 0.f) ? 1 : 0);
    int idx_pair = p * 4 + s;

    float S = 0.f, mn = 3.4e38f;
    int mni = 0, mask = 0, cnt = 0;
#pragma unroll
    for (int j = 0; j < 8; j++) {
        float aa = fabsf(x[j]);
        S += aa;
        if (aa < mn) { mn = aa; mni = j; }
        if (x[j] < 0.f) { mask |= 1 << j; cnt++; }
    }
    if (cnt & 1) mask ^= (1 << mni);
    float doth = 0.5f * S - ((cnt & 1) ? mn : 0.f);

    g_idx[id] = (dotp >= doth) ? idx_pair : (112 + (mask >> 1));
}

// ===========================================================================
// attn_mid: FUSED rgemm + exp + running lp + partial PV + running P cumsum.
// ===========================================================================
#define AM_AS 0
#define AM_ES (64 * 68)
#define AM_K  (AM_ES + 64 * 68)
#define AM_V  (AM_K + 2 * 64 * 68)
#define AM_RS (AM_V + 2 * 64 * 72)
#define AM_RUN (AM_RS + 64)
#define AM_SMEM ((AM_RUN + 64) * 4)

__global__ __launch_bounds__(256) void attn_mid() {
    float* As = smf + AM_AS;
    float* Es = smf + AM_ES;
    float* rsum = smf + AM_RS;
    float* running = smf + AM_RUN;
    uint32_t sb = smem_u32(smf);

    int tid = threadIdx.x;
    int lane = tid & 31, w = tid >> 5;
    int lq = lane & 3, lr = lane >> 2;
    int wm = (w & 3) * 16, wt = (w >> 2) * 32;
    int m0 = blockIdx.x * 64, bh = blockIdx.y;
    int b = bh >> 4, h = bh & 15;

    // load RW m-tile (one time)
#pragma unroll
    for (int i = 0; i < 4; i++) {
        int idx = tid + i * 256;
        int r = idx >> 4, c4 = (idx & 15) * 4;
        int m = m0 + r;
        float4 a = (m < NROOT) ? *(const float4*)(g_RW + m * HDIM + c4)
                               : make_float4(0, 0, 0, 0);
        *(float4*)(As + r * 68 + c4) = a;
    }
    if (tid < 64) { running[tid] = 0.f; rsum[tid] = 0.f; }

    auto load_kv = [&](int j, int buf) {
        int t0 = j * 64;
#pragma unroll
        for (int i = 0; i < 4; i++) {
            int idx = tid + i * 256;
            int r = idx >> 4, c4 = (idx & 15) * 4;
            const float* kp = g_k + ((size_t)b * SEQ + t0 + r) * DMODEL + h * HDIM + c4;
            const float* vp = g_v + ((size_t)b * SEQ + t0 + r) * DMODEL + h * HDIM + c4;
            CP16(sb + (uint32_t)(AM_K + buf * 64 * 68 + r * 68 + c4) * 4, kp);
            CP16(sb + (uint32_t)(AM_V + buf * 64 * 72 + r * 72 + c4) * 4, vp);
        }
        CP_COMMIT();
    };
    load_kv(0, 0);

    float pacc[4][4];
#pragma unroll
    for (int nt = 0; nt < 4; nt++)
#pragma unroll
        for (int q = 0; q < 4; q++) pacc[nt][q] = 0.f;

    int mA = m0 + wm + lr, mB = mA + 8;

    for (int j = 0; j < NTILE; j++) {
        CP_WAIT(0);        // current buffer complete
        __syncthreads();   // ALL threads done with iteration j-1 (incl. PV reads)
        if (j < NTILE - 1) load_kv(j + 1, (j + 1) & 1);  // safe: post-barrier

        const float* Kb = smf + AM_K + (j & 1) * 64 * 68;
        const float* Vb = smf + AM_V + (j & 1) * 64 * 72;
        int t0 = j * 64;

        // ---- S = RW x K_j ----
        float sacc[4][4];
#pragma unroll
        for (int nt = 0; nt < 4; nt++)
#pragma unroll
            for (int q = 0; q < 4; q++) sacc[nt][q] = 0.f;
#pragma unroll
        for (int ks = 0; ks < 8; ks++) {
            int kk = ks * 8;
            uint32_t a[4];
            a[0] = __float_as_uint(As[(wm + lr) * 68 + kk + lq]);
            a[1] = __float_as_uint(As[(wm + lr + 8) * 68 + kk + lq]);
            a[2] = __float_as_uint(As[(wm + lr) * 68 + kk + lq + 4]);
            a[3] = __float_as_uint(As[(wm + lr + 8) * 68 + kk + lq + 4]);
#pragma unroll
            for (int nt = 0; nt < 4; nt++) {
                int cc = wt + nt * 8 + lr;
                uint32_t bb[2];
                bb[0] = __float_as_uint(Kb[cc * 68 + kk + lq]);
                bb[1] = __float_as_uint(Kb[cc * 68 + kk + lq + 4]);
                MMA8(sacc[nt], a, bb);
            }
        }

        // ---- exp, store E (smem + gmem), row sums ----
        float sA = 0.f, sB = 0.f;
#pragma unroll
        for (int nt = 0; nt < 4; nt++) {
            float e0 = rtf32(__expf(sacc[nt][0]));
            float e1 = rtf32(__expf(sacc[nt][1]));
            float e2 = rtf32(__expf(sacc[nt][2]));
            float e3 = rtf32(__expf(sacc[nt][3]));
            sA += e0 + e1; sB += e2 + e3;
            int col = wt + nt * 8 + lq * 2;
            Es[(wm + lr) * 68 + col] = e0;
            Es[(wm + lr) * 68 + col + 1] = e1;
            Es[(wm + lr + 8) * 68 + col] = e2;
            Es[(wm + lr + 8) * 68 + col + 1] = e3;
            if (mA < NROOT)
                *(float2*)(g_E + ((size_t)bh * NROOT + mA) * SEQ + t0 + col) = make_float2(e0, e1);
            if (mB < NROOT)
                *(float2*)(g_E + ((size_t)bh * NROOT + mB) * SEQ + t0 + col) = make_float2(e2, e3);
        }
        sA += __shfl_xor_sync(0xffffffffu, sA, 1);
        sA += __shfl_xor_sync(0xffffffffu, sA, 2);
        sB += __shfl_xor_sync(0xffffffffu, sB, 1);
        sB += __shfl_xor_sync(0xffffffffu, sB, 2);
        if (lq == 0) {
            atomicAdd(&rsum[wm + lr], sA);
            atomicAdd(&rsum[wm + lr + 8], sB);
        }
        __syncthreads();   // Es + rsum visible

        // ---- pacc += Es x V_j ----
#pragma unroll
        for (int ks = 0; ks < 8; ks++) {
            int kk = ks * 8;
            uint32_t a[4];
            a[0] = __float_as_uint(Es[(wm + lr) * 68 + kk + lq]);
            a[1] = __float_as_uint(Es[(wm + lr + 8) * 68 + kk + lq]);
            a[2] = __float_as_uint(Es[(wm + lr) * 68 + kk + lq + 4]);
            a[3] = __float_as_uint(Es[(wm + lr + 8) * 68 + kk + lq + 4]);
#pragma unroll
            for (int nt = 0; nt < 4; nt++) {
                int cc = wt + nt * 8 + lr;
                uint32_t bb[2];
                bb[0] = __float_as_uint(Vb[(kk + lq) * 72 + cc]);
                bb[1] = __float_as_uint(Vb[(kk + lq + 4) * 72 + cc]);
                MMA8(pacc[nt], a, bb);
            }
        }

        // ---- cumulative lp + P stores ----
        if (tid < 64) {
            int m = m0 + tid;
            float r = running[tid] + rsum[tid];
            running[tid] = r;
            rsum[tid] = 0.f;
            if (m < NROOT) g_lp[(bh * NROOT + m) * NTILE + j] = r;
        }
        float* base = g_P + (size_t)(bh * NTILE + j) * NROOT * 64;
#pragma unroll
        for (int nt = 0; nt < 4; nt++) {
            int d = wt + nt * 8 + lq * 2;
            if (mA < NROOT) *(float2*)(base + mA * 64 + d) = make_float2(pacc[nt][0], pacc[nt][1]);
            if (mB < NROOT) *(float2*)(base + mB * 64 + d) = make_float2(pacc[nt][2], pacc[nt][3]);
        }
    }
}

// ===========================================================================
// attn_diag: diagonal tile via tf32 mma on causal-zeroed P, plus prefix add.
// ===========================================================================
__global__ __launch_bounds__(256) void attn_diag() {
    __shared__ float Ps[64 * 68];
    __shared__ float Vs[64 * 72];
    __shared__ float lsum[64];
    __shared__ int sidx[64];
    int tid = threadIdx.x;
    int lane = tid & 31, w = tid >> 5;
    int lq = lane & 3, lr = lane >> 2;
    int mblk = blockIdx.x, bh = blockIdx.y;
    int b = bh >> 4, h = bh & 15;
    int m0 = mblk * 64;
    if (tid < 64) sidx[tid] = g_idx[bh * SEQ + m0 + tid];
    __syncthreads();

#pragma unroll
    for (int k = 0; k < 4; k++) {
        int fl = tid + k * 256; int s = fl >> 4, c4 = (fl & 15) * 4;
        float4 v = *(const float4*)(g_v + ((size_t)b * SEQ + m0 + s) * DMODEL + h * HDIM + c4);
        *(float4*)(Vs + s * 72 + c4) = v;
    }
    {
        int row = tid >> 2, tg = tid & 3;
        const float* er = g_E + ((size_t)bh * NROOT + sidx[row]) * SEQ + m0 + tg * 16;
        float s = 0.f;
#pragma unroll
        for (int u = 0; u < 16; u++) {
            int sk = tg * 16 + u;
            float e = (sk <= row) ? er[u] : 0.f;
            Ps[row * 68 + sk] = e;
            s += e;
        }
        s += __shfl_xor_sync(0xffffffffu, s, 1);
        s += __shfl_xor_sync(0xffffffffu, s, 2);
        if (tg == 0) lsum[row] = s;
    }
    __syncthreads();

    int wm = (w & 3) * 16, wd = (w >> 2) * 32;
    float acc[4][4];
#pragma unroll
    for (int nt = 0; nt < 4; nt++)
#pragma unroll
        for (int q = 0; q < 4; q++) acc[nt][q] = 0.f;

#pragma unroll
    for (int ks = 0; ks < 8; ks++) {
        int kk = ks * 8;
        uint32_t a[4];
        a[0] = __float_as_uint(Ps[(wm + lr) * 68 + kk + lq]);
        a[1] = __float_as_uint(Ps[(wm + lr + 8) * 68 + kk + lq]);
        a[2] = __float_as_uint(Ps[(wm + lr) * 68 + kk + lq + 4]);
        a[3] = __float_as_uint(Ps[(wm + lr + 8) * 68 + kk + lq + 4]);
#pragma unroll
        for (int nt = 0; nt < 4; nt++) {
            int cc = wd + nt * 8 + lr;
            uint32_t bb[2];
            bb[0] = __float_as_uint(Vs[(kk + lq) * 72 + cc]);
            bb[1] = __float_as_uint(Vs[(kk + lq + 4) * 72 + cc]);
            MMA8(acc[nt], a, bb);
        }
    }

    int rA = wm + lr, rB = rA + 8;
    int rootA = sidx[rA], rootB = sidx[rB];
    float lA = lsum[rA], lB = lsum[rB];
    const float* cpA = nullptr;
    const float* cpB = nullptr;
    if (mblk > 0) {
        lA += g_lp[(bh * NROOT + rootA) * NTILE + mblk - 1];
        lB += g_lp[(bh * NROOT + rootB) * NTILE + mblk - 1];
        cpA = g_P + ((size_t)(bh * NTILE + mblk - 1) * NROOT + rootA) * 64;
        cpB = g_P + ((size_t)(bh * NTILE + mblk - 1) * NROOT + rootB) * 64;
    }
    float invA = 1.0f / lA, invB = 1.0f / lB;
    float* oA = g_o + ((size_t)b * SEQ + m0 + rA) * DMODEL + h * HDIM;
    float* oB = g_o + ((size_t)b * SEQ + m0 + rB) * DMODEL + h * HDIM;
#pragma unroll
    for (int nt = 0; nt < 4; nt++) {
        int d = wd + nt * 8 + lq * 2;
        float pa0 = 0.f, pa1 = 0.f, pb0 = 0.f, pb1 = 0.f;
        if (mblk > 0) {
            float2 t0 = *(const float2*)(cpA + d); pa0 = t0.x; pa1 = t0.y;
            float2 t1 = *(const float2*)(cpB + d); pb0 = t1.x; pb1 = t1.y;
        }
        *(float2*)(oA + d) = make_float2(rtf32((acc[nt][0] + pa0) * invA),
                                         rtf32((acc[nt][1] + pa1) * invA));
        *(float2*)(oB + d) = make_float2(rtf32((acc[nt][2] + pb0) * invB),
                                         rtf32((acc[nt][3] + pb1) * invB));
    }
}

// ---------------------------------------------------------------------------
// Launch
// ---------------------------------------------------------------------------
extern "C" void kernel_launch(void* const* d_in, const int* in_sizes, int n_in,
                              void* d_out, int out_size) {
    const float* x     = (const float*)d_in[0];
    const float* Wq    = (const float*)d_in[1];
    const float* Wk    = (const float*)d_in[2];
    const float* Wv    = (const float*)d_in[3];
    const float* Wte8  = (const float*)d_in[4];
    const float* Wfe8  = (const float*)d_in[5];
    const float* Wout  = (const float*)d_in[6];
    float* out = (float*)d_out;

    float *k, *v, *o, *coords, *coords2, *wqe8, *xr, *wkr, *wvr, *wor;
    cudaGetSymbolAddress((void**)&k, g_k);
    cudaGetSymbolAddress((void**)&v, g_v);
    cudaGetSymbolAddress((void**)&o, g_o);
    cudaGetSymbolAddress((void**)&coords, g_coords);
    cudaGetSymbolAddress((void**)&coords2, g_coords2);
    cudaGetSymbolAddress((void**)&wqe8, g_Wqe8);
    cudaGetSymbolAddress((void**)&xr, g_xr);
    cudaGetSymbolAddress((void**)&wkr, g_wkr);
    cudaGetSymbolAddress((void**)&wvr, g_wvr);
    cudaGetSymbolAddress((void**)&wor, g_wor);

    cudaFuncSetAttribute(gemm_mma<true>,  cudaFuncAttributeMaxDynamicSharedMemorySize, GM_SMEM);
    cudaFuncSetAttribute(gemm_mma<false>, cudaFuncAttributeMaxDynamicSharedMemorySize, GM_SMEM);
    cudaFuncSetAttribute(attn_mid, cudaFuncAttributeMaxDynamicSharedMemorySize, AM_SMEM);

    static cudaStream_t s2 = nullptr;
    static cudaEvent_t evF = nullptr, evJ = nullptr;
    if (s2 == nullptr) {
        cudaStreamCreateWithFlags(&s2, cudaStreamNonBlocking);
        cudaEventCreateWithFlags(&evF, cudaEventDisableTiming);
        cudaEventCreateWithFlags(&evJ, cudaEventDisableTiming);
    }

    // fused prep: x-round + weight rounds + Wqe8 + RW tables
    prep<<<PREP_BLKS, 256>>>(x, Wq, Wk, Wv, Wout, Wte8, Wfe8);

    // fork: coords (split-K, high precision) + argmin on side stream
    cudaEventRecord(evF, 0);
    cudaStreamWaitEvent(s2, evF, 0);
    gemm_mma<true><<<dim3(1, 32, 2), 128, GM_SMEM, s2>>>(
        x, wqe8, coords, wqe8 + 512 * 128, coords2, 128, 512, DMODEL, 512);
    e8_argmin_fast<<<256, 256, 0, s2>>>();
    cudaEventRecord(evJ, s2);

    // main stream: K/V then fused mid-chain
    gemm_mma<false><<<dim3(8, 32, 2), 128, GM_SMEM>>>(
        xr, wkr, k, wvr, v, DMODEL, DMODEL, DMODEL, 0);

    attn_mid<<<dim3(4, NBH), 256, AM_SMEM>>>();

    // join: attn_diag needs g_idx
    cudaStreamWaitEvent(0, evJ, 0);
    attn_diag<<<dim3(32, NBH), 256>>>();

    // output projection
    gemm_mma<false><<<dim3(8, 32, 1), 128, GM_SMEM>>>(
        o, wor, out, wor, out, DMODEL, DMODEL, DMODEL, 0);
}